// round 1
// baseline (speedup 1.0000x reference)
#include <cuda_runtime.h>
#include <math.h>

// Problem constants
#define B_  2
#define T_  2048
#define C_  1024
#define H_  16
#define D_  64
#define BT  (B_*T_)          // 4096
#define N3C (3*C_)           // 3072

// Scratch (device globals; no allocation allowed)
__device__ float g_q[B_*H_*T_*D_];     // [B,H,T,D]
__device__ float g_k[B_*H_*T_*D_];
__device__ float g_v[B_*H_*T_*D_];
__device__ float g_attn[B_*T_*C_];     // [B,T,C] attention output pre-projection

// ---------------------------------------------------------------------------
// Kernel 1: QKV projection  qkv = x @ W_qkv + b_qkv, scattered into q/k/v
// 128x128x8 register-blocked sgemm, 256 threads, 8x8 per thread.
// ---------------------------------------------------------------------------
__global__ __launch_bounds__(256)
void qkv_gemm_kernel(const float* __restrict__ X,      // [4096,1024]
                     const float* __restrict__ W,      // [1024,3072]
                     const float* __restrict__ bias)   // [3072]
{
    __shared__ float As[8][128];
    __shared__ float Bs[8][128];

    const int m0 = blockIdx.y * 128;
    const int n0 = blockIdx.x * 128;
    const int tid = threadIdx.x;
    const int tx = tid & 15;       // 0..15 -> output col group
    const int ty = tid >> 4;       // 0..15 -> output row group

    // A-tile load mapping: 128 rows x 8 cols, 2 threads/row, float4 each
    const int arow = tid >> 1;
    const int acol = (tid & 1) * 4;
    // B-tile load mapping: 8 rows x 128 cols, 32 threads/row, float4 each
    const int brow = tid >> 5;
    const int bcol = (tid & 31) * 4;

    const float* Xp = X + (m0 + arow) * C_ + acol;
    const float* Wp = W + brow * N3C + n0 + bcol;

    float acc[8][8];
    #pragma unroll
    for (int i = 0; i < 8; i++)
        #pragma unroll
        for (int j = 0; j < 8; j++) acc[i][j] = 0.f;

    float4 a4 = *(const float4*)(Xp);
    float4 b4 = *(const float4*)(Wp);

    for (int k0 = 0; k0 < C_; k0 += 8) {
        As[acol + 0][arow] = a4.x;
        As[acol + 1][arow] = a4.y;
        As[acol + 2][arow] = a4.z;
        As[acol + 3][arow] = a4.w;
        *(float4*)&Bs[brow][bcol] = b4;
        __syncthreads();
        if (k0 + 8 < C_) {
            a4 = *(const float4*)(Xp + (k0 + 8));
            b4 = *(const float4*)(Wp + (size_t)(k0 + 8) * N3C);
        }
        #pragma unroll
        for (int k = 0; k < 8; k++) {
            float af[8], bf[8];
            *(float4*)(af)     = *(const float4*)&As[k][ty * 8];
            *(float4*)(af + 4) = *(const float4*)&As[k][ty * 8 + 4];
            *(float4*)(bf)     = *(const float4*)&Bs[k][tx * 8];
            *(float4*)(bf + 4) = *(const float4*)&Bs[k][tx * 8 + 4];
            #pragma unroll
            for (int i = 0; i < 8; i++)
                #pragma unroll
                for (int j = 0; j < 8; j++)
                    acc[i][j] += af[i] * bf[j];
        }
        __syncthreads();
    }

    // Epilogue: add bias, scatter to g_q/g_k/g_v in [B,H,T,D] layout.
    // col c: head h = c/192, r = c%192; r<64 -> q[d=r], r<128 -> k, else v.
    const int cbase = n0 + tx * 8;
    float4 bias0 = *(const float4*)&bias[cbase];
    float4 bias1 = *(const float4*)&bias[cbase + 4];

    // precompute destinations for the two float4 column groups
    float* dstbase[2];
    int    doff[2];
    int    hh[2];
    #pragma unroll
    for (int g = 0; g < 2; g++) {
        int c = cbase + g * 4;
        int h = c / 192;
        int r = c - h * 192;
        int seg = r >> 6;
        int d = r & 63;
        dstbase[g] = (seg == 0) ? g_q : (seg == 1) ? g_k : g_v;
        doff[g] = d;
        hh[g] = h;
    }

    #pragma unroll
    for (int i = 0; i < 8; i++) {
        int m = m0 + ty * 8 + i;
        int b = m >> 11;
        int t = m & (T_ - 1);
        #pragma unroll
        for (int g = 0; g < 2; g++) {
            float4 bv = g ? bias1 : bias0;
            float4 v;
            v.x = acc[i][g * 4 + 0] + bv.x;
            v.y = acc[i][g * 4 + 1] + bv.y;
            v.z = acc[i][g * 4 + 2] + bv.z;
            v.w = acc[i][g * 4 + 3] + bv.w;
            size_t idx = (((size_t)(b * H_ + hh[g]) * T_ + t) * D_) + doff[g];
            *(float4*)&dstbase[g][idx] = v;
        }
    }
}

// ---------------------------------------------------------------------------
// Kernel 2: flash attention, fp32. 1 thread = 1 query row.
// Block: 128 threads = 128 query rows. Grid: (T/128, H, B).
// ---------------------------------------------------------------------------
__global__ __launch_bounds__(128, 2)
void attn_kernel()
{
    const int q0 = blockIdx.x * 128;
    const int h  = blockIdx.y;
    const int b  = blockIdx.z;
    const int tid = threadIdx.x;

    const size_t bh = (size_t)(b * H_ + h);
    const float* Qb = g_q + bh * (T_ * D_);
    const float* Kb = g_k + bh * (T_ * D_);
    const float* Vb = g_v + bh * (T_ * D_);

    __shared__ float4 Ks[64 * 16];   // 64 keys x 64 dims
    __shared__ float4 Vs[64 * 16];

    // load this thread's query row, pre-scaled by 1/sqrt(D)
    float4 q[16];
    const float4* qrow = (const float4*)(Qb + (size_t)(q0 + tid) * D_);
    #pragma unroll
    for (int i = 0; i < 16; i++) {
        float4 v = qrow[i];
        v.x *= 0.125f; v.y *= 0.125f; v.z *= 0.125f; v.w *= 0.125f;
        q[i] = v;
    }

    float4 o[16];
    #pragma unroll
    for (int i = 0; i < 16; i++) { o[i].x = 0.f; o[i].y = 0.f; o[i].z = 0.f; o[i].w = 0.f; }
    float m = -1e30f;
    float l = 0.f;

    for (int kt = 0; kt < T_; kt += 64) {
        __syncthreads();
        const float4* Kg = (const float4*)(Kb + (size_t)kt * D_);
        const float4* Vg = (const float4*)(Vb + (size_t)kt * D_);
        #pragma unroll
        for (int i = 0; i < 8; i++) {
            Ks[tid + i * 128] = Kg[tid + i * 128];
            Vs[tid + i * 128] = Vg[tid + i * 128];
        }
        __syncthreads();

        #pragma unroll
        for (int jc = 0; jc < 64; jc += 16) {
            float s[16];
            float mt = m;
            #pragma unroll
            for (int j = 0; j < 16; j++) {
                const float4* krow = &Ks[(jc + j) * 16];
                float a = 0.f;
                #pragma unroll
                for (int d = 0; d < 16; d++) {
                    float4 k4 = krow[d];
                    a += q[d].x * k4.x + q[d].y * k4.y + q[d].z * k4.z + q[d].w * k4.w;
                }
                s[j] = a;
                mt = fmaxf(mt, a);
            }
            float scale = __expf(m - mt);
            l *= scale;
            #pragma unroll
            for (int i = 0; i < 16; i++) {
                o[i].x *= scale; o[i].y *= scale; o[i].z *= scale; o[i].w *= scale;
            }
            m = mt;
            #pragma unroll
            for (int j = 0; j < 16; j++) {
                float p = __expf(s[j] - mt);
                l += p;
                const float4* vrow = &Vs[(jc + j) * 16];
                #pragma unroll
                for (int d = 0; d < 16; d++) {
                    float4 v4 = vrow[d];
                    o[d].x += p * v4.x;
                    o[d].y += p * v4.y;
                    o[d].z += p * v4.z;
                    o[d].w += p * v4.w;
                }
            }
        }
    }

    float inv = 1.f / l;
    float* outp = g_attn + ((size_t)b * T_ + (q0 + tid)) * C_ + h * D_;
    #pragma unroll
    for (int d = 0; d < 16; d++) {
        float4 v = o[d];
        v.x *= inv; v.y *= inv; v.z *= inv; v.w *= inv;
        ((float4*)outp)[d] = v;
    }
}

// ---------------------------------------------------------------------------
// Kernel 3: output projection  out = attn @ W_out + b_out
// Same 128x128x8 sgemm, N stride 1024.
// ---------------------------------------------------------------------------
__global__ __launch_bounds__(256)
void out_gemm_kernel(const float* __restrict__ W,      // [1024,1024]
                     const float* __restrict__ bias,   // [1024]
                     float* __restrict__ out)          // [4096,1024]
{
    __shared__ float As[8][128];
    __shared__ float Bs[8][128];

    const int m0 = blockIdx.y * 128;
    const int n0 = blockIdx.x * 128;
    const int tid = threadIdx.x;
    const int tx = tid & 15;
    const int ty = tid >> 4;

    const int arow = tid >> 1;
    const int acol = (tid & 1) * 4;
    const int brow = tid >> 5;
    const int bcol = (tid & 31) * 4;

    const float* Xp = g_attn + (size_t)(m0 + arow) * C_ + acol;
    const float* Wp = W + (size_t)brow * C_ + n0 + bcol;

    float acc[8][8];
    #pragma unroll
    for (int i = 0; i < 8; i++)
        #pragma unroll
        for (int j = 0; j < 8; j++) acc[i][j] = 0.f;

    float4 a4 = *(const float4*)(Xp);
    float4 b4 = *(const float4*)(Wp);

    for (int k0 = 0; k0 < C_; k0 += 8) {
        As[acol + 0][arow] = a4.x;
        As[acol + 1][arow] = a4.y;
        As[acol + 2][arow] = a4.z;
        As[acol + 3][arow] = a4.w;
        *(float4*)&Bs[brow][bcol] = b4;
        __syncthreads();
        if (k0 + 8 < C_) {
            a4 = *(const float4*)(Xp + (k0 + 8));
            b4 = *(const float4*)(Wp + (size_t)(k0 + 8) * C_);
        }
        #pragma unroll
        for (int k = 0; k < 8; k++) {
            float af[8], bf[8];
            *(float4*)(af)     = *(const float4*)&As[k][ty * 8];
            *(float4*)(af + 4) = *(const float4*)&As[k][ty * 8 + 4];
            *(float4*)(bf)     = *(const float4*)&Bs[k][tx * 8];
            *(float4*)(bf + 4) = *(const float4*)&Bs[k][tx * 8 + 4];
            #pragma unroll
            for (int i = 0; i < 8; i++)
                #pragma unroll
                for (int j = 0; j < 8; j++)
                    acc[i][j] += af[i] * bf[j];
        }
        __syncthreads();
    }

    const int cbase = n0 + tx * 8;
    float4 bias0 = *(const float4*)&bias[cbase];
    float4 bias1 = *(const float4*)&bias[cbase + 4];

    #pragma unroll
    for (int i = 0; i < 8; i++) {
        int mrow = m0 + ty * 8 + i;
        float* op = out + (size_t)mrow * C_ + cbase;
        float4 v0, v1;
        v0.x = acc[i][0] + bias0.x;
        v0.y = acc[i][1] + bias0.y;
        v0.z = acc[i][2] + bias0.z;
        v0.w = acc[i][3] + bias0.w;
        v1.x = acc[i][4] + bias1.x;
        v1.y = acc[i][5] + bias1.y;
        v1.z = acc[i][6] + bias1.z;
        v1.w = acc[i][7] + bias1.w;
        *(float4*)(op)     = v0;
        *(float4*)(op + 4) = v1;
    }
}

// ---------------------------------------------------------------------------
extern "C" void kernel_launch(void* const* d_in, const int* in_sizes, int n_in,
                              void* d_out, int out_size)
{
    const float* x     = (const float*)d_in[0];   // [2,2048,1024]
    const float* W_qkv = (const float*)d_in[1];   // [1024,3072]
    const float* b_qkv = (const float*)d_in[2];   // [3072]
    const float* W_out = (const float*)d_in[3];   // [1024,1024]
    const float* b_out = (const float*)d_in[4];   // [1024]
    float* out = (float*)d_out;                   // [2,2048,1024]

    (void)in_sizes; (void)n_in; (void)out_size;

    // 1) QKV projection + scatter to [B,H,T,D]
    {
        dim3 grid(N3C / 128, BT / 128);   // (24, 32)
        qkv_gemm_kernel<<<grid, 256>>>(x, W_qkv, b_qkv);
    }
    // 2) Flash attention
    {
        dim3 grid(T_ / 128, H_, B_);      // (16, 16, 2)
        attn_kernel<<<grid, 128>>>();
    }
    // 3) Output projection
    {
        dim3 grid(C_ / 128, BT / 128);    // (8, 32)
        out_gemm_kernel<<<grid, 256>>>(W_out, b_out, out);
    }
}

// round 3
// speedup vs baseline: 4.1634x; 4.1634x over previous
#include <cuda_runtime.h>
#include <cuda_bf16.h>
#include <stdint.h>
#include <math.h>

// Problem constants
#define B_  2
#define T_  2048
#define C_  1024
#define H_  16
#define D_  64
#define BT  (B_*T_)          // 4096
#define N3C (3*C_)           // 3072

// Scratch (device globals; no allocation allowed)
__device__ float g_q[B_*H_*T_*D_];     // [B,H,T,D] fp32
__device__ float g_k[B_*H_*T_*D_];
__device__ float g_v[B_*H_*T_*D_];
__device__ __align__(16) __nv_bfloat16 g_xh[BT*C_];    // x hi/lo
__device__ __align__(16) __nv_bfloat16 g_xl[BT*C_];
__device__ __align__(16) __nv_bfloat16 g_wqh[N3C*C_];  // W_qkv^T [3072][1024] hi/lo
__device__ __align__(16) __nv_bfloat16 g_wql[N3C*C_];
__device__ __align__(16) __nv_bfloat16 g_woh[C_*C_];   // W_out^T [1024][1024] hi/lo
__device__ __align__(16) __nv_bfloat16 g_wol[C_*C_];
__device__ __align__(16) __nv_bfloat16 g_ah[BT*C_];    // attn out hi/lo [B,T,C]
__device__ __align__(16) __nv_bfloat16 g_al[BT*C_];

// ---------------------------------------------------------------------------
// mma.sync helpers (arch-portable; compiles for compute_103)
// ---------------------------------------------------------------------------
__device__ __forceinline__ void mma_bf16(float* c, const uint32_t* a, uint32_t b0, uint32_t b1) {
    asm volatile("mma.sync.aligned.m16n8k16.row.col.f32.bf16.bf16.f32 "
        "{%0,%1,%2,%3}, {%4,%5,%6,%7}, {%8,%9}, {%0,%1,%2,%3};"
        : "+f"(c[0]), "+f"(c[1]), "+f"(c[2]), "+f"(c[3])
        : "r"(a[0]), "r"(a[1]), "r"(a[2]), "r"(a[3]), "r"(b0), "r"(b1));
}
__device__ __forceinline__ void mma_tf32(float* c, const uint32_t* a, uint32_t b0, uint32_t b1) {
    asm volatile("mma.sync.aligned.m16n8k8.row.col.f32.tf32.tf32.f32 "
        "{%0,%1,%2,%3}, {%4,%5,%6,%7}, {%8,%9}, {%0,%1,%2,%3};"
        : "+f"(c[0]), "+f"(c[1]), "+f"(c[2]), "+f"(c[3])
        : "r"(a[0]), "r"(a[1]), "r"(a[2]), "r"(a[3]), "r"(b0), "r"(b1));
}
__device__ __forceinline__ uint32_t f2tf32(float f) {
    uint32_t r; asm("cvt.rna.tf32.f32 %0, %1;" : "=r"(r) : "f"(f)); return r;
}

// ---------------------------------------------------------------------------
// Kernel 0a: convert x fp32 -> hi/lo bf16
// ---------------------------------------------------------------------------
__global__ __launch_bounds__(256)
void conv_x_kernel(const float4* __restrict__ X)
{
    int i = blockIdx.x * 256 + threadIdx.x;   // one float4 per thread
    float4 v = X[i];
    __nv_bfloat16 hx = __float2bfloat16(v.x);
    __nv_bfloat16 hy = __float2bfloat16(v.y);
    __nv_bfloat16 hz = __float2bfloat16(v.z);
    __nv_bfloat16 hw = __float2bfloat16(v.w);
    __nv_bfloat16 lx = __float2bfloat16(v.x - __bfloat162float(hx));
    __nv_bfloat16 ly = __float2bfloat16(v.y - __bfloat162float(hy));
    __nv_bfloat16 lz = __float2bfloat16(v.z - __bfloat162float(hz));
    __nv_bfloat16 lw = __float2bfloat16(v.w - __bfloat162float(hw));
    __nv_bfloat162* ph = (__nv_bfloat162*)g_xh + (size_t)i * 2;
    __nv_bfloat162* pl = (__nv_bfloat162*)g_xl + (size_t)i * 2;
    ph[0] = __halves2bfloat162(hx, hy);
    ph[1] = __halves2bfloat162(hz, hw);
    pl[0] = __halves2bfloat162(lx, ly);
    pl[1] = __halves2bfloat162(lz, lw);
}

// ---------------------------------------------------------------------------
// Kernel 0b: transpose + convert W [K,N] fp32 -> WT [N,K] hi/lo bf16
// ---------------------------------------------------------------------------
__global__ __launch_bounds__(256)
void conv_wt_kernel(const float* __restrict__ W, int which, int K, int N)
{
    __shared__ float tile[32][33];
    int n0 = blockIdx.x * 32;
    int k0 = blockIdx.y * 32;
    int tx = threadIdx.x;       // 0..31
    int ty = threadIdx.y;       // 0..7

    #pragma unroll
    for (int i = 0; i < 32; i += 8)
        tile[ty + i][tx] = W[(size_t)(k0 + ty + i) * N + n0 + tx];
    __syncthreads();

    __nv_bfloat16* Th = which ? g_woh : g_wqh;
    __nv_bfloat16* Tl = which ? g_wol : g_wql;
    #pragma unroll
    for (int i = 0; i < 32; i += 8) {
        float v = tile[tx][ty + i];
        __nv_bfloat16 h = __float2bfloat16(v);
        __nv_bfloat16 l = __float2bfloat16(v - __bfloat162float(h));
        size_t idx = (size_t)(n0 + ty + i) * K + k0 + tx;
        Th[idx] = h;
        Tl[idx] = l;
    }
}

// ---------------------------------------------------------------------------
// Kernel 1/3: bf16x3 GEMM via mma.sync. Block tile 128x128, kc=32.
// 8 warps = 2(M) x 4(N), warp tile 64x32.
// mode 0: A = g_xh/g_xl, B = g_wqh/g_wql, scatter epilogue to g_q/g_k/g_v
// mode 1: A = g_ah/g_al, B = g_woh/g_wol, epilogue writes outp + bias
// ---------------------------------------------------------------------------
#define AST 40   // smem row stride (bf16 elems): 40 % 32 words pattern -> conflict-free

__global__ __launch_bounds__(256, 1)
void mma_gemm_kernel(const float* __restrict__ bias, float* __restrict__ outp, int mode)
{
    __shared__ __nv_bfloat16 sAh[128 * AST];
    __shared__ __nv_bfloat16 sAl[128 * AST];
    __shared__ __nv_bfloat16 sBh[128 * AST];
    __shared__ __nv_bfloat16 sBl[128 * AST];

    const int tid  = threadIdx.x;
    const int m0   = blockIdx.y * 128;
    const int n0   = blockIdx.x * 128;
    const int warp = tid >> 5, lane = tid & 31;
    const int mw = warp & 1, nw = warp >> 1;
    const int g = lane >> 2, tig = lane & 3;

    const __nv_bfloat16* Ah = mode ? g_ah : g_xh;
    const __nv_bfloat16* Al = mode ? g_al : g_xl;
    const __nv_bfloat16* Bh = mode ? g_woh : g_wqh;
    const __nv_bfloat16* Bl = mode ? g_wol : g_wql;

    // gmem load mapping: thread -> (row = tid>>1, 2 uint4 = 32B of k)
    const int lrow = tid >> 1;
    const int lofs = (tid & 1) * 16;   // k element offset of first uint4
    const __nv_bfloat16* pAh = Ah + (size_t)(m0 + lrow) * C_ + lofs;
    const __nv_bfloat16* pAl = Al + (size_t)(m0 + lrow) * C_ + lofs;
    const __nv_bfloat16* pBh = Bh + (size_t)(n0 + lrow) * C_ + lofs;
    const __nv_bfloat16* pBl = Bl + (size_t)(n0 + lrow) * C_ + lofs;

    float acc[16][4];
    #pragma unroll
    for (int i = 0; i < 16; i++)
        #pragma unroll
        for (int j = 0; j < 4; j++) acc[i][j] = 0.f;

    uint4 rah[2], ral[2], rbh[2], rbl[2];
    rah[0] = *(const uint4*)(pAh);     rah[1] = *(const uint4*)(pAh + 8);
    ral[0] = *(const uint4*)(pAl);     ral[1] = *(const uint4*)(pAl + 8);
    rbh[0] = *(const uint4*)(pBh);     rbh[1] = *(const uint4*)(pBh + 8);
    rbl[0] = *(const uint4*)(pBl);     rbl[1] = *(const uint4*)(pBl + 8);

    for (int k0 = 0; k0 < C_; k0 += 32) {
        // STS prefetched chunk
        *(uint4*)&sAh[lrow * AST + lofs]     = rah[0];
        *(uint4*)&sAh[lrow * AST + lofs + 8] = rah[1];
        *(uint4*)&sAl[lrow * AST + lofs]     = ral[0];
        *(uint4*)&sAl[lrow * AST + lofs + 8] = ral[1];
        *(uint4*)&sBh[lrow * AST + lofs]     = rbh[0];
        *(uint4*)&sBh[lrow * AST + lofs + 8] = rbh[1];
        *(uint4*)&sBl[lrow * AST + lofs]     = rbl[0];
        *(uint4*)&sBl[lrow * AST + lofs + 8] = rbl[1];
        __syncthreads();

        if (k0 + 32 < C_) {
            rah[0] = *(const uint4*)(pAh + k0 + 32);  rah[1] = *(const uint4*)(pAh + k0 + 40);
            ral[0] = *(const uint4*)(pAl + k0 + 32);  ral[1] = *(const uint4*)(pAl + k0 + 40);
            rbh[0] = *(const uint4*)(pBh + k0 + 32);  rbh[1] = *(const uint4*)(pBh + k0 + 40);
            rbl[0] = *(const uint4*)(pBl + k0 + 32);  rbl[1] = *(const uint4*)(pBl + k0 + 40);
        }

        #pragma unroll
        for (int ks = 0; ks < 2; ks++) {
            const int kk = ks * 16 + 2 * tig;
            uint32_t ah[4][4], al[4][4];
            #pragma unroll
            for (int mf = 0; mf < 4; mf++) {
                const int r = mw * 64 + mf * 16;
                ah[mf][0] = *(const uint32_t*)&sAh[(r + g)     * AST + kk];
                ah[mf][1] = *(const uint32_t*)&sAh[(r + g + 8) * AST + kk];
                ah[mf][2] = *(const uint32_t*)&sAh[(r + g)     * AST + kk + 8];
                ah[mf][3] = *(const uint32_t*)&sAh[(r + g + 8) * AST + kk + 8];
                al[mf][0] = *(const uint32_t*)&sAl[(r + g)     * AST + kk];
                al[mf][1] = *(const uint32_t*)&sAl[(r + g + 8) * AST + kk];
                al[mf][2] = *(const uint32_t*)&sAl[(r + g)     * AST + kk + 8];
                al[mf][3] = *(const uint32_t*)&sAl[(r + g + 8) * AST + kk + 8];
            }
            #pragma unroll
            for (int nf = 0; nf < 4; nf++) {
                const int c = nw * 32 + nf * 8 + g;
                uint32_t bh0 = *(const uint32_t*)&sBh[c * AST + kk];
                uint32_t bh1 = *(const uint32_t*)&sBh[c * AST + kk + 8];
                uint32_t bl0 = *(const uint32_t*)&sBl[c * AST + kk];
                uint32_t bl1 = *(const uint32_t*)&sBl[c * AST + kk + 8];
                #pragma unroll
                for (int mf = 0; mf < 4; mf++) {
                    mma_bf16(acc[mf * 4 + nf], ah[mf], bh0, bh1);
                    mma_bf16(acc[mf * 4 + nf], ah[mf], bl0, bl1);
                    mma_bf16(acc[mf * 4 + nf], al[mf], bh0, bh1);
                }
            }
        }
        __syncthreads();
    }

    // Epilogue
    #pragma unroll
    for (int nf = 0; nf < 4; nf++) {
        const int c = n0 + nw * 32 + nf * 8 + 2 * tig;
        float2 bv = *(const float2*)&bias[c];
        #pragma unroll
        for (int mf = 0; mf < 4; mf++) {
            const float* a = acc[mf * 4 + nf];
            const int r0 = m0 + mw * 64 + mf * 16 + g;
            if (mode == 0) {
                int h  = c / 192;
                int rr = c - h * 192;
                int seg = rr >> 6;
                int d0  = rr & 63;
                float* base = (seg == 0) ? g_q : (seg == 1) ? g_k : g_v;
                int b = r0 >> 11;
                int t = r0 & (T_ - 1);
                size_t idx0 = ((size_t)(b * H_ + h) * T_ + t) * D_ + d0;
                float2 v0 = {a[0] + bv.x, a[1] + bv.y};
                float2 v1 = {a[2] + bv.x, a[3] + bv.y};
                *(float2*)&base[idx0]           = v0;
                *(float2*)&base[idx0 + 8 * D_]  = v1;   // row r0+8, same b/h
            } else {
                float2 v0 = {a[0] + bv.x, a[1] + bv.y};
                float2 v1 = {a[2] + bv.x, a[3] + bv.y};
                *(float2*)&outp[(size_t)r0 * C_ + c]       = v0;
                *(float2*)&outp[(size_t)(r0 + 8) * C_ + c] = v1;
            }
        }
    }
}

// ---------------------------------------------------------------------------
// Kernel 2: flash attention with tf32 mma.sync.
// Block: 128 thr (4 warps), Q tile 64 rows (16/warp), key blocks of 64.
// ---------------------------------------------------------------------------
#define KST 84   // K smem row stride (floats), 84%32=20 -> conflict-free QK B-frag
#define VST 72   // V smem row stride, 72%32=8 -> conflict-free PV B-frag
#define PST 68   // P smem row stride, 68%32=4 -> conflict-free PV A-frag

__global__ __launch_bounds__(128, 3)
void attn_kernel()
{
    extern __shared__ float smf[];
    float* Ks = smf;                       // [64][KST]
    float* Vs = smf + 64 * KST;            // [64][VST]
    const int tid  = threadIdx.x;
    const int warp = tid >> 5, lane = tid & 31;
    const int g = lane >> 2, tig = lane & 3;
    float* Ps = smf + 64 * KST + 64 * VST + warp * 16 * PST;   // per-warp [16][PST]

    const int q0 = blockIdx.x * 64;
    const int h  = blockIdx.y;
    const int b  = blockIdx.z;
    const size_t bh = (size_t)(b * H_ + h);
    const float* Qb = g_q + bh * (T_ * D_);
    const float* Kb = g_k + bh * (T_ * D_);
    const float* Vb = g_v + bh * (T_ * D_);

    // Q fragments, resident (tf32), rows q0+warp*16+{g,g+8}
    uint32_t qf[8][4];
    {
        const float* qr0 = Qb + (size_t)(q0 + warp * 16 + g) * D_;
        const float* qr1 = qr0 + 8 * D_;
        #pragma unroll
        for (int kf = 0; kf < 8; kf++) {
            qf[kf][0] = f2tf32(qr0[kf * 8 + tig]     * 0.125f);
            qf[kf][1] = f2tf32(qr1[kf * 8 + tig]     * 0.125f);
            qf[kf][2] = f2tf32(qr0[kf * 8 + tig + 4] * 0.125f);
            qf[kf][3] = f2tf32(qr1[kf * 8 + tig + 4] * 0.125f);
        }
    }

    float oacc[8][4];
    #pragma unroll
    for (int i = 0; i < 8; i++)
        #pragma unroll
        for (int j = 0; j < 4; j++) oacc[i][j] = 0.f;
    float m0 = -1e30f, m1 = -1e30f, l0 = 0.f, l1 = 0.f;

    for (int kb = 0; kb < T_; kb += 64) {
        __syncthreads();
        // fill K/V tiles (coalesced float4, cvt to tf32)
        {
            const float4* Kg = (const float4*)(Kb + (size_t)kb * D_);
            const float4* Vg = (const float4*)(Vb + (size_t)kb * D_);
            #pragma unroll
            for (int j = 0; j < 8; j++) {
                int flat = j * 128 + tid;          // over 1024 float4
                int row = flat >> 4;
                int c4  = (flat & 15) * 4;
                float4 kv = Kg[flat];
                float4 vv = Vg[flat];
                float4 kt, vt;
                kt.x = __uint_as_float(f2tf32(kv.x));
                kt.y = __uint_as_float(f2tf32(kv.y));
                kt.z = __uint_as_float(f2tf32(kv.z));
                kt.w = __uint_as_float(f2tf32(kv.w));
                vt.x = __uint_as_float(f2tf32(vv.x));
                vt.y = __uint_as_float(f2tf32(vv.y));
                vt.z = __uint_as_float(f2tf32(vv.z));
                vt.w = __uint_as_float(f2tf32(vv.w));
                *(float4*)&Ks[row * KST + c4] = kt;
                *(float4*)&Vs[row * VST + c4] = vt;
            }
        }
        __syncthreads();

        // S = Q K^T
        float sacc[8][4];
        #pragma unroll
        for (int i = 0; i < 8; i++)
            #pragma unroll
            for (int j = 0; j < 4; j++) sacc[i][j] = 0.f;
        #pragma unroll
        for (int nf = 0; nf < 8; nf++) {
            const uint32_t* Kw = (const uint32_t*)(Ks + (nf * 8 + g) * KST);
            #pragma unroll
            for (int kf = 0; kf < 8; kf++) {
                uint32_t b0 = Kw[kf * 8 + tig];
                uint32_t b1 = Kw[kf * 8 + tig + 4];
                mma_tf32(sacc[nf], qf[kf], b0, b1);
            }
        }

        // online softmax (rows g / g+8; quad lanes share rows)
        float r0 = -1e30f, r1 = -1e30f;
        #pragma unroll
        for (int nf = 0; nf < 8; nf++) {
            r0 = fmaxf(r0, fmaxf(sacc[nf][0], sacc[nf][1]));
            r1 = fmaxf(r1, fmaxf(sacc[nf][2], sacc[nf][3]));
        }
        r0 = fmaxf(r0, __shfl_xor_sync(0xffffffffu, r0, 1));
        r0 = fmaxf(r0, __shfl_xor_sync(0xffffffffu, r0, 2));
        r1 = fmaxf(r1, __shfl_xor_sync(0xffffffffu, r1, 1));
        r1 = fmaxf(r1, __shfl_xor_sync(0xffffffffu, r1, 2));
        float m0n = fmaxf(m0, r0);
        float m1n = fmaxf(m1, r1);
        float f0 = __expf(m0 - m0n);
        float f1 = __expf(m1 - m1n);
        l0 *= f0; l1 *= f1;
        #pragma unroll
        for (int nf = 0; nf < 8; nf++) {
            oacc[nf][0] *= f0; oacc[nf][1] *= f0;
            oacc[nf][2] *= f1; oacc[nf][3] *= f1;
        }
        m0 = m0n; m1 = m1n;

        float ps0 = 0.f, ps1 = 0.f;
        uint32_t* Pr0 = (uint32_t*)(Ps + g * PST);
        uint32_t* Pr1 = (uint32_t*)(Ps + (g + 8) * PST);
        #pragma unroll
        for (int nf = 0; nf < 8; nf++) {
            float p0 = __expf(sacc[nf][0] - m0n);
            float p1 = __expf(sacc[nf][1] - m0n);
            float p2 = __expf(sacc[nf][2] - m1n);
            float p3 = __expf(sacc[nf][3] - m1n);
            ps0 += p0 + p1;
            ps1 += p2 + p3;
            uint2 w0 = {f2tf32(p0), f2tf32(p1)};
            uint2 w1 = {f2tf32(p2), f2tf32(p3)};
            *(uint2*)&Pr0[nf * 8 + 2 * tig] = w0;
            *(uint2*)&Pr1[nf * 8 + 2 * tig] = w1;
        }
        ps0 += __shfl_xor_sync(0xffffffffu, ps0, 1);
        ps0 += __shfl_xor_sync(0xffffffffu, ps0, 2);
        ps1 += __shfl_xor_sync(0xffffffffu, ps1, 1);
        ps1 += __shfl_xor_sync(0xffffffffu, ps1, 2);
        l0 += ps0; l1 += ps1;
        __syncwarp();

        // O += P V
        #pragma unroll
        for (int kf = 0; kf < 8; kf++) {
            uint32_t a[4];
            a[0] = *(uint32_t*)&Ps[g * PST + kf * 8 + tig];
            a[1] = *(uint32_t*)&Ps[(g + 8) * PST + kf * 8 + tig];
            a[2] = *(uint32_t*)&Ps[g * PST + kf * 8 + tig + 4];
            a[3] = *(uint32_t*)&Ps[(g + 8) * PST + kf * 8 + tig + 4];
            const uint32_t* V0 = (const uint32_t*)(Vs + (kf * 8 + tig) * VST);
            const uint32_t* V1 = (const uint32_t*)(Vs + (kf * 8 + tig + 4) * VST);
            #pragma unroll
            for (int nf = 0; nf < 8; nf++) {
                mma_tf32(oacc[nf], a, V0[nf * 8 + g], V1[nf * 8 + g]);
            }
        }
        __syncwarp();
    }

    // epilogue: normalize, split to bf16 hi/lo, write [B,T,C]
    float inv0 = 1.f / l0;
    float inv1 = 1.f / l1;
    const int t0 = q0 + warp * 16 + g;
    __nv_bfloat16* oh0 = g_ah + ((size_t)b * T_ + t0) * C_ + h * D_;
    __nv_bfloat16* ol0 = g_al + ((size_t)b * T_ + t0) * C_ + h * D_;
    __nv_bfloat16* oh1 = oh0 + 8 * (size_t)C_;
    __nv_bfloat16* ol1 = ol0 + 8 * (size_t)C_;
    #pragma unroll
    for (int nf = 0; nf < 8; nf++) {
        const int c = nf * 8 + 2 * tig;
        float v0 = oacc[nf][0] * inv0, v1 = oacc[nf][1] * inv0;
        float v2 = oacc[nf][2] * inv1, v3 = oacc[nf][3] * inv1;
        __nv_bfloat16 h0 = __float2bfloat16(v0), h1 = __float2bfloat16(v1);
        __nv_bfloat16 h2 = __float2bfloat16(v2), h3 = __float2bfloat16(v3);
        *(__nv_bfloat162*)&oh0[c] = __halves2bfloat162(h0, h1);
        *(__nv_bfloat162*)&oh1[c] = __halves2bfloat162(h2, h3);
        *(__nv_bfloat162*)&ol0[c] = __halves2bfloat162(
            __float2bfloat16(v0 - __bfloat162float(h0)),
            __float2bfloat16(v1 - __bfloat162float(h1)));
        *(__nv_bfloat162*)&ol1[c] = __halves2bfloat162(
            __float2bfloat16(v2 - __bfloat162float(h2)),
            __float2bfloat16(v3 - __bfloat162float(h3)));
    }
}

// ---------------------------------------------------------------------------
extern "C" void kernel_launch(void* const* d_in, const int* in_sizes, int n_in,
                              void* d_out, int out_size)
{
    const float* x     = (const float*)d_in[0];   // [2,2048,1024]
    const float* W_qkv = (const float*)d_in[1];   // [1024,3072]
    const float* b_qkv = (const float*)d_in[2];   // [3072]
    const float* W_out = (const float*)d_in[3];   // [1024,1024]
    const float* b_out = (const float*)d_in[4];   // [1024]
    float* out = (float*)d_out;                   // [2,2048,1024]

    (void)in_sizes; (void)n_in; (void)out_size;

    const int ATTN_SMEM = (64 * KST + 64 * VST + 4 * 16 * PST) * 4;  // 57344
    cudaFuncSetAttribute(attn_kernel,
                         cudaFuncAttributeMaxDynamicSharedMemorySize, ATTN_SMEM);

    // 0) conversions
    conv_x_kernel<<<(BT * C_ / 4) / 256, 256>>>((const float4*)x);
    {
        dim3 blk(32, 8);
        conv_wt_kernel<<<dim3(N3C / 32, C_ / 32), blk>>>(W_qkv, 0, C_, N3C);
        conv_wt_kernel<<<dim3(C_ / 32, C_ / 32), blk>>>(W_out, 1, C_, C_);
    }
    // 1) QKV projection (bf16x3 mma.sync) + scatter to [B,H,T,D]
    mma_gemm_kernel<<<dim3(N3C / 128, BT / 128), 256>>>(b_qkv, nullptr, 0);
    // 2) Flash attention (tf32 mma.sync), emits bf16 hi/lo
    attn_kernel<<<dim3(T_ / 64, H_, B_), 128, ATTN_SMEM>>>();
    // 3) Output projection (bf16x3 mma.sync)
    mma_gemm_kernel<<<dim3(C_ / 128, BT / 128), 256>>>(b_out, out, 1);
}

// round 4
// speedup vs baseline: 4.3740x; 1.0506x over previous
#include <cuda_runtime.h>
#include <cuda_bf16.h>
#include <stdint.h>
#include <math.h>

// Problem constants
#define B_  2
#define T_  2048
#define C_  1024
#define H_  16
#define D_  64
#define BT  (B_*T_)          // 4096
#define N3C (3*C_)           // 3072

// Scratch (device globals; no allocation allowed)
__device__ float g_q[B_*H_*T_*D_];     // [B,H,T,D] fp32
__device__ float g_k[B_*H_*T_*D_];
__device__ float g_v[B_*H_*T_*D_];
__device__ __align__(16) __nv_bfloat16 g_xh[BT*C_];    // x hi/lo
__device__ __align__(16) __nv_bfloat16 g_xl[BT*C_];
__device__ __align__(16) __nv_bfloat16 g_wqh[N3C*C_];  // W_qkv^T [3072][1024] hi/lo
__device__ __align__(16) __nv_bfloat16 g_wql[N3C*C_];
__device__ __align__(16) __nv_bfloat16 g_woh[C_*C_];   // W_out^T [1024][1024] hi/lo
__device__ __align__(16) __nv_bfloat16 g_wol[C_*C_];
__device__ __align__(16) __nv_bfloat16 g_ah[BT*C_];    // attn out hi/lo [B,T,C]
__device__ __align__(16) __nv_bfloat16 g_al[BT*C_];

// ---------------------------------------------------------------------------
// mma.sync helpers (arch-portable; compiles for compute_103)
// ---------------------------------------------------------------------------
__device__ __forceinline__ void mma_bf16(float* c, const uint32_t* a, uint32_t b0, uint32_t b1) {
    asm volatile("mma.sync.aligned.m16n8k16.row.col.f32.bf16.bf16.f32 "
        "{%0,%1,%2,%3}, {%4,%5,%6,%7}, {%8,%9}, {%0,%1,%2,%3};"
        : "+f"(c[0]), "+f"(c[1]), "+f"(c[2]), "+f"(c[3])
        : "r"(a[0]), "r"(a[1]), "r"(a[2]), "r"(a[3]), "r"(b0), "r"(b1));
}
__device__ __forceinline__ void mma_tf32(float* c, const uint32_t* a, uint32_t b0, uint32_t b1) {
    asm volatile("mma.sync.aligned.m16n8k8.row.col.f32.tf32.tf32.f32 "
        "{%0,%1,%2,%3}, {%4,%5,%6,%7}, {%8,%9}, {%0,%1,%2,%3};"
        : "+f"(c[0]), "+f"(c[1]), "+f"(c[2]), "+f"(c[3])
        : "r"(a[0]), "r"(a[1]), "r"(a[2]), "r"(a[3]), "r"(b0), "r"(b1));
}
__device__ __forceinline__ uint32_t f2tf32(float f) {
    uint32_t r; asm("cvt.rna.tf32.f32 %0, %1;" : "=r"(r) : "f"(f)); return r;
}
__device__ __forceinline__ uint32_t smem_u32(const void* p) {
    uint32_t a;
    asm("{ .reg .u64 t; cvta.to.shared.u64 t, %1; cvt.u32.u64 %0, t; }" : "=r"(a) : "l"(p));
    return a;
}
__device__ __forceinline__ void cp16(uint32_t dst, const void* src) {
    asm volatile("cp.async.cg.shared.global [%0], [%1], 16;" :: "r"(dst), "l"(src));
}
#define CP_COMMIT() asm volatile("cp.async.commit_group;" ::: "memory")
#define CP_WAIT(n)  asm volatile("cp.async.wait_group %0;" :: "n"(n) : "memory")

// ---------------------------------------------------------------------------
// Kernel 0a: convert x fp32 -> hi/lo bf16
// ---------------------------------------------------------------------------
__global__ __launch_bounds__(256)
void conv_x_kernel(const float4* __restrict__ X)
{
    int i = blockIdx.x * 256 + threadIdx.x;   // one float4 per thread
    float4 v = X[i];
    __nv_bfloat16 hx = __float2bfloat16(v.x);
    __nv_bfloat16 hy = __float2bfloat16(v.y);
    __nv_bfloat16 hz = __float2bfloat16(v.z);
    __nv_bfloat16 hw = __float2bfloat16(v.w);
    __nv_bfloat16 lx = __float2bfloat16(v.x - __bfloat162float(hx));
    __nv_bfloat16 ly = __float2bfloat16(v.y - __bfloat162float(hy));
    __nv_bfloat16 lz = __float2bfloat16(v.z - __bfloat162float(hz));
    __nv_bfloat16 lw = __float2bfloat16(v.w - __bfloat162float(hw));
    __nv_bfloat162* ph = (__nv_bfloat162*)g_xh + (size_t)i * 2;
    __nv_bfloat162* pl = (__nv_bfloat162*)g_xl + (size_t)i * 2;
    ph[0] = __halves2bfloat162(hx, hy);
    ph[1] = __halves2bfloat162(hz, hw);
    pl[0] = __halves2bfloat162(lx, ly);
    pl[1] = __halves2bfloat162(lz, lw);
}

// ---------------------------------------------------------------------------
// Kernel 0b: transpose + convert W [K,N] fp32 -> WT [N,K] hi/lo bf16
// ---------------------------------------------------------------------------
__global__ __launch_bounds__(256)
void conv_wt_kernel(const float* __restrict__ W, int which, int K, int N)
{
    __shared__ float tile[32][33];
    int n0 = blockIdx.x * 32;
    int k0 = blockIdx.y * 32;
    int tx = threadIdx.x;       // 0..31
    int ty = threadIdx.y;       // 0..7

    #pragma unroll
    for (int i = 0; i < 32; i += 8)
        tile[ty + i][tx] = W[(size_t)(k0 + ty + i) * N + n0 + tx];
    __syncthreads();

    __nv_bfloat16* Th = which ? g_woh : g_wqh;
    __nv_bfloat16* Tl = which ? g_wol : g_wql;
    #pragma unroll
    for (int i = 0; i < 32; i += 8) {
        float v = tile[tx][ty + i];
        __nv_bfloat16 h = __float2bfloat16(v);
        __nv_bfloat16 l = __float2bfloat16(v - __bfloat162float(h));
        size_t idx = (size_t)(n0 + ty + i) * K + k0 + tx;
        Th[idx] = h;
        Tl[idx] = l;
    }
}

// ---------------------------------------------------------------------------
// Kernel 1/3: bf16x3 GEMM via mma.sync + 3-stage cp.async pipeline.
// Block tile 128x128, kc=32, 8 warps = 2(M) x 4(N), warp tile 64x32.
// ---------------------------------------------------------------------------
#define AST 40           // smem row stride (bf16): bank-conflict-free frag loads
#define TILE_B  (128*AST*2)          // 10240 bytes per tile
#define STAGE_B (4*TILE_B)           // AH, AL, BH, BL
#define STAGES  3
#define KT      (C_/32)              // 32 k-tiles

__global__ __launch_bounds__(256, 1)
void mma_gemm_kernel(const float* __restrict__ bias, float* __restrict__ outp, int mode)
{
    extern __shared__ char smem[];
    const uint32_t sb = smem_u32(smem);

    const int tid  = threadIdx.x;
    const int m0   = blockIdx.y * 128;
    const int n0   = blockIdx.x * 128;
    const int warp = tid >> 5, lane = tid & 31;
    const int mw = warp & 1, nw = warp >> 1;
    const int g = lane >> 2, tig = lane & 3;

    const __nv_bfloat16* Ah = mode ? g_ah : g_xh;
    const __nv_bfloat16* Al = mode ? g_al : g_xl;
    const __nv_bfloat16* Bh = mode ? g_woh : g_wqh;
    const __nv_bfloat16* Bl = mode ? g_wol : g_wql;

    // gmem load mapping: thread -> (row = tid>>1, 2 x 16B of k)
    const int lrow = tid >> 1;
    const int lofs = (tid & 1) * 16;
    const __nv_bfloat16* pAh = Ah + (size_t)(m0 + lrow) * C_ + lofs;
    const __nv_bfloat16* pAl = Al + (size_t)(m0 + lrow) * C_ + lofs;
    const __nv_bfloat16* pBh = Bh + (size_t)(n0 + lrow) * C_ + lofs;
    const __nv_bfloat16* pBl = Bl + (size_t)(n0 + lrow) * C_ + lofs;
    const uint32_t soff = (uint32_t)(lrow * AST + lofs) * 2;

    float acc[16][4];
    #pragma unroll
    for (int i = 0; i < 16; i++)
        #pragma unroll
        for (int j = 0; j < 4; j++) acc[i][j] = 0.f;

    // stage issue: 8 cp.async (4 tiles x 32B)
    #define ISSUE(ktile, stg) do {                                             \
        uint32_t s0 = sb + (uint32_t)(stg) * STAGE_B + soff;                   \
        const int ko = (ktile) * 32;                                           \
        cp16(s0,                 pAh + ko); cp16(s0 + 16,              pAh + ko + 8); \
        cp16(s0 + TILE_B,        pAl + ko); cp16(s0 + TILE_B + 16,     pAl + ko + 8); \
        cp16(s0 + 2*TILE_B,      pBh + ko); cp16(s0 + 2*TILE_B + 16,   pBh + ko + 8); \
        cp16(s0 + 3*TILE_B,      pBl + ko); cp16(s0 + 3*TILE_B + 16,   pBl + ko + 8); \
    } while (0)

    // prologue: stages 0..STAGES-2 in flight
    ISSUE(0, 0); CP_COMMIT();
    ISSUE(1, 1); CP_COMMIT();

    for (int kt = 0; kt < KT; kt++) {
        CP_WAIT(1);            // group kt complete
        __syncthreads();

        const int stg = kt % STAGES;
        const __nv_bfloat16* sAh = (const __nv_bfloat16*)(smem + (size_t)stg * STAGE_B);
        const __nv_bfloat16* sAl = sAh + 128 * AST;
        const __nv_bfloat16* sBh = sAl + 128 * AST;
        const __nv_bfloat16* sBl = sBh + 128 * AST;

        #pragma unroll
        for (int ks = 0; ks < 2; ks++) {
            const int kk = ks * 16 + 2 * tig;
            uint32_t ah[4][4], al[4][4];
            #pragma unroll
            for (int mf = 0; mf < 4; mf++) {
                const int r = mw * 64 + mf * 16;
                ah[mf][0] = *(const uint32_t*)&sAh[(r + g)     * AST + kk];
                ah[mf][1] = *(const uint32_t*)&sAh[(r + g + 8) * AST + kk];
                ah[mf][2] = *(const uint32_t*)&sAh[(r + g)     * AST + kk + 8];
                ah[mf][3] = *(const uint32_t*)&sAh[(r + g + 8) * AST + kk + 8];
                al[mf][0] = *(const uint32_t*)&sAl[(r + g)     * AST + kk];
                al[mf][1] = *(const uint32_t*)&sAl[(r + g + 8) * AST + kk];
                al[mf][2] = *(const uint32_t*)&sAl[(r + g)     * AST + kk + 8];
                al[mf][3] = *(const uint32_t*)&sAl[(r + g + 8) * AST + kk + 8];
            }
            #pragma unroll
            for (int nf = 0; nf < 4; nf++) {
                const int c = nw * 32 + nf * 8 + g;
                uint32_t bh0 = *(const uint32_t*)&sBh[c * AST + kk];
                uint32_t bh1 = *(const uint32_t*)&sBh[c * AST + kk + 8];
                uint32_t bl0 = *(const uint32_t*)&sBl[c * AST + kk];
                uint32_t bl1 = *(const uint32_t*)&sBl[c * AST + kk + 8];
                #pragma unroll
                for (int mf = 0; mf < 4; mf++) {
                    mma_bf16(acc[mf * 4 + nf], ah[mf], bh0, bh1);
                    mma_bf16(acc[mf * 4 + nf], ah[mf], bl0, bl1);
                    mma_bf16(acc[mf * 4 + nf], al[mf], bh0, bh1);
                }
            }
        }
        __syncthreads();       // all reads of stage (kt+2)%3 buffer done before refill
        if (kt + STAGES - 1 < KT) ISSUE(kt + STAGES - 1, (kt + STAGES - 1) % STAGES);
        CP_COMMIT();           // commit every iter (possibly empty) to keep group count exact
    }
    #undef ISSUE

    // Epilogue
    #pragma unroll
    for (int nf = 0; nf < 4; nf++) {
        const int c = n0 + nw * 32 + nf * 8 + 2 * tig;
        float2 bv = *(const float2*)&bias[c];
        #pragma unroll
        for (int mf = 0; mf < 4; mf++) {
            const float* a = acc[mf * 4 + nf];
            const int r0 = m0 + mw * 64 + mf * 16 + g;
            if (mode == 0) {
                int h  = c / 192;
                int rr = c - h * 192;
                int seg = rr >> 6;
                int d0  = rr & 63;
                float* base = (seg == 0) ? g_q : (seg == 1) ? g_k : g_v;
                int b = r0 >> 11;
                int t = r0 & (T_ - 1);
                size_t idx0 = ((size_t)(b * H_ + h) * T_ + t) * D_ + d0;
                float2 v0 = {a[0] + bv.x, a[1] + bv.y};
                float2 v1 = {a[2] + bv.x, a[3] + bv.y};
                *(float2*)&base[idx0]           = v0;
                *(float2*)&base[idx0 + 8 * D_]  = v1;   // row r0+8, same b/h
            } else {
                float2 v0 = {a[0] + bv.x, a[1] + bv.y};
                float2 v1 = {a[2] + bv.x, a[3] + bv.y};
                *(float2*)&outp[(size_t)r0 * C_ + c]       = v0;
                *(float2*)&outp[(size_t)(r0 + 8) * C_ + c] = v1;
            }
        }
    }
}

// ---------------------------------------------------------------------------
// Kernel 2: flash attention with tf32 mma.sync. (unchanged from R3)
// ---------------------------------------------------------------------------
#define KST 84
#define VST 72
#define PST 68

__global__ __launch_bounds__(128, 3)
void attn_kernel()
{
    extern __shared__ float smf[];
    float* Ks = smf;                       // [64][KST]
    float* Vs = smf + 64 * KST;            // [64][VST]
    const int tid  = threadIdx.x;
    const int warp = tid >> 5, lane = tid & 31;
    const int g = lane >> 2, tig = lane & 3;
    float* Ps = smf + 64 * KST + 64 * VST + warp * 16 * PST;   // per-warp [16][PST]

    const int q0 = blockIdx.x * 64;
    const int h  = blockIdx.y;
    const int b  = blockIdx.z;
    const size_t bh = (size_t)(b * H_ + h);
    const float* Qb = g_q + bh * (T_ * D_);
    const float* Kb = g_k + bh * (T_ * D_);
    const float* Vb = g_v + bh * (T_ * D_);

    uint32_t qf[8][4];
    {
        const float* qr0 = Qb + (size_t)(q0 + warp * 16 + g) * D_;
        const float* qr1 = qr0 + 8 * D_;
        #pragma unroll
        for (int kf = 0; kf < 8; kf++) {
            qf[kf][0] = f2tf32(qr0[kf * 8 + tig]     * 0.125f);
            qf[kf][1] = f2tf32(qr1[kf * 8 + tig]     * 0.125f);
            qf[kf][2] = f2tf32(qr0[kf * 8 + tig + 4] * 0.125f);
            qf[kf][3] = f2tf32(qr1[kf * 8 + tig + 4] * 0.125f);
        }
    }

    float oacc[8][4];
    #pragma unroll
    for (int i = 0; i < 8; i++)
        #pragma unroll
        for (int j = 0; j < 4; j++) oacc[i][j] = 0.f;
    float m0 = -1e30f, m1 = -1e30f, l0 = 0.f, l1 = 0.f;

    for (int kb = 0; kb < T_; kb += 64) {
        __syncthreads();
        {
            const float4* Kg = (const float4*)(Kb + (size_t)kb * D_);
            const float4* Vg = (const float4*)(Vb + (size_t)kb * D_);
            #pragma unroll
            for (int j = 0; j < 8; j++) {
                int flat = j * 128 + tid;
                int row = flat >> 4;
                int c4  = (flat & 15) * 4;
                float4 kv = Kg[flat];
                float4 vv = Vg[flat];
                float4 kt, vt;
                kt.x = __uint_as_float(f2tf32(kv.x));
                kt.y = __uint_as_float(f2tf32(kv.y));
                kt.z = __uint_as_float(f2tf32(kv.z));
                kt.w = __uint_as_float(f2tf32(kv.w));
                vt.x = __uint_as_float(f2tf32(vv.x));
                vt.y = __uint_as_float(f2tf32(vv.y));
                vt.z = __uint_as_float(f2tf32(vv.z));
                vt.w = __uint_as_float(f2tf32(vv.w));
                *(float4*)&Ks[row * KST + c4] = kt;
                *(float4*)&Vs[row * VST + c4] = vt;
            }
        }
        __syncthreads();

        float sacc[8][4];
        #pragma unroll
        for (int i = 0; i < 8; i++)
            #pragma unroll
            for (int j = 0; j < 4; j++) sacc[i][j] = 0.f;
        #pragma unroll
        for (int nf = 0; nf < 8; nf++) {
            const uint32_t* Kw = (const uint32_t*)(Ks + (nf * 8 + g) * KST);
            #pragma unroll
            for (int kf = 0; kf < 8; kf++) {
                uint32_t b0 = Kw[kf * 8 + tig];
                uint32_t b1 = Kw[kf * 8 + tig + 4];
                mma_tf32(sacc[nf], qf[kf], b0, b1);
            }
        }

        float r0 = -1e30f, r1 = -1e30f;
        #pragma unroll
        for (int nf = 0; nf < 8; nf++) {
            r0 = fmaxf(r0, fmaxf(sacc[nf][0], sacc[nf][1]));
            r1 = fmaxf(r1, fmaxf(sacc[nf][2], sacc[nf][3]));
        }
        r0 = fmaxf(r0, __shfl_xor_sync(0xffffffffu, r0, 1));
        r0 = fmaxf(r0, __shfl_xor_sync(0xffffffffu, r0, 2));
        r1 = fmaxf(r1, __shfl_xor_sync(0xffffffffu, r1, 1));
        r1 = fmaxf(r1, __shfl_xor_sync(0xffffffffu, r1, 2));
        float m0n = fmaxf(m0, r0);
        float m1n = fmaxf(m1, r1);
        float f0 = __expf(m0 - m0n);
        float f1 = __expf(m1 - m1n);
        l0 *= f0; l1 *= f1;
        #pragma unroll
        for (int nf = 0; nf < 8; nf++) {
            oacc[nf][0] *= f0; oacc[nf][1] *= f0;
            oacc[nf][2] *= f1; oacc[nf][3] *= f1;
        }
        m0 = m0n; m1 = m1n;

        float ps0 = 0.f, ps1 = 0.f;
        uint32_t* Pr0 = (uint32_t*)(Ps + g * PST);
        uint32_t* Pr1 = (uint32_t*)(Ps + (g + 8) * PST);
        #pragma unroll
        for (int nf = 0; nf < 8; nf++) {
            float p0 = __expf(sacc[nf][0] - m0n);
            float p1 = __expf(sacc[nf][1] - m0n);
            float p2 = __expf(sacc[nf][2] - m1n);
            float p3 = __expf(sacc[nf][3] - m1n);
            ps0 += p0 + p1;
            ps1 += p2 + p3;
            uint2 w0 = {f2tf32(p0), f2tf32(p1)};
            uint2 w1 = {f2tf32(p2), f2tf32(p3)};
            *(uint2*)&Pr0[nf * 8 + 2 * tig] = w0;
            *(uint2*)&Pr1[nf * 8 + 2 * tig] = w1;
        }
        ps0 += __shfl_xor_sync(0xffffffffu, ps0, 1);
        ps0 += __shfl_xor_sync(0xffffffffu, ps0, 2);
        ps1 += __shfl_xor_sync(0xffffffffu, ps1, 1);
        ps1 += __shfl_xor_sync(0xffffffffu, ps1, 2);
        l0 += ps0; l1 += ps1;
        __syncwarp();

        #pragma unroll
        for (int kf = 0; kf < 8; kf++) {
            uint32_t a[4];
            a[0] = *(uint32_t*)&Ps[g * PST + kf * 8 + tig];
            a[1] = *(uint32_t*)&Ps[(g + 8) * PST + kf * 8 + tig];
            a[2] = *(uint32_t*)&Ps[g * PST + kf * 8 + tig + 4];
            a[3] = *(uint32_t*)&Ps[(g + 8) * PST + kf * 8 + tig + 4];
            const uint32_t* V0 = (const uint32_t*)(Vs + (kf * 8 + tig) * VST);
            const uint32_t* V1 = (const uint32_t*)(Vs + (kf * 8 + tig + 4) * VST);
            #pragma unroll
            for (int nf = 0; nf < 8; nf++) {
                mma_tf32(oacc[nf], a, V0[nf * 8 + g], V1[nf * 8 + g]);
            }
        }
        __syncwarp();
    }

    float inv0 = 1.f / l0;
    float inv1 = 1.f / l1;
    const int t0 = q0 + warp * 16 + g;
    __nv_bfloat16* oh0 = g_ah + ((size_t)b * T_ + t0) * C_ + h * D_;
    __nv_bfloat16* ol0 = g_al + ((size_t)b * T_ + t0) * C_ + h * D_;
    __nv_bfloat16* oh1 = oh0 + 8 * (size_t)C_;
    __nv_bfloat16* ol1 = ol0 + 8 * (size_t)C_;
    #pragma unroll
    for (int nf = 0; nf < 8; nf++) {
        const int c = nf * 8 + 2 * tig;
        float v0 = oacc[nf][0] * inv0, v1 = oacc[nf][1] * inv0;
        float v2 = oacc[nf][2] * inv1, v3 = oacc[nf][3] * inv1;
        __nv_bfloat16 h0 = __float2bfloat16(v0), h1 = __float2bfloat16(v1);
        __nv_bfloat16 h2 = __float2bfloat16(v2), h3 = __float2bfloat16(v3);
        *(__nv_bfloat162*)&oh0[c] = __halves2bfloat162(h0, h1);
        *(__nv_bfloat162*)&oh1[c] = __halves2bfloat162(h2, h3);
        *(__nv_bfloat162*)&ol0[c] = __halves2bfloat162(
            __float2bfloat16(v0 - __bfloat162float(h0)),
            __float2bfloat16(v1 - __bfloat162float(h1)));
        *(__nv_bfloat162*)&ol1[c] = __halves2bfloat162(
            __float2bfloat16(v2 - __bfloat162float(h2)),
            __float2bfloat16(v3 - __bfloat162float(h3)));
    }
}

// ---------------------------------------------------------------------------
extern "C" void kernel_launch(void* const* d_in, const int* in_sizes, int n_in,
                              void* d_out, int out_size)
{
    const float* x     = (const float*)d_in[0];   // [2,2048,1024]
    const float* W_qkv = (const float*)d_in[1];   // [1024,3072]
    const float* b_qkv = (const float*)d_in[2];   // [3072]
    const float* W_out = (const float*)d_in[3];   // [1024,1024]
    const float* b_out = (const float*)d_in[4];   // [1024]
    float* out = (float*)d_out;                   // [2,2048,1024]

    (void)in_sizes; (void)n_in; (void)out_size;

    const int GEMM_SMEM = STAGES * STAGE_B;        // 3 * 40960 = 122880
    cudaFuncSetAttribute(mma_gemm_kernel,
                         cudaFuncAttributeMaxDynamicSharedMemorySize, GEMM_SMEM);
    const int ATTN_SMEM = (64 * KST + 64 * VST + 4 * 16 * PST) * 4;  // 57344
    cudaFuncSetAttribute(attn_kernel,
                         cudaFuncAttributeMaxDynamicSharedMemorySize, ATTN_SMEM);

    // 0) conversions
    conv_x_kernel<<<(BT * C_ / 4) / 256, 256>>>((const float4*)x);
    {
        dim3 blk(32, 8);
        conv_wt_kernel<<<dim3(N3C / 32, C_ / 32), blk>>>(W_qkv, 0, C_, N3C);
        conv_wt_kernel<<<dim3(C_ / 32, C_ / 32), blk>>>(W_out, 1, C_, C_);
    }
    // 1) QKV projection (bf16x3 mma.sync, cp.async pipeline)
    mma_gemm_kernel<<<dim3(N3C / 128, BT / 128), 256, GEMM_SMEM>>>(b_qkv, nullptr, 0);
    // 2) Flash attention (tf32 mma.sync)
    attn_kernel<<<dim3(T_ / 64, H_, B_), 128, ATTN_SMEM>>>();
    // 3) Output projection (bf16x3 mma.sync, cp.async pipeline)
    mma_gemm_kernel<<<dim3(C_ / 128, BT / 128), 256, GEMM_SMEM>>>(b_out, out, 1);
}

// round 5
// speedup vs baseline: 4.6305x; 1.0586x over previous
#include <cuda_runtime.h>
#include <cuda_bf16.h>
#include <stdint.h>
#include <math.h>

// Problem constants
#define B_  2
#define T_  2048
#define C_  1024
#define H_  16
#define D_  64
#define BT  (B_*T_)          // 4096
#define N3C (3*C_)           // 3072

// Scratch (device globals; no allocation allowed)
__device__ float g_q[B_*H_*T_*D_];     // [B,H,T,D] fp32
__device__ float g_k[B_*H_*T_*D_];
__device__ float g_v[B_*H_*T_*D_];
__device__ __align__(16) __nv_bfloat16 g_xh[BT*C_];    // x hi/lo
__device__ __align__(16) __nv_bfloat16 g_xl[BT*C_];
__device__ __align__(16) __nv_bfloat16 g_wqh[N3C*C_];  // W_qkv^T [3072][1024] hi/lo
__device__ __align__(16) __nv_bfloat16 g_wql[N3C*C_];
__device__ __align__(16) __nv_bfloat16 g_woh[C_*C_];   // W_out^T [1024][1024] hi/lo
__device__ __align__(16) __nv_bfloat16 g_wol[C_*C_];
__device__ __align__(16) __nv_bfloat16 g_ah[BT*C_];    // attn out hi/lo [B,T,C]
__device__ __align__(16) __nv_bfloat16 g_al[BT*C_];

// ---------------------------------------------------------------------------
// mma.sync helpers (arch-portable; compiles for compute_103)
// ---------------------------------------------------------------------------
__device__ __forceinline__ void mma_bf16(float* c, const uint32_t* a, uint32_t b0, uint32_t b1) {
    asm volatile("mma.sync.aligned.m16n8k16.row.col.f32.bf16.bf16.f32 "
        "{%0,%1,%2,%3}, {%4,%5,%6,%7}, {%8,%9}, {%0,%1,%2,%3};"
        : "+f"(c[0]), "+f"(c[1]), "+f"(c[2]), "+f"(c[3])
        : "r"(a[0]), "r"(a[1]), "r"(a[2]), "r"(a[3]), "r"(b0), "r"(b1));
}
__device__ __forceinline__ void mma_tf32(float* c, const uint32_t* a, uint32_t b0, uint32_t b1) {
    asm volatile("mma.sync.aligned.m16n8k8.row.col.f32.tf32.tf32.f32 "
        "{%0,%1,%2,%3}, {%4,%5,%6,%7}, {%8,%9}, {%0,%1,%2,%3};"
        : "+f"(c[0]), "+f"(c[1]), "+f"(c[2]), "+f"(c[3])
        : "r"(a[0]), "r"(a[1]), "r"(a[2]), "r"(a[3]), "r"(b0), "r"(b1));
}
__device__ __forceinline__ uint32_t f2tf32(float f) {
    uint32_t r; asm("cvt.rna.tf32.f32 %0, %1;" : "=r"(r) : "f"(f)); return r;
}
__device__ __forceinline__ uint32_t smem_u32(const void* p) {
    uint32_t a;
    asm("{ .reg .u64 t; cvta.to.shared.u64 t, %1; cvt.u32.u64 %0, t; }" : "=r"(a) : "l"(p));
    return a;
}
__device__ __forceinline__ void cp16(uint32_t dst, const void* src) {
    asm volatile("cp.async.cg.shared.global [%0], [%1], 16;" :: "r"(dst), "l"(src));
}
#define CP_COMMIT() asm volatile("cp.async.commit_group;" ::: "memory")
#define CP_WAIT(n)  asm volatile("cp.async.wait_group %0;" :: "n"(n) : "memory")

// ---------------------------------------------------------------------------
// Kernel 0a: convert x fp32 -> hi/lo bf16
// ---------------------------------------------------------------------------
__global__ __launch_bounds__(256)
void conv_x_kernel(const float4* __restrict__ X)
{
    int i = blockIdx.x * 256 + threadIdx.x;   // one float4 per thread
    float4 v = X[i];
    __nv_bfloat16 hx = __float2bfloat16(v.x);
    __nv_bfloat16 hy = __float2bfloat16(v.y);
    __nv_bfloat16 hz = __float2bfloat16(v.z);
    __nv_bfloat16 hw = __float2bfloat16(v.w);
    __nv_bfloat16 lx = __float2bfloat16(v.x - __bfloat162float(hx));
    __nv_bfloat16 ly = __float2bfloat16(v.y - __bfloat162float(hy));
    __nv_bfloat16 lz = __float2bfloat16(v.z - __bfloat162float(hz));
    __nv_bfloat16 lw = __float2bfloat16(v.w - __bfloat162float(hw));
    __nv_bfloat162* ph = (__nv_bfloat162*)g_xh + (size_t)i * 2;
    __nv_bfloat162* pl = (__nv_bfloat162*)g_xl + (size_t)i * 2;
    ph[0] = __halves2bfloat162(hx, hy);
    ph[1] = __halves2bfloat162(hz, hw);
    pl[0] = __halves2bfloat162(lx, ly);
    pl[1] = __halves2bfloat162(lz, lw);
}

// ---------------------------------------------------------------------------
// Kernel 0b: transpose + convert W [K,N] fp32 -> WT [N,K] hi/lo bf16
// ---------------------------------------------------------------------------
__global__ __launch_bounds__(256)
void conv_wt_kernel(const float* __restrict__ W, int which, int K, int N)
{
    __shared__ float tile[32][33];
    int n0 = blockIdx.x * 32;
    int k0 = blockIdx.y * 32;
    int tx = threadIdx.x;       // 0..31
    int ty = threadIdx.y;       // 0..7

    #pragma unroll
    for (int i = 0; i < 32; i += 8)
        tile[ty + i][tx] = W[(size_t)(k0 + ty + i) * N + n0 + tx];
    __syncthreads();

    __nv_bfloat16* Th = which ? g_woh : g_wqh;
    __nv_bfloat16* Tl = which ? g_wol : g_wql;
    #pragma unroll
    for (int i = 0; i < 32; i += 8) {
        float v = tile[tx][ty + i];
        __nv_bfloat16 h = __float2bfloat16(v);
        __nv_bfloat16 l = __float2bfloat16(v - __bfloat162float(h));
        size_t idx = (size_t)(n0 + ty + i) * K + k0 + tx;
        Th[idx] = h;
        Tl[idx] = l;
    }
}

// ---------------------------------------------------------------------------
// Kernel 1/3: bf16x3 GEMM via mma.sync + 2-stage cp.async pipeline.
// Block tile 128x128, kc=32, 8 warps = 2(M) x 4(N), warp tile 64x32.
// 80KB smem/CTA -> 2 CTAs/SM (16 warps) for latency hiding.
// ---------------------------------------------------------------------------
#define AST 40           // smem row stride (bf16): bank-conflict-free frag loads
#define TILE_B  (128*AST*2)          // 10240 bytes per tile
#define STAGE_B (4*TILE_B)           // AH, AL, BH, BL
#define STAGES  2
#define KT      (C_/32)              // 32 k-tiles

__global__ __launch_bounds__(256, 2)
void mma_gemm_kernel(const float* __restrict__ bias, float* __restrict__ outp, int mode)
{
    extern __shared__ char smem[];
    const uint32_t sb = smem_u32(smem);

    const int tid  = threadIdx.x;
    const int m0   = blockIdx.y * 128;
    const int n0   = blockIdx.x * 128;
    const int warp = tid >> 5, lane = tid & 31;
    const int mw = warp & 1, nw = warp >> 1;
    const int g = lane >> 2, tig = lane & 3;

    const __nv_bfloat16* Ah = mode ? g_ah : g_xh;
    const __nv_bfloat16* Al = mode ? g_al : g_xl;
    const __nv_bfloat16* Bh = mode ? g_woh : g_wqh;
    const __nv_bfloat16* Bl = mode ? g_wol : g_wql;

    // gmem load mapping: thread -> (row = tid>>1, 2 x 16B of k)
    const int lrow = tid >> 1;
    const int lofs = (tid & 1) * 16;
    const __nv_bfloat16* pAh = Ah + (size_t)(m0 + lrow) * C_ + lofs;
    const __nv_bfloat16* pAl = Al + (size_t)(m0 + lrow) * C_ + lofs;
    const __nv_bfloat16* pBh = Bh + (size_t)(n0 + lrow) * C_ + lofs;
    const __nv_bfloat16* pBl = Bl + (size_t)(n0 + lrow) * C_ + lofs;
    const uint32_t soff = (uint32_t)(lrow * AST + lofs) * 2;

    float acc[16][4];
    #pragma unroll
    for (int i = 0; i < 16; i++)
        #pragma unroll
        for (int j = 0; j < 4; j++) acc[i][j] = 0.f;

    // stage issue: 8 cp.async (4 tiles x 32B)
    #define ISSUE(ktile, stg) do {                                             \
        uint32_t s0 = sb + (uint32_t)(stg) * STAGE_B + soff;                   \
        const int ko = (ktile) * 32;                                           \
        cp16(s0,                 pAh + ko); cp16(s0 + 16,              pAh + ko + 8); \
        cp16(s0 + TILE_B,        pAl + ko); cp16(s0 + TILE_B + 16,     pAl + ko + 8); \
        cp16(s0 + 2*TILE_B,      pBh + ko); cp16(s0 + 2*TILE_B + 16,   pBh + ko + 8); \
        cp16(s0 + 3*TILE_B,      pBl + ko); cp16(s0 + 3*TILE_B + 16,   pBl + ko + 8); \
    } while (0)

    // prologue: stage 0 in flight
    ISSUE(0, 0); CP_COMMIT();

    for (int kt = 0; kt < KT; kt++) {
        // issue next tile into the other buffer (read of that buffer finished
        // before the trailing __syncthreads of iteration kt-1)
        if (kt + 1 < KT) ISSUE(kt + 1, (kt + 1) & 1);
        CP_COMMIT();           // always commit to keep group count exact
        CP_WAIT(1);            // group kt complete; group kt+1 still in flight
        __syncthreads();

        const __nv_bfloat16* sAh = (const __nv_bfloat16*)(smem + (size_t)(kt & 1) * STAGE_B);
        const __nv_bfloat16* sAl = sAh + 128 * AST;
        const __nv_bfloat16* sBh = sAl + 128 * AST;
        const __nv_bfloat16* sBl = sBh + 128 * AST;

        #pragma unroll
        for (int ks = 0; ks < 2; ks++) {
            const int kk = ks * 16 + 2 * tig;
            uint32_t ah[4][4], al[4][4];
            #pragma unroll
            for (int mf = 0; mf < 4; mf++) {
                const int r = mw * 64 + mf * 16;
                ah[mf][0] = *(const uint32_t*)&sAh[(r + g)     * AST + kk];
                ah[mf][1] = *(const uint32_t*)&sAh[(r + g + 8) * AST + kk];
                ah[mf][2] = *(const uint32_t*)&sAh[(r + g)     * AST + kk + 8];
                ah[mf][3] = *(const uint32_t*)&sAh[(r + g + 8) * AST + kk + 8];
                al[mf][0] = *(const uint32_t*)&sAl[(r + g)     * AST + kk];
                al[mf][1] = *(const uint32_t*)&sAl[(r + g + 8) * AST + kk];
                al[mf][2] = *(const uint32_t*)&sAl[(r + g)     * AST + kk + 8];
                al[mf][3] = *(const uint32_t*)&sAl[(r + g + 8) * AST + kk + 8];
            }
            #pragma unroll
            for (int nf = 0; nf < 4; nf++) {
                const int c = nw * 32 + nf * 8 + g;
                uint32_t bh0 = *(const uint32_t*)&sBh[c * AST + kk];
                uint32_t bh1 = *(const uint32_t*)&sBh[c * AST + kk + 8];
                uint32_t bl0 = *(const uint32_t*)&sBl[c * AST + kk];
                uint32_t bl1 = *(const uint32_t*)&sBl[c * AST + kk + 8];
                #pragma unroll
                for (int mf = 0; mf < 4; mf++) {
                    mma_bf16(acc[mf * 4 + nf], ah[mf], bh0, bh1);
                    mma_bf16(acc[mf * 4 + nf], ah[mf], bl0, bl1);
                    mma_bf16(acc[mf * 4 + nf], al[mf], bh0, bh1);
                }
            }
        }
        __syncthreads();       // all reads of this buffer done before refill
    }
    #undef ISSUE

    // Epilogue
    #pragma unroll
    for (int nf = 0; nf < 4; nf++) {
        const int c = n0 + nw * 32 + nf * 8 + 2 * tig;
        float2 bv = *(const float2*)&bias[c];
        #pragma unroll
        for (int mf = 0; mf < 4; mf++) {
            const float* a = acc[mf * 4 + nf];
            const int r0 = m0 + mw * 64 + mf * 16 + g;
            if (mode == 0) {
                int h  = c / 192;
                int rr = c - h * 192;
                int seg = rr >> 6;
                int d0  = rr & 63;
                float* base = (seg == 0) ? g_q : (seg == 1) ? g_k : g_v;
                int b = r0 >> 11;
                int t = r0 & (T_ - 1);
                size_t idx0 = ((size_t)(b * H_ + h) * T_ + t) * D_ + d0;
                float2 v0 = {a[0] + bv.x, a[1] + bv.y};
                float2 v1 = {a[2] + bv.x, a[3] + bv.y};
                *(float2*)&base[idx0]           = v0;
                *(float2*)&base[idx0 + 8 * D_]  = v1;   // row r0+8, same b/h
            } else {
                float2 v0 = {a[0] + bv.x, a[1] + bv.y};
                float2 v1 = {a[2] + bv.x, a[3] + bv.y};
                *(float2*)&outp[(size_t)r0 * C_ + c]       = v0;
                *(float2*)&outp[(size_t)(r0 + 8) * C_ + c] = v1;
            }
        }
    }
}

// ---------------------------------------------------------------------------
// Kernel 2: flash attention with tf32 mma.sync. (unchanged)
// ---------------------------------------------------------------------------
#define KST 84
#define VST 72
#define PST 68

__global__ __launch_bounds__(128, 3)
void attn_kernel()
{
    extern __shared__ float smf[];
    float* Ks = smf;                       // [64][KST]
    float* Vs = smf + 64 * KST;            // [64][VST]
    const int tid  = threadIdx.x;
    const int warp = tid >> 5, lane = tid & 31;
    const int g = lane >> 2, tig = lane & 3;
    float* Ps = smf + 64 * KST + 64 * VST + warp * 16 * PST;   // per-warp [16][PST]

    const int q0 = blockIdx.x * 64;
    const int h  = blockIdx.y;
    const int b  = blockIdx.z;
    const size_t bh = (size_t)(b * H_ + h);
    const float* Qb = g_q + bh * (T_ * D_);
    const float* Kb = g_k + bh * (T_ * D_);
    const float* Vb = g_v + bh * (T_ * D_);

    uint32_t qf[8][4];
    {
        const float* qr0 = Qb + (size_t)(q0 + warp * 16 + g) * D_;
        const float* qr1 = qr0 + 8 * D_;
        #pragma unroll
        for (int kf = 0; kf < 8; kf++) {
            qf[kf][0] = f2tf32(qr0[kf * 8 + tig]     * 0.125f);
            qf[kf][1] = f2tf32(qr1[kf * 8 + tig]     * 0.125f);
            qf[kf][2] = f2tf32(qr0[kf * 8 + tig + 4] * 0.125f);
            qf[kf][3] = f2tf32(qr1[kf * 8 + tig + 4] * 0.125f);
        }
    }

    float oacc[8][4];
    #pragma unroll
    for (int i = 0; i < 8; i++)
        #pragma unroll
        for (int j = 0; j < 4; j++) oacc[i][j] = 0.f;
    float m0 = -1e30f, m1 = -1e30f, l0 = 0.f, l1 = 0.f;

    for (int kb = 0; kb < T_; kb += 64) {
        __syncthreads();
        {
            const float4* Kg = (const float4*)(Kb + (size_t)kb * D_);
            const float4* Vg = (const float4*)(Vb + (size_t)kb * D_);
            #pragma unroll
            for (int j = 0; j < 8; j++) {
                int flat = j * 128 + tid;
                int row = flat >> 4;
                int c4  = (flat & 15) * 4;
                float4 kv = Kg[flat];
                float4 vv = Vg[flat];
                float4 kt, vt;
                kt.x = __uint_as_float(f2tf32(kv.x));
                kt.y = __uint_as_float(f2tf32(kv.y));
                kt.z = __uint_as_float(f2tf32(kv.z));
                kt.w = __uint_as_float(f2tf32(kv.w));
                vt.x = __uint_as_float(f2tf32(vv.x));
                vt.y = __uint_as_float(f2tf32(vv.y));
                vt.z = __uint_as_float(f2tf32(vv.z));
                vt.w = __uint_as_float(f2tf32(vv.w));
                *(float4*)&Ks[row * KST + c4] = kt;
                *(float4*)&Vs[row * VST + c4] = vt;
            }
        }
        __syncthreads();

        float sacc[8][4];
        #pragma unroll
        for (int i = 0; i < 8; i++)
            #pragma unroll
            for (int j = 0; j < 4; j++) sacc[i][j] = 0.f;
        #pragma unroll
        for (int nf = 0; nf < 8; nf++) {
            const uint32_t* Kw = (const uint32_t*)(Ks + (nf * 8 + g) * KST);
            #pragma unroll
            for (int kf = 0; kf < 8; kf++) {
                uint32_t b0 = Kw[kf * 8 + tig];
                uint32_t b1 = Kw[kf * 8 + tig + 4];
                mma_tf32(sacc[nf], qf[kf], b0, b1);
            }
        }

        float r0 = -1e30f, r1 = -1e30f;
        #pragma unroll
        for (int nf = 0; nf < 8; nf++) {
            r0 = fmaxf(r0, fmaxf(sacc[nf][0], sacc[nf][1]));
            r1 = fmaxf(r1, fmaxf(sacc[nf][2], sacc[nf][3]));
        }
        r0 = fmaxf(r0, __shfl_xor_sync(0xffffffffu, r0, 1));
        r0 = fmaxf(r0, __shfl_xor_sync(0xffffffffu, r0, 2));
        r1 = fmaxf(r1, __shfl_xor_sync(0xffffffffu, r1, 1));
        r1 = fmaxf(r1, __shfl_xor_sync(0xffffffffu, r1, 2));
        float m0n = fmaxf(m0, r0);
        float m1n = fmaxf(m1, r1);
        float f0 = __expf(m0 - m0n);
        float f1 = __expf(m1 - m1n);
        l0 *= f0; l1 *= f1;
        #pragma unroll
        for (int nf = 0; nf < 8; nf++) {
            oacc[nf][0] *= f0; oacc[nf][1] *= f0;
            oacc[nf][2] *= f1; oacc[nf][3] *= f1;
        }
        m0 = m0n; m1 = m1n;

        float ps0 = 0.f, ps1 = 0.f;
        uint32_t* Pr0 = (uint32_t*)(Ps + g * PST);
        uint32_t* Pr1 = (uint32_t*)(Ps + (g + 8) * PST);
        #pragma unroll
        for (int nf = 0; nf < 8; nf++) {
            float p0 = __expf(sacc[nf][0] - m0n);
            float p1 = __expf(sacc[nf][1] - m0n);
            float p2 = __expf(sacc[nf][2] - m1n);
            float p3 = __expf(sacc[nf][3] - m1n);
            ps0 += p0 + p1;
            ps1 += p2 + p3;
            uint2 w0 = {f2tf32(p0), f2tf32(p1)};
            uint2 w1 = {f2tf32(p2), f2tf32(p3)};
            *(uint2*)&Pr0[nf * 8 + 2 * tig] = w0;
            *(uint2*)&Pr1[nf * 8 + 2 * tig] = w1;
        }
        ps0 += __shfl_xor_sync(0xffffffffu, ps0, 1);
        ps0 += __shfl_xor_sync(0xffffffffu, ps0, 2);
        ps1 += __shfl_xor_sync(0xffffffffu, ps1, 1);
        ps1 += __shfl_xor_sync(0xffffffffu, ps1, 2);
        l0 += ps0; l1 += ps1;
        __syncwarp();

        #pragma unroll
        for (int kf = 0; kf < 8; kf++) {
            uint32_t a[4];
            a[0] = *(uint32_t*)&Ps[g * PST + kf * 8 + tig];
            a[1] = *(uint32_t*)&Ps[(g + 8) * PST + kf * 8 + tig];
            a[2] = *(uint32_t*)&Ps[g * PST + kf * 8 + tig + 4];
            a[3] = *(uint32_t*)&Ps[(g + 8) * PST + kf * 8 + tig + 4];
            const uint32_t* V0 = (const uint32_t*)(Vs + (kf * 8 + tig) * VST);
            const uint32_t* V1 = (const uint32_t*)(Vs + (kf * 8 + tig + 4) * VST);
            #pragma unroll
            for (int nf = 0; nf < 8; nf++) {
                mma_tf32(oacc[nf], a, V0[nf * 8 + g], V1[nf * 8 + g]);
            }
        }
        __syncwarp();
    }

    float inv0 = 1.f / l0;
    float inv1 = 1.f / l1;
    const int t0 = q0 + warp * 16 + g;
    __nv_bfloat16* oh0 = g_ah + ((size_t)b * T_ + t0) * C_ + h * D_;
    __nv_bfloat16* ol0 = g_al + ((size_t)b * T_ + t0) * C_ + h * D_;
    __nv_bfloat16* oh1 = oh0 + 8 * (size_t)C_;
    __nv_bfloat16* ol1 = ol0 + 8 * (size_t)C_;
    #pragma unroll
    for (int nf = 0; nf < 8; nf++) {
        const int c = nf * 8 + 2 * tig;
        float v0 = oacc[nf][0] * inv0, v1 = oacc[nf][1] * inv0;
        float v2 = oacc[nf][2] * inv1, v3 = oacc[nf][3] * inv1;
        __nv_bfloat16 h0 = __float2bfloat16(v0), h1 = __float2bfloat16(v1);
        __nv_bfloat16 h2 = __float2bfloat16(v2), h3 = __float2bfloat16(v3);
        *(__nv_bfloat162*)&oh0[c] = __halves2bfloat162(h0, h1);
        *(__nv_bfloat162*)&oh1[c] = __halves2bfloat162(h2, h3);
        *(__nv_bfloat162*)&ol0[c] = __halves2bfloat162(
            __float2bfloat16(v0 - __bfloat162float(h0)),
            __float2bfloat16(v1 - __bfloat162float(h1)));
        *(__nv_bfloat162*)&ol1[c] = __halves2bfloat162(
            __float2bfloat16(v2 - __bfloat162float(h2)),
            __float2bfloat16(v3 - __bfloat162float(h3)));
    }
}

// ---------------------------------------------------------------------------
extern "C" void kernel_launch(void* const* d_in, const int* in_sizes, int n_in,
                              void* d_out, int out_size)
{
    const float* x     = (const float*)d_in[0];   // [2,2048,1024]
    const float* W_qkv = (const float*)d_in[1];   // [1024,3072]
    const float* b_qkv = (const float*)d_in[2];   // [3072]
    const float* W_out = (const float*)d_in[3];   // [1024,1024]
    const float* b_out = (const float*)d_in[4];   // [1024]
    float* out = (float*)d_out;                   // [2,2048,1024]

    (void)in_sizes; (void)n_in; (void)out_size;

    const int GEMM_SMEM = STAGES * STAGE_B;        // 2 * 40960 = 81920
    cudaFuncSetAttribute(mma_gemm_kernel,
                         cudaFuncAttributeMaxDynamicSharedMemorySize, GEMM_SMEM);
    const int ATTN_SMEM = (64 * KST + 64 * VST + 4 * 16 * PST) * 4;  // 57344
    cudaFuncSetAttribute(attn_kernel,
                         cudaFuncAttributeMaxDynamicSharedMemorySize, ATTN_SMEM);

    // 0) conversions
    conv_x_kernel<<<(BT * C_ / 4) / 256, 256>>>((const float4*)x);
    {
        dim3 blk(32, 8);
        conv_wt_kernel<<<dim3(N3C / 32, C_ / 32), blk>>>(W_qkv, 0, C_, N3C);
        conv_wt_kernel<<<dim3(C_ / 32, C_ / 32), blk>>>(W_out, 1, C_, C_);
    }
    // 1) QKV projection (bf16x3 mma.sync, 2-stage cp.async, 2 CTAs/SM)
    mma_gemm_kernel<<<dim3(N3C / 128, BT / 128), 256, GEMM_SMEM>>>(b_qkv, nullptr, 0);
    // 2) Flash attention (tf32 mma.sync)
    attn_kernel<<<dim3(T_ / 64, H_, B_), 128, ATTN_SMEM>>>();
    // 3) Output projection (bf16x3 mma.sync, 2-stage cp.async, 2 CTAs/SM)
    mma_gemm_kernel<<<dim3(C_ / 128, BT / 128), 256, GEMM_SMEM>>>(b_out, out, 1);
}

// round 6
// speedup vs baseline: 4.9023x; 1.0587x over previous
#include <cuda_runtime.h>
#include <cuda_bf16.h>
#include <stdint.h>
#include <math.h>

// Problem constants
#define B_  2
#define T_  2048
#define C_  1024
#define H_  16
#define D_  64
#define BT  (B_*T_)          // 4096
#define N3C (3*C_)           // 3072

// Scratch (device globals; no allocation allowed)
__device__ float g_q[B_*H_*T_*D_];     // [B,H,T,D] fp32
__device__ float g_k[B_*H_*T_*D_];     // pre-rounded to tf32 grid
__device__ float g_v[B_*H_*T_*D_];     // pre-rounded to tf32 grid
__device__ __align__(16) __nv_bfloat16 g_xh[BT*C_];    // x hi/lo
__device__ __align__(16) __nv_bfloat16 g_xl[BT*C_];
__device__ __align__(16) __nv_bfloat16 g_wqh[N3C*C_];  // W_qkv^T [3072][1024] hi/lo
__device__ __align__(16) __nv_bfloat16 g_wql[N3C*C_];
__device__ __align__(16) __nv_bfloat16 g_woh[C_*C_];   // W_out^T [1024][1024] hi/lo
__device__ __align__(16) __nv_bfloat16 g_wol[C_*C_];
__device__ __align__(16) __nv_bfloat16 g_ah[BT*C_];    // attn out hi/lo [B,T,C]
__device__ __align__(16) __nv_bfloat16 g_al[BT*C_];

// ---------------------------------------------------------------------------
// mma.sync / ldmatrix helpers (arch-portable; compiles for compute_103)
// ---------------------------------------------------------------------------
__device__ __forceinline__ void mma_bf16(float* c, const uint32_t* a, uint32_t b0, uint32_t b1) {
    asm volatile("mma.sync.aligned.m16n8k16.row.col.f32.bf16.bf16.f32 "
        "{%0,%1,%2,%3}, {%4,%5,%6,%7}, {%8,%9}, {%0,%1,%2,%3};"
        : "+f"(c[0]), "+f"(c[1]), "+f"(c[2]), "+f"(c[3])
        : "r"(a[0]), "r"(a[1]), "r"(a[2]), "r"(a[3]), "r"(b0), "r"(b1));
}
__device__ __forceinline__ void mma_tf32(float* c, const uint32_t* a, uint32_t b0, uint32_t b1) {
    asm volatile("mma.sync.aligned.m16n8k8.row.col.f32.tf32.tf32.f32 "
        "{%0,%1,%2,%3}, {%4,%5,%6,%7}, {%8,%9}, {%0,%1,%2,%3};"
        : "+f"(c[0]), "+f"(c[1]), "+f"(c[2]), "+f"(c[3])
        : "r"(a[0]), "r"(a[1]), "r"(a[2]), "r"(a[3]), "r"(b0), "r"(b1));
}
__device__ __forceinline__ uint32_t f2tf32(float f) {
    uint32_t r; asm("cvt.rna.tf32.f32 %0, %1;" : "=r"(r) : "f"(f)); return r;
}
__device__ __forceinline__ uint32_t smem_u32(const void* p) {
    uint32_t a;
    asm("{ .reg .u64 t; cvta.to.shared.u64 t, %1; cvt.u32.u64 %0, t; }" : "=r"(a) : "l"(p));
    return a;
}
__device__ __forceinline__ void ldsm_x4(uint32_t* r, uint32_t addr) {
    asm volatile("ldmatrix.sync.aligned.m8n8.x4.shared.b16 {%0,%1,%2,%3}, [%4];"
        : "=r"(r[0]), "=r"(r[1]), "=r"(r[2]), "=r"(r[3]) : "r"(addr));
}
__device__ __forceinline__ void cp16(uint32_t dst, const void* src) {
    asm volatile("cp.async.cg.shared.global [%0], [%1], 16;" :: "r"(dst), "l"(src));
}
#define CP_COMMIT() asm volatile("cp.async.commit_group;" ::: "memory")
#define CP_WAIT(n)  asm volatile("cp.async.wait_group %0;" :: "n"(n) : "memory")

// ---------------------------------------------------------------------------
// Kernel 0a: convert x fp32 -> hi/lo bf16
// ---------------------------------------------------------------------------
__global__ __launch_bounds__(256)
void conv_x_kernel(const float4* __restrict__ X)
{
    int i = blockIdx.x * 256 + threadIdx.x;
    float4 v = X[i];
    __nv_bfloat16 hx = __float2bfloat16(v.x);
    __nv_bfloat16 hy = __float2bfloat16(v.y);
    __nv_bfloat16 hz = __float2bfloat16(v.z);
    __nv_bfloat16 hw = __float2bfloat16(v.w);
    __nv_bfloat16 lx = __float2bfloat16(v.x - __bfloat162float(hx));
    __nv_bfloat16 ly = __float2bfloat16(v.y - __bfloat162float(hy));
    __nv_bfloat16 lz = __float2bfloat16(v.z - __bfloat162float(hz));
    __nv_bfloat16 lw = __float2bfloat16(v.w - __bfloat162float(hw));
    __nv_bfloat162* ph = (__nv_bfloat162*)g_xh + (size_t)i * 2;
    __nv_bfloat162* pl = (__nv_bfloat162*)g_xl + (size_t)i * 2;
    ph[0] = __halves2bfloat162(hx, hy);
    ph[1] = __halves2bfloat162(hz, hw);
    pl[0] = __halves2bfloat162(lx, ly);
    pl[1] = __halves2bfloat162(lz, lw);
}

// ---------------------------------------------------------------------------
// Kernel 0b: transpose + convert W [K,N] fp32 -> WT [N,K] hi/lo bf16
// ---------------------------------------------------------------------------
__global__ __launch_bounds__(256)
void conv_wt_kernel(const float* __restrict__ W, int which, int K, int N)
{
    __shared__ float tile[32][33];
    int n0 = blockIdx.x * 32;
    int k0 = blockIdx.y * 32;
    int tx = threadIdx.x;
    int ty = threadIdx.y;

    #pragma unroll
    for (int i = 0; i < 32; i += 8)
        tile[ty + i][tx] = W[(size_t)(k0 + ty + i) * N + n0 + tx];
    __syncthreads();

    __nv_bfloat16* Th = which ? g_woh : g_wqh;
    __nv_bfloat16* Tl = which ? g_wol : g_wql;
    #pragma unroll
    for (int i = 0; i < 32; i += 8) {
        float v = tile[tx][ty + i];
        __nv_bfloat16 h = __float2bfloat16(v);
        __nv_bfloat16 l = __float2bfloat16(v - __bfloat162float(h));
        size_t idx = (size_t)(n0 + ty + i) * K + k0 + tx;
        Th[idx] = h;
        Tl[idx] = l;
    }
}

// ---------------------------------------------------------------------------
// Kernel 1/3: bf16x3 GEMM via mma.sync + ldmatrix + 2-stage cp.async.
// Block tile 128x128, kc=32, 8 warps = 2(M) x 4(N), warp tile 64x32.
// ---------------------------------------------------------------------------
#define AST 40           // smem row stride (bf16): conflict-free LDSM phases
#define TILE_B  (128*AST*2)          // 10240 bytes per tile
#define STAGE_B (4*TILE_B)           // AH, AL, BH, BL
#define STAGES  2
#define KT      (C_/32)              // 32 k-tiles

__global__ __launch_bounds__(256, 2)
void mma_gemm_kernel(const float* __restrict__ bias, float* __restrict__ outp, int mode)
{
    extern __shared__ char smem[];
    const uint32_t sb = smem_u32(smem);

    const int tid  = threadIdx.x;
    const int m0   = blockIdx.y * 128;
    const int n0   = blockIdx.x * 128;
    const int warp = tid >> 5, lane = tid & 31;
    const int mw = warp & 1, nw = warp >> 1;
    const int g = lane >> 2, tig = lane & 3;

    const __nv_bfloat16* Ah = mode ? g_ah : g_xh;
    const __nv_bfloat16* Al = mode ? g_al : g_xl;
    const __nv_bfloat16* Bh = mode ? g_woh : g_wqh;
    const __nv_bfloat16* Bl = mode ? g_wol : g_wql;

    // gmem load mapping: thread -> (row = tid>>1, 2 x 16B of k)
    const int lrow = tid >> 1;
    const int lofs = (tid & 1) * 16;
    const __nv_bfloat16* pAh = Ah + (size_t)(m0 + lrow) * C_ + lofs;
    const __nv_bfloat16* pAl = Al + (size_t)(m0 + lrow) * C_ + lofs;
    const __nv_bfloat16* pBh = Bh + (size_t)(n0 + lrow) * C_ + lofs;
    const __nv_bfloat16* pBl = Bl + (size_t)(n0 + lrow) * C_ + lofs;
    const uint32_t soff = (uint32_t)(lrow * AST + lofs) * 2;

    // ldmatrix per-lane offsets (bytes)
    // A x4: lanes 0-7 m0-7/k0-7, 8-15 m8-15/k0-7, 16-23 m0-7/k8-15, 24-31 m8-15/k8-15
    const uint32_t aoff = (uint32_t)((lane & 15) * AST + (lane >> 4) * 8) * 2;
    // B x4: lanes 0-7 Bh n0-7/k0-7, 8-15 Bh k8-15, 16-23 Bl k0-7, 24-31 Bl k8-15
    const uint32_t boff = (uint32_t)((lane & 7) * AST + ((lane >> 3) & 1) * 8) * 2
                        + (uint32_t)(lane >> 4) * TILE_B;

    float acc[16][4];
    #pragma unroll
    for (int i = 0; i < 16; i++)
        #pragma unroll
        for (int j = 0; j < 4; j++) acc[i][j] = 0.f;

    #define ISSUE(ktile, stg) do {                                             \
        uint32_t s0 = sb + (uint32_t)(stg) * STAGE_B + soff;                   \
        const int ko = (ktile) * 32;                                           \
        cp16(s0,                 pAh + ko); cp16(s0 + 16,              pAh + ko + 8); \
        cp16(s0 + TILE_B,        pAl + ko); cp16(s0 + TILE_B + 16,     pAl + ko + 8); \
        cp16(s0 + 2*TILE_B,      pBh + ko); cp16(s0 + 2*TILE_B + 16,   pBh + ko + 8); \
        cp16(s0 + 3*TILE_B,      pBl + ko); cp16(s0 + 3*TILE_B + 16,   pBl + ko + 8); \
    } while (0)

    ISSUE(0, 0); CP_COMMIT();

    for (int kt = 0; kt < KT; kt++) {
        if (kt + 1 < KT) ISSUE(kt + 1, (kt + 1) & 1);
        CP_COMMIT();
        CP_WAIT(1);
        __syncthreads();

        const uint32_t stgb = sb + (uint32_t)(kt & 1) * STAGE_B;

        #pragma unroll
        for (int ks = 0; ks < 2; ks++) {
            // A fragments: hi + lo, 2 LDSM.x4 per mf
            uint32_t ah[4][4], al[4][4];
            #pragma unroll
            for (int mf = 0; mf < 4; mf++) {
                uint32_t ab = stgb + (uint32_t)(((mw * 64 + mf * 16) * AST + ks * 16) * 2) + aoff;
                ldsm_x4(ah[mf], ab);
                ldsm_x4(al[mf], ab + TILE_B);
            }
            #pragma unroll
            for (int nf = 0; nf < 4; nf++) {
                // one LDSM.x4 loads bh0,bh1,bl0,bl1
                uint32_t bfrag[4];
                uint32_t bb = stgb + 2 * TILE_B
                            + (uint32_t)(((nw * 32 + nf * 8) * AST + ks * 16) * 2) + boff;
                ldsm_x4(bfrag, bb);
                #pragma unroll
                for (int mf = 0; mf < 4; mf++) {
                    mma_bf16(acc[mf * 4 + nf], ah[mf], bfrag[0], bfrag[1]);
                    mma_bf16(acc[mf * 4 + nf], ah[mf], bfrag[2], bfrag[3]);
                    mma_bf16(acc[mf * 4 + nf], al[mf], bfrag[0], bfrag[1]);
                }
            }
        }
        __syncthreads();
    }
    #undef ISSUE

    // Epilogue
    #pragma unroll
    for (int nf = 0; nf < 4; nf++) {
        const int c = n0 + nw * 32 + nf * 8 + 2 * tig;
        float2 bv = *(const float2*)&bias[c];
        #pragma unroll
        for (int mf = 0; mf < 4; mf++) {
            const float* a = acc[mf * 4 + nf];
            const int r0 = m0 + mw * 64 + mf * 16 + g;
            if (mode == 0) {
                int h  = c / 192;
                int rr = c - h * 192;
                int seg = rr >> 6;
                int d0  = rr & 63;
                float* base = (seg == 0) ? g_q : (seg == 1) ? g_k : g_v;
                int b = r0 >> 11;
                int t = r0 & (T_ - 1);
                size_t idx0 = ((size_t)(b * H_ + h) * T_ + t) * D_ + d0;
                float2 v0 = {a[0] + bv.x, a[1] + bv.y};
                float2 v1 = {a[2] + bv.x, a[3] + bv.y};
                if (seg != 0) {   // K/V consumed as tf32: pre-round here (same rna rounding)
                    v0.x = __uint_as_float(f2tf32(v0.x));
                    v0.y = __uint_as_float(f2tf32(v0.y));
                    v1.x = __uint_as_float(f2tf32(v1.x));
                    v1.y = __uint_as_float(f2tf32(v1.y));
                }
                *(float2*)&base[idx0]           = v0;
                *(float2*)&base[idx0 + 8 * D_]  = v1;
            } else {
                float2 v0 = {a[0] + bv.x, a[1] + bv.y};
                float2 v1 = {a[2] + bv.x, a[3] + bv.y};
                *(float2*)&outp[(size_t)r0 * C_ + c]       = v0;
                *(float2*)&outp[(size_t)(r0 + 8) * C_ + c] = v1;
            }
        }
    }
}

// ---------------------------------------------------------------------------
// Kernel 2: flash attention with tf32 mma.sync. K/V pre-rounded -> pure copy.
// ---------------------------------------------------------------------------
#define KST 84
#define VST 72
#define PST 68

__global__ __launch_bounds__(128, 3)
void attn_kernel()
{
    extern __shared__ float smf[];
    float* Ks = smf;                       // [64][KST]
    float* Vs = smf + 64 * KST;            // [64][VST]
    const int tid  = threadIdx.x;
    const int warp = tid >> 5, lane = tid & 31;
    const int g = lane >> 2, tig = lane & 3;
    float* Ps = smf + 64 * KST + 64 * VST + warp * 16 * PST;   // per-warp [16][PST]

    const int q0 = blockIdx.x * 64;
    const int h  = blockIdx.y;
    const int b  = blockIdx.z;
    const size_t bh = (size_t)(b * H_ + h);
    const float* Qb = g_q + bh * (T_ * D_);
    const float* Kb = g_k + bh * (T_ * D_);
    const float* Vb = g_v + bh * (T_ * D_);

    uint32_t qf[8][4];
    {
        const float* qr0 = Qb + (size_t)(q0 + warp * 16 + g) * D_;
        const float* qr1 = qr0 + 8 * D_;
        #pragma unroll
        for (int kf = 0; kf < 8; kf++) {
            qf[kf][0] = f2tf32(qr0[kf * 8 + tig]     * 0.125f);
            qf[kf][1] = f2tf32(qr1[kf * 8 + tig]     * 0.125f);
            qf[kf][2] = f2tf32(qr0[kf * 8 + tig + 4] * 0.125f);
            qf[kf][3] = f2tf32(qr1[kf * 8 + tig + 4] * 0.125f);
        }
    }

    float oacc[8][4];
    #pragma unroll
    for (int i = 0; i < 8; i++)
        #pragma unroll
        for (int j = 0; j < 4; j++) oacc[i][j] = 0.f;
    float m0 = -1e30f, m1 = -1e30f, l0 = 0.f, l1 = 0.f;

    for (int kb = 0; kb < T_; kb += 64) {
        __syncthreads();
        {
            const float4* Kg = (const float4*)(Kb + (size_t)kb * D_);
            const float4* Vg = (const float4*)(Vb + (size_t)kb * D_);
            #pragma unroll
            for (int j = 0; j < 8; j++) {
                int flat = j * 128 + tid;
                int row = flat >> 4;
                int c4  = (flat & 15) * 4;
                *(float4*)&Ks[row * KST + c4] = Kg[flat];   // pre-rounded tf32 values
                *(float4*)&Vs[row * VST + c4] = Vg[flat];
            }
        }
        __syncthreads();

        float sacc[8][4];
        #pragma unroll
        for (int i = 0; i < 8; i++)
            #pragma unroll
            for (int j = 0; j < 4; j++) sacc[i][j] = 0.f;
        #pragma unroll
        for (int nf = 0; nf < 8; nf++) {
            const uint32_t* Kw = (const uint32_t*)(Ks + (nf * 8 + g) * KST);
            #pragma unroll
            for (int kf = 0; kf < 8; kf++) {
                uint32_t b0 = Kw[kf * 8 + tig];
                uint32_t b1 = Kw[kf * 8 + tig + 4];
                mma_tf32(sacc[nf], qf[kf], b0, b1);
            }
        }

        float r0 = -1e30f, r1 = -1e30f;
        #pragma unroll
        for (int nf = 0; nf < 8; nf++) {
            r0 = fmaxf(r0, fmaxf(sacc[nf][0], sacc[nf][1]));
            r1 = fmaxf(r1, fmaxf(sacc[nf][2], sacc[nf][3]));
        }
        r0 = fmaxf(r0, __shfl_xor_sync(0xffffffffu, r0, 1));
        r0 = fmaxf(r0, __shfl_xor_sync(0xffffffffu, r0, 2));
        r1 = fmaxf(r1, __shfl_xor_sync(0xffffffffu, r1, 1));
        r1 = fmaxf(r1, __shfl_xor_sync(0xffffffffu, r1, 2));
        float m0n = fmaxf(m0, r0);
        float m1n = fmaxf(m1, r1);
        float f0 = __expf(m0 - m0n);
        float f1 = __expf(m1 - m1n);
        l0 *= f0; l1 *= f1;
        #pragma unroll
        for (int nf = 0; nf < 8; nf++) {
            oacc[nf][0] *= f0; oacc[nf][1] *= f0;
            oacc[nf][2] *= f1; oacc[nf][3] *= f1;
        }
        m0 = m0n; m1 = m1n;

        float ps0 = 0.f, ps1 = 0.f;
        uint32_t* Pr0 = (uint32_t*)(Ps + g * PST);
        uint32_t* Pr1 = (uint32_t*)(Ps + (g + 8) * PST);
        #pragma unroll
        for (int nf = 0; nf < 8; nf++) {
            float p0 = __expf(sacc[nf][0] - m0n);
            float p1 = __expf(sacc[nf][1] - m0n);
            float p2 = __expf(sacc[nf][2] - m1n);
            float p3 = __expf(sacc[nf][3] - m1n);
            ps0 += p0 + p1;
            ps1 += p2 + p3;
            uint2 w0 = {f2tf32(p0), f2tf32(p1)};
            uint2 w1 = {f2tf32(p2), f2tf32(p3)};
            *(uint2*)&Pr0[nf * 8 + 2 * tig] = w0;
            *(uint2*)&Pr1[nf * 8 + 2 * tig] = w1;
        }
        ps0 += __shfl_xor_sync(0xffffffffu, ps0, 1);
        ps0 += __shfl_xor_sync(0xffffffffu, ps0, 2);
        ps1 += __shfl_xor_sync(0xffffffffu, ps1, 1);
        ps1 += __shfl_xor_sync(0xffffffffu, ps1, 2);
        l0 += ps0; l1 += ps1;
        __syncwarp();

        #pragma unroll
        for (int kf = 0; kf < 8; kf++) {
            uint32_t a[4];
            a[0] = *(uint32_t*)&Ps[g * PST + kf * 8 + tig];
            a[1] = *(uint32_t*)&Ps[(g + 8) * PST + kf * 8 + tig];
            a[2] = *(uint32_t*)&Ps[g * PST + kf * 8 + tig + 4];
            a[3] = *(uint32_t*)&Ps[(g + 8) * PST + kf * 8 + tig + 4];
            const uint32_t* V0 = (const uint32_t*)(Vs + (kf * 8 + tig) * VST);
            const uint32_t* V1 = (const uint32_t*)(Vs + (kf * 8 + tig + 4) * VST);
            #pragma unroll
            for (int nf = 0; nf < 8; nf++) {
                mma_tf32(oacc[nf], a, V0[nf * 8 + g], V1[nf * 8 + g]);
            }
        }
        __syncwarp();
    }

    float inv0 = 1.f / l0;
    float inv1 = 1.f / l1;
    const int t0 = q0 + warp * 16 + g;
    __nv_bfloat16* oh0 = g_ah + ((size_t)b * T_ + t0) * C_ + h * D_;
    __nv_bfloat16* ol0 = g_al + ((size_t)b * T_ + t0) * C_ + h * D_;
    __nv_bfloat16* oh1 = oh0 + 8 * (size_t)C_;
    __nv_bfloat16* ol1 = ol0 + 8 * (size_t)C_;
    #pragma unroll
    for (int nf = 0; nf < 8; nf++) {
        const int c = nf * 8 + 2 * tig;
        float v0 = oacc[nf][0] * inv0, v1 = oacc[nf][1] * inv0;
        float v2 = oacc[nf][2] * inv1, v3 = oacc[nf][3] * inv1;
        __nv_bfloat16 h0 = __float2bfloat16(v0), h1 = __float2bfloat16(v1);
        __nv_bfloat16 h2 = __float2bfloat16(v2), h3 = __float2bfloat16(v3);
        *(__nv_bfloat162*)&oh0[c] = __halves2bfloat162(h0, h1);
        *(__nv_bfloat162*)&oh1[c] = __halves2bfloat162(h2, h3);
        *(__nv_bfloat162*)&ol0[c] = __halves2bfloat162(
            __float2bfloat16(v0 - __bfloat162float(h0)),
            __float2bfloat16(v1 - __bfloat162float(h1)));
        *(__nv_bfloat162*)&ol1[c] = __halves2bfloat162(
            __float2bfloat16(v2 - __bfloat162float(h2)),
            __float2bfloat16(v3 - __bfloat162float(h3)));
    }
}

// ---------------------------------------------------------------------------
extern "C" void kernel_launch(void* const* d_in, const int* in_sizes, int n_in,
                              void* d_out, int out_size)
{
    const float* x     = (const float*)d_in[0];   // [2,2048,1024]
    const float* W_qkv = (const float*)d_in[1];   // [1024,3072]
    const float* b_qkv = (const float*)d_in[2];   // [3072]
    const float* W_out = (const float*)d_in[3];   // [1024,1024]
    const float* b_out = (const float*)d_in[4];   // [1024]
    float* out = (float*)d_out;                   // [2,2048,1024]

    (void)in_sizes; (void)n_in; (void)out_size;

    const int GEMM_SMEM = STAGES * STAGE_B;        // 81920
    cudaFuncSetAttribute(mma_gemm_kernel,
                         cudaFuncAttributeMaxDynamicSharedMemorySize, GEMM_SMEM);
    const int ATTN_SMEM = (64 * KST + 64 * VST + 4 * 16 * PST) * 4;  // 57344
    cudaFuncSetAttribute(attn_kernel,
                         cudaFuncAttributeMaxDynamicSharedMemorySize, ATTN_SMEM);

    // 0) conversions
    conv_x_kernel<<<(BT * C_ / 4) / 256, 256>>>((const float4*)x);
    {
        dim3 blk(32, 8);
        conv_wt_kernel<<<dim3(N3C / 32, C_ / 32), blk>>>(W_qkv, 0, C_, N3C);
        conv_wt_kernel<<<dim3(C_ / 32, C_ / 32), blk>>>(W_out, 1, C_, C_);
    }
    // 1) QKV projection (bf16x3 mma.sync + ldmatrix)
    mma_gemm_kernel<<<dim3(N3C / 128, BT / 128), 256, GEMM_SMEM>>>(b_qkv, nullptr, 0);
    // 2) Flash attention (tf32 mma.sync)
    attn_kernel<<<dim3(T_ / 64, H_, B_), 128, ATTN_SMEM>>>();
    // 3) Output projection (bf16x3 mma.sync + ldmatrix)
    mma_gemm_kernel<<<dim3(C_ / 128, BT / 128), 256, GEMM_SMEM>>>(b_out, out, 1);
}

// round 7
// speedup vs baseline: 5.0453x; 1.0292x over previous
#include <cuda_runtime.h>
#include <cuda_bf16.h>
#include <stdint.h>
#include <math.h>

// Problem constants
#define B_  2
#define T_  2048
#define C_  1024
#define H_  16
#define D_  64
#define BT  (B_*T_)          // 4096
#define N3C (3*C_)           // 3072

// Scratch (device globals; no allocation allowed)
__device__ float g_q[B_*H_*T_*D_];     // [B,H,T,D] fp32
__device__ float g_k[B_*H_*T_*D_];     // pre-rounded to tf32 grid
__device__ float g_v[B_*H_*T_*D_];     // pre-rounded to tf32 grid
__device__ __align__(16) __nv_bfloat16 g_xh[BT*C_];    // x hi/lo
__device__ __align__(16) __nv_bfloat16 g_xl[BT*C_];
__device__ __align__(16) __nv_bfloat16 g_wqh[N3C*C_];  // W_qkv^T [3072][1024] hi/lo
__device__ __align__(16) __nv_bfloat16 g_wql[N3C*C_];
__device__ __align__(16) __nv_bfloat16 g_woh[C_*C_];   // W_out^T [1024][1024] hi/lo
__device__ __align__(16) __nv_bfloat16 g_wol[C_*C_];
__device__ __align__(16) __nv_bfloat16 g_ah[BT*C_];    // attn out hi/lo [B,T,C]
__device__ __align__(16) __nv_bfloat16 g_al[BT*C_];

// ---------------------------------------------------------------------------
// mma.sync / ldmatrix helpers (arch-portable; compiles for compute_103)
// ---------------------------------------------------------------------------
__device__ __forceinline__ void mma_bf16(float* c, const uint32_t* a, uint32_t b0, uint32_t b1) {
    asm volatile("mma.sync.aligned.m16n8k16.row.col.f32.bf16.bf16.f32 "
        "{%0,%1,%2,%3}, {%4,%5,%6,%7}, {%8,%9}, {%0,%1,%2,%3};"
        : "+f"(c[0]), "+f"(c[1]), "+f"(c[2]), "+f"(c[3])
        : "r"(a[0]), "r"(a[1]), "r"(a[2]), "r"(a[3]), "r"(b0), "r"(b1));
}
__device__ __forceinline__ void mma_tf32(float* c, const uint32_t* a, uint32_t b0, uint32_t b1) {
    asm volatile("mma.sync.aligned.m16n8k8.row.col.f32.tf32.tf32.f32 "
        "{%0,%1,%2,%3}, {%4,%5,%6,%7}, {%8,%9}, {%0,%1,%2,%3};"
        : "+f"(c[0]), "+f"(c[1]), "+f"(c[2]), "+f"(c[3])
        : "r"(a[0]), "r"(a[1]), "r"(a[2]), "r"(a[3]), "r"(b0), "r"(b1));
}
__device__ __forceinline__ uint32_t f2tf32(float f) {
    uint32_t r; asm("cvt.rna.tf32.f32 %0, %1;" : "=r"(r) : "f"(f)); return r;
}
__device__ __forceinline__ uint32_t smem_u32(const void* p) {
    uint32_t a;
    asm("{ .reg .u64 t; cvta.to.shared.u64 t, %1; cvt.u32.u64 %0, t; }" : "=r"(a) : "l"(p));
    return a;
}
__device__ __forceinline__ void ldsm_x4(uint32_t* r, uint32_t addr) {
    asm volatile("ldmatrix.sync.aligned.m8n8.x4.shared.b16 {%0,%1,%2,%3}, [%4];"
        : "=r"(r[0]), "=r"(r[1]), "=r"(r[2]), "=r"(r[3]) : "r"(addr));
}
__device__ __forceinline__ void cp16(uint32_t dst, const void* src) {
    asm volatile("cp.async.cg.shared.global [%0], [%1], 16;" :: "r"(dst), "l"(src));
}
#define CP_COMMIT() asm volatile("cp.async.commit_group;" ::: "memory")
#define CP_WAIT(n)  asm volatile("cp.async.wait_group %0;" :: "n"(n) : "memory")

// ---------------------------------------------------------------------------
// Kernel 0a: convert x fp32 -> hi/lo bf16
// ---------------------------------------------------------------------------
__global__ __launch_bounds__(256)
void conv_x_kernel(const float4* __restrict__ X)
{
    int i = blockIdx.x * 256 + threadIdx.x;
    float4 v = X[i];
    __nv_bfloat16 hx = __float2bfloat16(v.x);
    __nv_bfloat16 hy = __float2bfloat16(v.y);
    __nv_bfloat16 hz = __float2bfloat16(v.z);
    __nv_bfloat16 hw = __float2bfloat16(v.w);
    __nv_bfloat16 lx = __float2bfloat16(v.x - __bfloat162float(hx));
    __nv_bfloat16 ly = __float2bfloat16(v.y - __bfloat162float(hy));
    __nv_bfloat16 lz = __float2bfloat16(v.z - __bfloat162float(hz));
    __nv_bfloat16 lw = __float2bfloat16(v.w - __bfloat162float(hw));
    __nv_bfloat162* ph = (__nv_bfloat162*)g_xh + (size_t)i * 2;
    __nv_bfloat162* pl = (__nv_bfloat162*)g_xl + (size_t)i * 2;
    ph[0] = __halves2bfloat162(hx, hy);
    ph[1] = __halves2bfloat162(hz, hw);
    pl[0] = __halves2bfloat162(lx, ly);
    pl[1] = __halves2bfloat162(lz, lw);
}

// ---------------------------------------------------------------------------
// Kernel 0b: transpose + convert W [K,N] fp32 -> WT [N,K] hi/lo bf16
// ---------------------------------------------------------------------------
__global__ __launch_bounds__(256)
void conv_wt_kernel(const float* __restrict__ W, int which, int K, int N)
{
    __shared__ float tile[32][33];
    int n0 = blockIdx.x * 32;
    int k0 = blockIdx.y * 32;
    int tx = threadIdx.x;
    int ty = threadIdx.y;

    #pragma unroll
    for (int i = 0; i < 32; i += 8)
        tile[ty + i][tx] = W[(size_t)(k0 + ty + i) * N + n0 + tx];
    __syncthreads();

    __nv_bfloat16* Th = which ? g_woh : g_wqh;
    __nv_bfloat16* Tl = which ? g_wol : g_wql;
    #pragma unroll
    for (int i = 0; i < 32; i += 8) {
        float v = tile[tx][ty + i];
        __nv_bfloat16 h = __float2bfloat16(v);
        __nv_bfloat16 l = __float2bfloat16(v - __bfloat162float(h));
        size_t idx = (size_t)(n0 + ty + i) * K + k0 + tx;
        Th[idx] = h;
        Tl[idx] = l;
    }
}

// ---------------------------------------------------------------------------
// Kernel 1/3: bf16x3 GEMM, fragment-software-pipelined.
// Block tile 128x128, kc=16, 4-stage cp.async, 8 warps = 2(M) x 4(N).
// Per iteration: issue tile kt+3, MMA tile kt (frags in regs), wait+sync,
// LDSM frags for tile kt+1. MMAs never wait on same-iteration LDSM.
// ---------------------------------------------------------------------------
#define AST16 24                      // row stride (bf16) for kc=16 tiles
#define TILE2 (128*AST16*2)           // 6144 bytes per matrix tile
#define STG_B (4*TILE2)               // 24576: AH, AL, BH, BL
#define NSTG  4
#define KT16  (C_/16)                 // 64 k-tiles

__global__ __launch_bounds__(256, 2)
void mma_gemm_kernel(const float* __restrict__ bias, float* __restrict__ outp, int mode)
{
    extern __shared__ char smem[];
    const uint32_t sb = smem_u32(smem);

    const int tid  = threadIdx.x;
    const int m0   = blockIdx.y * 128;
    const int n0   = blockIdx.x * 128;
    const int warp = tid >> 5, lane = tid & 31;
    const int mw = warp & 1, nw = warp >> 1;
    const int g = lane >> 2, tig = lane & 3;

    const __nv_bfloat16* Ah = mode ? g_ah : g_xh;
    const __nv_bfloat16* Al = mode ? g_al : g_xl;
    const __nv_bfloat16* Bh = mode ? g_woh : g_wqh;
    const __nv_bfloat16* Bl = mode ? g_wol : g_wql;

    // gmem load mapping: thread -> (row = tid>>1, one 16B chunk of k)
    const int lrow = tid >> 1;
    const int lofs = (tid & 1) * 8;   // k-elem offset
    const __nv_bfloat16* pAh = Ah + (size_t)(m0 + lrow) * C_ + lofs;
    const __nv_bfloat16* pAl = Al + (size_t)(m0 + lrow) * C_ + lofs;
    const __nv_bfloat16* pBh = Bh + (size_t)(n0 + lrow) * C_ + lofs;
    const __nv_bfloat16* pBl = Bl + (size_t)(n0 + lrow) * C_ + lofs;
    const uint32_t soff = (uint32_t)(lrow * AST16 * 2 + (tid & 1) * 16);

    // ldmatrix per-lane byte offsets (row stride 48B; phases conflict-free)
    const uint32_t aoff = (uint32_t)((lane & 15) * (AST16 * 2) + (lane >> 4) * 16);
    const uint32_t boff = (uint32_t)((lane & 7) * (AST16 * 2) + ((lane >> 3) & 1) * 16)
                        + (uint32_t)(lane >> 4) * TILE2;

    float acc[16][4];
    #pragma unroll
    for (int i = 0; i < 16; i++)
        #pragma unroll
        for (int j = 0; j < 4; j++) acc[i][j] = 0.f;

    uint32_t ah[4][4], al[4][4], bf[4][4];

    #define ISSUE(ktile, stg) do {                                   \
        uint32_t s0 = sb + (uint32_t)(stg) * STG_B + soff;           \
        const int ko = (ktile) * 16;                                 \
        cp16(s0,             pAh + ko);                              \
        cp16(s0 +   TILE2,   pAl + ko);                              \
        cp16(s0 + 2*TILE2,   pBh + ko);                              \
        cp16(s0 + 3*TILE2,   pBl + ko);                              \
    } while (0)

    #define LOADFRAGS(kt_) do {                                      \
        uint32_t stgb = sb + (uint32_t)((kt_) & 3) * STG_B;          \
        _Pragma("unroll")                                            \
        for (int mf = 0; mf < 4; mf++) {                             \
            uint32_t ab = stgb + (uint32_t)((mw*64 + mf*16) * (AST16*2)) + aoff; \
            ldsm_x4(ah[mf], ab);                                     \
            ldsm_x4(al[mf], ab + TILE2);                             \
        }                                                            \
        _Pragma("unroll")                                            \
        for (int nf = 0; nf < 4; nf++) {                             \
            uint32_t bb = stgb + 2*TILE2                             \
                        + (uint32_t)((nw*32 + nf*8) * (AST16*2)) + boff; \
            ldsm_x4(bf[nf], bb);                                     \
        }                                                            \
    } while (0)

    // prologue: 3 tiles in flight, frags for tile 0 in regs
    ISSUE(0, 0); CP_COMMIT();
    ISSUE(1, 1); CP_COMMIT();
    ISSUE(2, 2); CP_COMMIT();
    CP_WAIT(2);
    __syncthreads();
    LOADFRAGS(0);

    for (int kt = 0; kt < KT16; kt++) {
        if (kt + 3 < KT16) ISSUE(kt + 3, (kt + 3) & 3);
        CP_COMMIT();                      // exactly one group per iteration

        // MMAs for tile kt from registers
        #pragma unroll
        for (int nf = 0; nf < 4; nf++) {
            #pragma unroll
            for (int mf = 0; mf < 4; mf++) {
                mma_bf16(acc[mf * 4 + nf], ah[mf], bf[nf][0], bf[nf][1]);
                mma_bf16(acc[mf * 4 + nf], ah[mf], bf[nf][2], bf[nf][3]);
                mma_bf16(acc[mf * 4 + nf], al[mf], bf[nf][0], bf[nf][1]);
            }
        }

        CP_WAIT(2);                       // tiles <= kt+1 complete
        __syncthreads();                  // cross-thread visibility
        if (kt + 1 < KT16) LOADFRAGS(kt + 1);
    }
    #undef ISSUE
    #undef LOADFRAGS

    // Epilogue
    #pragma unroll
    for (int nf = 0; nf < 4; nf++) {
        const int c = n0 + nw * 32 + nf * 8 + 2 * tig;
        float2 bv = *(const float2*)&bias[c];
        #pragma unroll
        for (int mf = 0; mf < 4; mf++) {
            const float* a = acc[mf * 4 + nf];
            const int r0 = m0 + mw * 64 + mf * 16 + g;
            if (mode == 0) {
                int h  = c / 192;
                int rr = c - h * 192;
                int seg = rr >> 6;
                int d0  = rr & 63;
                float* base = (seg == 0) ? g_q : (seg == 1) ? g_k : g_v;
                int b = r0 >> 11;
                int t = r0 & (T_ - 1);
                size_t idx0 = ((size_t)(b * H_ + h) * T_ + t) * D_ + d0;
                float2 v0 = {a[0] + bv.x, a[1] + bv.y};
                float2 v1 = {a[2] + bv.x, a[3] + bv.y};
                if (seg != 0) {   // K/V consumed as tf32: pre-round (same rna rounding)
                    v0.x = __uint_as_float(f2tf32(v0.x));
                    v0.y = __uint_as_float(f2tf32(v0.y));
                    v1.x = __uint_as_float(f2tf32(v1.x));
                    v1.y = __uint_as_float(f2tf32(v1.y));
                }
                *(float2*)&base[idx0]           = v0;
                *(float2*)&base[idx0 + 8 * D_]  = v1;
            } else {
                float2 v0 = {a[0] + bv.x, a[1] + bv.y};
                float2 v1 = {a[2] + bv.x, a[3] + bv.y};
                *(float2*)&outp[(size_t)r0 * C_ + c]       = v0;
                *(float2*)&outp[(size_t)(r0 + 8) * C_ + c] = v1;
            }
        }
    }
}

// ---------------------------------------------------------------------------
// Kernel 2: flash attention with tf32 mma.sync. K/V pre-rounded -> pure copy.
// ---------------------------------------------------------------------------
#define KST 84
#define VST 72
#define PST 68

__global__ __launch_bounds__(128, 3)
void attn_kernel()
{
    extern __shared__ float smf[];
    float* Ks = smf;                       // [64][KST]
    float* Vs = smf + 64 * KST;            // [64][VST]
    const int tid  = threadIdx.x;
    const int warp = tid >> 5, lane = tid & 31;
    const int g = lane >> 2, tig = lane & 3;
    float* Ps = smf + 64 * KST + 64 * VST + warp * 16 * PST;   // per-warp [16][PST]

    const int q0 = blockIdx.x * 64;
    const int h  = blockIdx.y;
    const int b  = blockIdx.z;
    const size_t bh = (size_t)(b * H_ + h);
    const float* Qb = g_q + bh * (T_ * D_);
    const float* Kb = g_k + bh * (T_ * D_);
    const float* Vb = g_v + bh * (T_ * D_);

    uint32_t qf[8][4];
    {
        const float* qr0 = Qb + (size_t)(q0 + warp * 16 + g) * D_;
        const float* qr1 = qr0 + 8 * D_;
        #pragma unroll
        for (int kf = 0; kf < 8; kf++) {
            qf[kf][0] = f2tf32(qr0[kf * 8 + tig]     * 0.125f);
            qf[kf][1] = f2tf32(qr1[kf * 8 + tig]     * 0.125f);
            qf[kf][2] = f2tf32(qr0[kf * 8 + tig + 4] * 0.125f);
            qf[kf][3] = f2tf32(qr1[kf * 8 + tig + 4] * 0.125f);
        }
    }

    float oacc[8][4];
    #pragma unroll
    for (int i = 0; i < 8; i++)
        #pragma unroll
        for (int j = 0; j < 4; j++) oacc[i][j] = 0.f;
    float m0 = -1e30f, m1 = -1e30f, l0 = 0.f, l1 = 0.f;

    for (int kb = 0; kb < T_; kb += 64) {
        __syncthreads();
        {
            const float4* Kg = (const float4*)(Kb + (size_t)kb * D_);
            const float4* Vg = (const float4*)(Vb + (size_t)kb * D_);
            #pragma unroll
            for (int j = 0; j < 8; j++) {
                int flat = j * 128 + tid;
                int row = flat >> 4;
                int c4  = (flat & 15) * 4;
                *(float4*)&Ks[row * KST + c4] = Kg[flat];   // pre-rounded tf32 values
                *(float4*)&Vs[row * VST + c4] = Vg[flat];
            }
        }
        __syncthreads();

        float sacc[8][4];
        #pragma unroll
        for (int i = 0; i < 8; i++)
            #pragma unroll
            for (int j = 0; j < 4; j++) sacc[i][j] = 0.f;
        #pragma unroll
        for (int nf = 0; nf < 8; nf++) {
            const uint32_t* Kw = (const uint32_t*)(Ks + (nf * 8 + g) * KST);
            #pragma unroll
            for (int kf = 0; kf < 8; kf++) {
                uint32_t b0 = Kw[kf * 8 + tig];
                uint32_t b1 = Kw[kf * 8 + tig + 4];
                mma_tf32(sacc[nf], qf[kf], b0, b1);
            }
        }

        float r0 = -1e30f, r1 = -1e30f;
        #pragma unroll
        for (int nf = 0; nf < 8; nf++) {
            r0 = fmaxf(r0, fmaxf(sacc[nf][0], sacc[nf][1]));
            r1 = fmaxf(r1, fmaxf(sacc[nf][2], sacc[nf][3]));
        }
        r0 = fmaxf(r0, __shfl_xor_sync(0xffffffffu, r0, 1));
        r0 = fmaxf(r0, __shfl_xor_sync(0xffffffffu, r0, 2));
        r1 = fmaxf(r1, __shfl_xor_sync(0xffffffffu, r1, 1));
        r1 = fmaxf(r1, __shfl_xor_sync(0xffffffffu, r1, 2));
        float m0n = fmaxf(m0, r0);
        float m1n = fmaxf(m1, r1);
        float f0 = __expf(m0 - m0n);
        float f1 = __expf(m1 - m1n);
        l0 *= f0; l1 *= f1;
        #pragma unroll
        for (int nf = 0; nf < 8; nf++) {
            oacc[nf][0] *= f0; oacc[nf][1] *= f0;
            oacc[nf][2] *= f1; oacc[nf][3] *= f1;
        }
        m0 = m0n; m1 = m1n;

        float ps0 = 0.f, ps1 = 0.f;
        uint32_t* Pr0 = (uint32_t*)(Ps + g * PST);
        uint32_t* Pr1 = (uint32_t*)(Ps + (g + 8) * PST);
        #pragma unroll
        for (int nf = 0; nf < 8; nf++) {
            float p0 = __expf(sacc[nf][0] - m0n);
            float p1 = __expf(sacc[nf][1] - m0n);
            float p2 = __expf(sacc[nf][2] - m1n);
            float p3 = __expf(sacc[nf][3] - m1n);
            ps0 += p0 + p1;
            ps1 += p2 + p3;
            uint2 w0 = {f2tf32(p0), f2tf32(p1)};
            uint2 w1 = {f2tf32(p2), f2tf32(p3)};
            *(uint2*)&Pr0[nf * 8 + 2 * tig] = w0;
            *(uint2*)&Pr1[nf * 8 + 2 * tig] = w1;
        }
        ps0 += __shfl_xor_sync(0xffffffffu, ps0, 1);
        ps0 += __shfl_xor_sync(0xffffffffu, ps0, 2);
        ps1 += __shfl_xor_sync(0xffffffffu, ps1, 1);
        ps1 += __shfl_xor_sync(0xffffffffu, ps1, 2);
        l0 += ps0; l1 += ps1;
        __syncwarp();

        #pragma unroll
        for (int kf = 0; kf < 8; kf++) {
            uint32_t a[4];
            a[0] = *(uint32_t*)&Ps[g * PST + kf * 8 + tig];
            a[1] = *(uint32_t*)&Ps[(g + 8) * PST + kf * 8 + tig];
            a[2] = *(uint32_t*)&Ps[g * PST + kf * 8 + tig + 4];
            a[3] = *(uint32_t*)&Ps[(g + 8) * PST + kf * 8 + tig + 4];
            const uint32_t* V0 = (const uint32_t*)(Vs + (kf * 8 + tig) * VST);
            const uint32_t* V1 = (const uint32_t*)(Vs + (kf * 8 + tig + 4) * VST);
            #pragma unroll
            for (int nf = 0; nf < 8; nf++) {
                mma_tf32(oacc[nf], a, V0[nf * 8 + g], V1[nf * 8 + g]);
            }
        }
        __syncwarp();
    }

    float inv0 = 1.f / l0;
    float inv1 = 1.f / l1;
    const int t0 = q0 + warp * 16 + g;
    __nv_bfloat16* oh0 = g_ah + ((size_t)b * T_ + t0) * C_ + h * D_;
    __nv_bfloat16* ol0 = g_al + ((size_t)b * T_ + t0) * C_ + h * D_;
    __nv_bfloat16* oh1 = oh0 + 8 * (size_t)C_;
    __nv_bfloat16* ol1 = ol0 + 8 * (size_t)C_;
    #pragma unroll
    for (int nf = 0; nf < 8; nf++) {
        const int c = nf * 8 + 2 * tig;
        float v0 = oacc[nf][0] * inv0, v1 = oacc[nf][1] * inv0;
        float v2 = oacc[nf][2] * inv1, v3 = oacc[nf][3] * inv1;
        __nv_bfloat16 h0 = __float2bfloat16(v0), h1 = __float2bfloat16(v1);
        __nv_bfloat16 h2 = __float2bfloat16(v2), h3 = __float2bfloat16(v3);
        *(__nv_bfloat162*)&oh0[c] = __halves2bfloat162(h0, h1);
        *(__nv_bfloat162*)&oh1[c] = __halves2bfloat162(h2, h3);
        *(__nv_bfloat162*)&ol0[c] = __halves2bfloat162(
            __float2bfloat16(v0 - __bfloat162float(h0)),
            __float2bfloat16(v1 - __bfloat162float(h1)));
        *(__nv_bfloat162*)&ol1[c] = __halves2bfloat162(
            __float2bfloat16(v2 - __bfloat162float(h2)),
            __float2bfloat16(v3 - __bfloat162float(h3)));
    }
}

// ---------------------------------------------------------------------------
extern "C" void kernel_launch(void* const* d_in, const int* in_sizes, int n_in,
                              void* d_out, int out_size)
{
    const float* x     = (const float*)d_in[0];   // [2,2048,1024]
    const float* W_qkv = (const float*)d_in[1];   // [1024,3072]
    const float* b_qkv = (const float*)d_in[2];   // [3072]
    const float* W_out = (const float*)d_in[3];   // [1024,1024]
    const float* b_out = (const float*)d_in[4];   // [1024]
    float* out = (float*)d_out;                   // [2,2048,1024]

    (void)in_sizes; (void)n_in; (void)out_size;

    const int GEMM_SMEM = NSTG * STG_B;            // 4 * 24576 = 98304
    cudaFuncSetAttribute(mma_gemm_kernel,
                         cudaFuncAttributeMaxDynamicSharedMemorySize, GEMM_SMEM);
    const int ATTN_SMEM = (64 * KST + 64 * VST + 4 * 16 * PST) * 4;  // 57344
    cudaFuncSetAttribute(attn_kernel,
                         cudaFuncAttributeMaxDynamicSharedMemorySize, ATTN_SMEM);

    // 0) conversions
    conv_x_kernel<<<(BT * C_ / 4) / 256, 256>>>((const float4*)x);
    {
        dim3 blk(32, 8);
        conv_wt_kernel<<<dim3(N3C / 32, C_ / 32), blk>>>(W_qkv, 0, C_, N3C);
        conv_wt_kernel<<<dim3(C_ / 32, C_ / 32), blk>>>(W_out, 1, C_, C_);
    }
    // 1) QKV projection (bf16x3 mma.sync, frag-pipelined)
    mma_gemm_kernel<<<dim3(N3C / 128, BT / 128), 256, GEMM_SMEM>>>(b_qkv, nullptr, 0);
    // 2) Flash attention (tf32 mma.sync)
    attn_kernel<<<dim3(T_ / 64, H_, B_), 128, ATTN_SMEM>>>();
    // 3) Output projection (bf16x3 mma.sync, frag-pipelined)
    mma_gemm_kernel<<<dim3(C_ / 128, BT / 128), 256, GEMM_SMEM>>>(b_out, out, 1);
}

// round 8
// speedup vs baseline: 6.1801x; 1.2249x over previous
#include <cuda_runtime.h>
#include <cuda_bf16.h>
#include <stdint.h>
#include <math.h>

// Problem constants
#define B_  2
#define T_  2048
#define C_  1024
#define H_  16
#define D_  64
#define BT  (B_*T_)          // 4096
#define N3C (3*C_)           // 3072

// Scratch (device globals; no allocation allowed)
__device__ float g_q[B_*H_*T_*D_];     // [B,H,T,D] fp32
__device__ float g_k[B_*H_*T_*D_];     // pre-rounded to tf32 grid
__device__ __align__(16) __nv_bfloat16 g_vb[B_*H_*T_*D_];  // V as bf16
__device__ __align__(16) __nv_bfloat16 g_xh[BT*C_];    // x hi/lo
__device__ __align__(16) __nv_bfloat16 g_xl[BT*C_];
__device__ __align__(16) __nv_bfloat16 g_wqh[N3C*C_];  // W_qkv^T hi/lo
__device__ __align__(16) __nv_bfloat16 g_wql[N3C*C_];
__device__ __align__(16) __nv_bfloat16 g_woh[C_*C_];   // W_out^T hi/lo
__device__ __align__(16) __nv_bfloat16 g_wol[C_*C_];
__device__ __align__(16) __nv_bfloat16 g_ah[BT*C_];    // attn out hi/lo [B,T,C]
__device__ __align__(16) __nv_bfloat16 g_al[BT*C_];

// ---------------------------------------------------------------------------
// mma.sync / ldmatrix helpers (arch-portable; compiles for compute_103)
// ---------------------------------------------------------------------------
__device__ __forceinline__ void mma_bf16(float* c, const uint32_t* a, uint32_t b0, uint32_t b1) {
    asm volatile("mma.sync.aligned.m16n8k16.row.col.f32.bf16.bf16.f32 "
        "{%0,%1,%2,%3}, {%4,%5,%6,%7}, {%8,%9}, {%0,%1,%2,%3};"
        : "+f"(c[0]), "+f"(c[1]), "+f"(c[2]), "+f"(c[3])
        : "r"(a[0]), "r"(a[1]), "r"(a[2]), "r"(a[3]), "r"(b0), "r"(b1));
}
__device__ __forceinline__ void mma_tf32(float* c, const uint32_t* a, uint32_t b0, uint32_t b1) {
    asm volatile("mma.sync.aligned.m16n8k8.row.col.f32.tf32.tf32.f32 "
        "{%0,%1,%2,%3}, {%4,%5,%6,%7}, {%8,%9}, {%0,%1,%2,%3};"
        : "+f"(c[0]), "+f"(c[1]), "+f"(c[2]), "+f"(c[3])
        : "r"(a[0]), "r"(a[1]), "r"(a[2]), "r"(a[3]), "r"(b0), "r"(b1));
}
__device__ __forceinline__ uint32_t f2tf32(float f) {
    uint32_t r; asm("cvt.rna.tf32.f32 %0, %1;" : "=r"(r) : "f"(f)); return r;
}
__device__ __forceinline__ uint32_t smem_u32(const void* p) {
    uint32_t a;
    asm("{ .reg .u64 t; cvta.to.shared.u64 t, %1; cvt.u32.u64 %0, t; }" : "=r"(a) : "l"(p));
    return a;
}
__device__ __forceinline__ void ldsm_x4(uint32_t* r, uint32_t addr) {
    asm volatile("ldmatrix.sync.aligned.m8n8.x4.shared.b16 {%0,%1,%2,%3}, [%4];"
        : "=r"(r[0]), "=r"(r[1]), "=r"(r[2]), "=r"(r[3]) : "r"(addr));
}
__device__ __forceinline__ void ldsm_x4_t(uint32_t* r, uint32_t addr) {
    asm volatile("ldmatrix.sync.aligned.m8n8.x4.trans.shared.b16 {%0,%1,%2,%3}, [%4];"
        : "=r"(r[0]), "=r"(r[1]), "=r"(r[2]), "=r"(r[3]) : "r"(addr));
}
__device__ __forceinline__ void cp16(uint32_t dst, const void* src) {
    asm volatile("cp.async.cg.shared.global [%0], [%1], 16;" :: "r"(dst), "l"(src));
}
#define CP_COMMIT() asm volatile("cp.async.commit_group;" ::: "memory")
#define CP_WAIT(n)  asm volatile("cp.async.wait_group %0;" :: "n"(n) : "memory")
__device__ __forceinline__ uint32_t pack_bf16x2(float lo, float hi) {
    __nv_bfloat162 t = __floats2bfloat162_rn(lo, hi);
    return *(uint32_t*)&t;
}

// ---------------------------------------------------------------------------
// Kernel 0a: convert x fp32 -> hi/lo bf16
// ---------------------------------------------------------------------------
__global__ __launch_bounds__(256)
void conv_x_kernel(const float4* __restrict__ X)
{
    int i = blockIdx.x * 256 + threadIdx.x;
    float4 v = X[i];
    __nv_bfloat16 hx = __float2bfloat16(v.x);
    __nv_bfloat16 hy = __float2bfloat16(v.y);
    __nv_bfloat16 hz = __float2bfloat16(v.z);
    __nv_bfloat16 hw = __float2bfloat16(v.w);
    __nv_bfloat16 lx = __float2bfloat16(v.x - __bfloat162float(hx));
    __nv_bfloat16 ly = __float2bfloat16(v.y - __bfloat162float(hy));
    __nv_bfloat16 lz = __float2bfloat16(v.z - __bfloat162float(hz));
    __nv_bfloat16 lw = __float2bfloat16(v.w - __bfloat162float(hw));
    __nv_bfloat162* ph = (__nv_bfloat162*)g_xh + (size_t)i * 2;
    __nv_bfloat162* pl = (__nv_bfloat162*)g_xl + (size_t)i * 2;
    ph[0] = __halves2bfloat162(hx, hy);
    ph[1] = __halves2bfloat162(hz, hw);
    pl[0] = __halves2bfloat162(lx, ly);
    pl[1] = __halves2bfloat162(lz, lw);
}

// ---------------------------------------------------------------------------
// Kernel 0b: transpose + convert W [K,N] fp32 -> WT [N,K] hi/lo bf16
// ---------------------------------------------------------------------------
__global__ __launch_bounds__(256)
void conv_wt_kernel(const float* __restrict__ W, int which, int K, int N)
{
    __shared__ float tile[32][33];
    int n0 = blockIdx.x * 32;
    int k0 = blockIdx.y * 32;
    int tx = threadIdx.x;
    int ty = threadIdx.y;

    #pragma unroll
    for (int i = 0; i < 32; i += 8)
        tile[ty + i][tx] = W[(size_t)(k0 + ty + i) * N + n0 + tx];
    __syncthreads();

    __nv_bfloat16* Th = which ? g_woh : g_wqh;
    __nv_bfloat16* Tl = which ? g_wol : g_wql;
    #pragma unroll
    for (int i = 0; i < 32; i += 8) {
        float v = tile[tx][ty + i];
        __nv_bfloat16 h = __float2bfloat16(v);
        __nv_bfloat16 l = __float2bfloat16(v - __bfloat162float(h));
        size_t idx = (size_t)(n0 + ty + i) * K + k0 + tx;
        Th[idx] = h;
        Tl[idx] = l;
    }
}

// ---------------------------------------------------------------------------
// Kernel 1/3: bf16x3 GEMM, fragment-software-pipelined (unchanged from R7).
// ---------------------------------------------------------------------------
#define AST16 24
#define TILE2 (128*AST16*2)
#define STG_B (4*TILE2)
#define NSTG  4
#define KT16  (C_/16)

__global__ __launch_bounds__(256, 2)
void mma_gemm_kernel(const float* __restrict__ bias, float* __restrict__ outp, int mode)
{
    extern __shared__ char smem[];
    const uint32_t sb = smem_u32(smem);

    const int tid  = threadIdx.x;
    const int m0   = blockIdx.y * 128;
    const int n0   = blockIdx.x * 128;
    const int warp = tid >> 5, lane = tid & 31;
    const int mw = warp & 1, nw = warp >> 1;
    const int g = lane >> 2, tig = lane & 3;

    const __nv_bfloat16* Ah = mode ? g_ah : g_xh;
    const __nv_bfloat16* Al = mode ? g_al : g_xl;
    const __nv_bfloat16* Bh = mode ? g_woh : g_wqh;
    const __nv_bfloat16* Bl = mode ? g_wol : g_wql;

    const int lrow = tid >> 1;
    const int lofs = (tid & 1) * 8;
    const __nv_bfloat16* pAh = Ah + (size_t)(m0 + lrow) * C_ + lofs;
    const __nv_bfloat16* pAl = Al + (size_t)(m0 + lrow) * C_ + lofs;
    const __nv_bfloat16* pBh = Bh + (size_t)(n0 + lrow) * C_ + lofs;
    const __nv_bfloat16* pBl = Bl + (size_t)(n0 + lrow) * C_ + lofs;
    const uint32_t soff = (uint32_t)(lrow * AST16 * 2 + (tid & 1) * 16);

    const uint32_t aoff = (uint32_t)((lane & 15) * (AST16 * 2) + (lane >> 4) * 16);
    const uint32_t boff = (uint32_t)((lane & 7) * (AST16 * 2) + ((lane >> 3) & 1) * 16)
                        + (uint32_t)(lane >> 4) * TILE2;

    float acc[16][4];
    #pragma unroll
    for (int i = 0; i < 16; i++)
        #pragma unroll
        for (int j = 0; j < 4; j++) acc[i][j] = 0.f;

    uint32_t ah[4][4], al[4][4], bf[4][4];

    #define ISSUE(ktile, stg) do {                                   \
        uint32_t s0 = sb + (uint32_t)(stg) * STG_B + soff;           \
        const int ko = (ktile) * 16;                                 \
        cp16(s0,             pAh + ko);                              \
        cp16(s0 +   TILE2,   pAl + ko);                              \
        cp16(s0 + 2*TILE2,   pBh + ko);                              \
        cp16(s0 + 3*TILE2,   pBl + ko);                              \
    } while (0)

    #define LOADFRAGS(kt_) do {                                      \
        uint32_t stgb = sb + (uint32_t)((kt_) & 3) * STG_B;          \
        _Pragma("unroll")                                            \
        for (int mf = 0; mf < 4; mf++) {                             \
            uint32_t ab = stgb + (uint32_t)((mw*64 + mf*16) * (AST16*2)) + aoff; \
            ldsm_x4(ah[mf], ab);                                     \
            ldsm_x4(al[mf], ab + TILE2);                             \
        }                                                            \
        _Pragma("unroll")                                            \
        for (int nf = 0; nf < 4; nf++) {                             \
            uint32_t bb = stgb + 2*TILE2                             \
                        + (uint32_t)((nw*32 + nf*8) * (AST16*2)) + boff; \
            ldsm_x4(bf[nf], bb);                                     \
        }                                                            \
    } while (0)

    ISSUE(0, 0); CP_COMMIT();
    ISSUE(1, 1); CP_COMMIT();
    ISSUE(2, 2); CP_COMMIT();
    CP_WAIT(2);
    __syncthreads();
    LOADFRAGS(0);

    for (int kt = 0; kt < KT16; kt++) {
        if (kt + 3 < KT16) ISSUE(kt + 3, (kt + 3) & 3);
        CP_COMMIT();

        #pragma unroll
        for (int nf = 0; nf < 4; nf++) {
            #pragma unroll
            for (int mf = 0; mf < 4; mf++) {
                mma_bf16(acc[mf * 4 + nf], ah[mf], bf[nf][0], bf[nf][1]);
                mma_bf16(acc[mf * 4 + nf], ah[mf], bf[nf][2], bf[nf][3]);
                mma_bf16(acc[mf * 4 + nf], al[mf], bf[nf][0], bf[nf][1]);
            }
        }

        CP_WAIT(2);
        __syncthreads();
        if (kt + 1 < KT16) LOADFRAGS(kt + 1);
    }
    #undef ISSUE
    #undef LOADFRAGS

    // Epilogue
    #pragma unroll
    for (int nf = 0; nf < 4; nf++) {
        const int c = n0 + nw * 32 + nf * 8 + 2 * tig;
        float2 bv = *(const float2*)&bias[c];
        #pragma unroll
        for (int mf = 0; mf < 4; mf++) {
            const float* a = acc[mf * 4 + nf];
            const int r0 = m0 + mw * 64 + mf * 16 + g;
            if (mode == 0) {
                int h  = c / 192;
                int rr = c - h * 192;
                int seg = rr >> 6;
                int d0  = rr & 63;
                int b = r0 >> 11;
                int t = r0 & (T_ - 1);
                size_t idx0 = ((size_t)(b * H_ + h) * T_ + t) * D_ + d0;
                float2 v0 = {a[0] + bv.x, a[1] + bv.y};
                float2 v1 = {a[2] + bv.x, a[3] + bv.y};
                if (seg == 2) {          // V: store bf16
                    *(__nv_bfloat162*)&g_vb[idx0]          = __floats2bfloat162_rn(v0.x, v0.y);
                    *(__nv_bfloat162*)&g_vb[idx0 + 8 * D_] = __floats2bfloat162_rn(v1.x, v1.y);
                } else {
                    float* base = (seg == 0) ? g_q : g_k;
                    if (seg == 1) {      // K consumed as tf32: pre-round
                        v0.x = __uint_as_float(f2tf32(v0.x));
                        v0.y = __uint_as_float(f2tf32(v0.y));
                        v1.x = __uint_as_float(f2tf32(v1.x));
                        v1.y = __uint_as_float(f2tf32(v1.y));
                    }
                    *(float2*)&base[idx0]          = v0;
                    *(float2*)&base[idx0 + 8 * D_] = v1;
                }
            } else {
                float2 v0 = {a[0] + bv.x, a[1] + bv.y};
                float2 v1 = {a[2] + bv.x, a[3] + bv.y};
                *(float2*)&outp[(size_t)r0 * C_ + c]       = v0;
                *(float2*)&outp[(size_t)(r0 + 8) * C_ + c] = v1;
            }
        }
    }
}

// ---------------------------------------------------------------------------
// Kernel 2: flash attention. S = QK^T in tf32 mma; PV in bf16 m16n8k16 with
// P packed directly from S accumulators (layout match), V via ldmatrix.trans.
// K/V tiles double-buffered with cp.async.
// ---------------------------------------------------------------------------
#define KST 84                         // K row stride (floats), 336B (16B-aligned)
#define VSTB 72                        // V row stride (bf16), 144B (16B-aligned)
#define KTILE_AB (64*KST*4)            // 21504
#define VTILE_AB (64*VSTB*2)           // 9216
#define ASTG_AB  (KTILE_AB + VTILE_AB) // 30720

__global__ __launch_bounds__(128, 3)
void attn_kernel()
{
    extern __shared__ char smc[];
    const uint32_t sb = smem_u32(smc);
    const int tid  = threadIdx.x;
    const int warp = tid >> 5, lane = tid & 31;
    const int g = lane >> 2, tig = lane & 3;

    const int q0 = blockIdx.x * 64;
    const int h  = blockIdx.y;
    const int b  = blockIdx.z;
    const size_t bh = (size_t)(b * H_ + h);
    const float* Qb = g_q + bh * (T_ * D_);
    const float* Kb = g_k + bh * (T_ * D_);
    const __nv_bfloat16* Vb = g_vb + bh * (T_ * D_);

    // Q fragments, resident (tf32), rows q0+warp*16+{g,g+8}
    uint32_t qf[8][4];
    {
        const float* qr0 = Qb + (size_t)(q0 + warp * 16 + g) * D_;
        const float* qr1 = qr0 + 8 * D_;
        #pragma unroll
        for (int kf = 0; kf < 8; kf++) {
            qf[kf][0] = f2tf32(qr0[kf * 8 + tig]     * 0.125f);
            qf[kf][1] = f2tf32(qr1[kf * 8 + tig]     * 0.125f);
            qf[kf][2] = f2tf32(qr0[kf * 8 + tig + 4] * 0.125f);
            qf[kf][3] = f2tf32(qr1[kf * 8 + tig + 4] * 0.125f);
        }
    }

    float oacc[8][4];
    #pragma unroll
    for (int i = 0; i < 8; i++)
        #pragma unroll
        for (int j = 0; j < 4; j++) oacc[i][j] = 0.f;
    float m0 = -1e30f, m1 = -1e30f, l0 = 0.f, l1 = 0.f;

    // cp.async issue of K (16KB) + V (8KB) tile kb_ into stage stg_
    #define KV_ISSUE(kb_, stg_) do {                                          \
        uint32_t base = sb + (uint32_t)(stg_) * ASTG_AB;                      \
        const char* kg = (const char*)(Kb + (size_t)(kb_) * 64 * D_);         \
        const char* vg = (const char*)(Vb + (size_t)(kb_) * 64 * D_);         \
        _Pragma("unroll")                                                     \
        for (int u = 0; u < 8; u++) {                                         \
            int un = u * 128 + tid;                                           \
            cp16(base + (un >> 4) * (KST * 4) + (un & 15) * 16, kg + un * 16);\
        }                                                                     \
        _Pragma("unroll")                                                     \
        for (int u = 0; u < 4; u++) {                                         \
            int un = u * 128 + tid;                                           \
            cp16(base + KTILE_AB + (un >> 3) * (VSTB * 2) + (un & 7) * 16,    \
                 vg + un * 16);                                               \
        }                                                                     \
    } while (0)

    KV_ISSUE(0, 0); CP_COMMIT();

    // V ldmatrix.trans per-lane offset: rows = key (lane&15), dim block +8 for lanes>=16
    const uint32_t vlo = (uint32_t)((lane & 15) * (VSTB * 2) + (lane >> 4) * 16);

    for (int kb = 0; kb < T_ / 64; kb++) {
        if (kb + 1 < T_ / 64) KV_ISSUE(kb + 1, (kb + 1) & 1);
        CP_COMMIT();
        CP_WAIT(1);
        __syncthreads();

        const uint32_t stgb = sb + (uint32_t)(kb & 1) * ASTG_AB;
        const float* Ks = (const float*)(smc + (size_t)(kb & 1) * ASTG_AB);
        const uint32_t vbase = stgb + KTILE_AB;

        // S = Q K^T (tf32)
        float sacc[8][4];
        #pragma unroll
        for (int i = 0; i < 8; i++)
            #pragma unroll
            for (int j = 0; j < 4; j++) sacc[i][j] = 0.f;
        #pragma unroll
        for (int nf = 0; nf < 8; nf++) {
            const uint32_t* Kw = (const uint32_t*)(Ks + (nf * 8 + g) * KST);
            #pragma unroll
            for (int kf = 0; kf < 8; kf++) {
                uint32_t b0 = Kw[kf * 8 + tig];
                uint32_t b1 = Kw[kf * 8 + tig + 4];
                mma_tf32(sacc[nf], qf[kf], b0, b1);
            }
        }

        // online softmax (rows g / g+8; quad lanes share rows)
        float r0 = -1e30f, r1 = -1e30f;
        #pragma unroll
        for (int nf = 0; nf < 8; nf++) {
            r0 = fmaxf(r0, fmaxf(sacc[nf][0], sacc[nf][1]));
            r1 = fmaxf(r1, fmaxf(sacc[nf][2], sacc[nf][3]));
        }
        r0 = fmaxf(r0, __shfl_xor_sync(0xffffffffu, r0, 1));
        r0 = fmaxf(r0, __shfl_xor_sync(0xffffffffu, r0, 2));
        r1 = fmaxf(r1, __shfl_xor_sync(0xffffffffu, r1, 1));
        r1 = fmaxf(r1, __shfl_xor_sync(0xffffffffu, r1, 2));
        float m0n = fmaxf(m0, r0);
        float m1n = fmaxf(m1, r1);
        float f0 = __expf(m0 - m0n);
        float f1 = __expf(m1 - m1n);
        l0 *= f0; l1 *= f1;
        #pragma unroll
        for (int nf = 0; nf < 8; nf++) {
            oacc[nf][0] *= f0; oacc[nf][1] *= f0;
            oacc[nf][2] *= f1; oacc[nf][3] *= f1;
        }
        m0 = m0n; m1 = m1n;

        // p = exp(s - m); overwrite sacc with p (fp32), accumulate l
        float ps0 = 0.f, ps1 = 0.f;
        #pragma unroll
        for (int nf = 0; nf < 8; nf++) {
            float p0 = __expf(sacc[nf][0] - m0n);
            float p1 = __expf(sacc[nf][1] - m0n);
            float p2 = __expf(sacc[nf][2] - m1n);
            float p3 = __expf(sacc[nf][3] - m1n);
            ps0 += p0 + p1;
            ps1 += p2 + p3;
            sacc[nf][0] = p0; sacc[nf][1] = p1;
            sacc[nf][2] = p2; sacc[nf][3] = p3;
        }
        ps0 += __shfl_xor_sync(0xffffffffu, ps0, 1);
        ps0 += __shfl_xor_sync(0xffffffffu, ps0, 2);
        ps1 += __shfl_xor_sync(0xffffffffu, ps1, 1);
        ps1 += __shfl_xor_sync(0xffffffffu, ps1, 2);
        l0 += ps0; l1 += ps1;

        // O += P V  (bf16 m16n8k16; P A-frags packed from S accumulators)
        #pragma unroll
        for (int kf = 0; kf < 4; kf++) {
            uint32_t pa[4];
            pa[0] = pack_bf16x2(sacc[2*kf][0],     sacc[2*kf][1]);
            pa[1] = pack_bf16x2(sacc[2*kf][2],     sacc[2*kf][3]);
            pa[2] = pack_bf16x2(sacc[2*kf+1][0],   sacc[2*kf+1][1]);
            pa[3] = pack_bf16x2(sacc[2*kf+1][2],   sacc[2*kf+1][3]);
            #pragma unroll
            for (int nb = 0; nb < 4; nb++) {
                uint32_t bv[4];
                uint32_t va = vbase + (uint32_t)(kf * 16 * (VSTB * 2) + nb * 32) + vlo;
                ldsm_x4_t(bv, va);
                mma_bf16(oacc[2*nb],     pa, bv[0], bv[1]);
                mma_bf16(oacc[2*nb + 1], pa, bv[2], bv[3]);
            }
        }
        __syncthreads();
    }
    #undef KV_ISSUE

    // epilogue: normalize, split to bf16 hi/lo, write [B,T,C]
    float inv0 = 1.f / l0;
    float inv1 = 1.f / l1;
    const int t0 = q0 + warp * 16 + g;
    __nv_bfloat16* oh0 = g_ah + ((size_t)b * T_ + t0) * C_ + h * D_;
    __nv_bfloat16* ol0 = g_al + ((size_t)b * T_ + t0) * C_ + h * D_;
    __nv_bfloat16* oh1 = oh0 + 8 * (size_t)C_;
    __nv_bfloat16* ol1 = ol0 + 8 * (size_t)C_;
    #pragma unroll
    for (int nf = 0; nf < 8; nf++) {
        const int c = nf * 8 + 2 * tig;
        float v0 = oacc[nf][0] * inv0, v1 = oacc[nf][1] * inv0;
        float v2 = oacc[nf][2] * inv1, v3 = oacc[nf][3] * inv1;
        __nv_bfloat16 h0 = __float2bfloat16(v0), h1 = __float2bfloat16(v1);
        __nv_bfloat16 h2 = __float2bfloat16(v2), h3 = __float2bfloat16(v3);
        *(__nv_bfloat162*)&oh0[c] = __halves2bfloat162(h0, h1);
        *(__nv_bfloat162*)&oh1[c] = __halves2bfloat162(h2, h3);
        *(__nv_bfloat162*)&ol0[c] = __halves2bfloat162(
            __float2bfloat16(v0 - __bfloat162float(h0)),
            __float2bfloat16(v1 - __bfloat162float(h1)));
        *(__nv_bfloat162*)&ol1[c] = __halves2bfloat162(
            __float2bfloat16(v2 - __bfloat162float(h2)),
            __float2bfloat16(v3 - __bfloat162float(h3)));
    }
}

// ---------------------------------------------------------------------------
extern "C" void kernel_launch(void* const* d_in, const int* in_sizes, int n_in,
                              void* d_out, int out_size)
{
    const float* x     = (const float*)d_in[0];   // [2,2048,1024]
    const float* W_qkv = (const float*)d_in[1];   // [1024,3072]
    const float* b_qkv = (const float*)d_in[2];   // [3072]
    const float* W_out = (const float*)d_in[3];   // [1024,1024]
    const float* b_out = (const float*)d_in[4];   // [1024]
    float* out = (float*)d_out;                   // [2,2048,1024]

    (void)in_sizes; (void)n_in; (void)out_size;

    const int GEMM_SMEM = NSTG * STG_B;            // 98304
    cudaFuncSetAttribute(mma_gemm_kernel,
                         cudaFuncAttributeMaxDynamicSharedMemorySize, GEMM_SMEM);
    const int ATTN_SMEM = 2 * ASTG_AB;             // 61440
    cudaFuncSetAttribute(attn_kernel,
                         cudaFuncAttributeMaxDynamicSharedMemorySize, ATTN_SMEM);

    // 0) conversions
    conv_x_kernel<<<(BT * C_ / 4) / 256, 256>>>((const float4*)x);
    {
        dim3 blk(32, 8);
        conv_wt_kernel<<<dim3(N3C / 32, C_ / 32), blk>>>(W_qkv, 0, C_, N3C);
        conv_wt_kernel<<<dim3(C_ / 32, C_ / 32), blk>>>(W_out, 1, C_, C_);
    }
    // 1) QKV projection (bf16x3 mma.sync, frag-pipelined)
    mma_gemm_kernel<<<dim3(N3C / 128, BT / 128), 256, GEMM_SMEM>>>(b_qkv, nullptr, 0);
    // 2) Flash attention (tf32 QK + bf16 PV, cp.async double-buffered)
    attn_kernel<<<dim3(T_ / 64, H_, B_), 128, ATTN_SMEM>>>();
    // 3) Output projection (bf16x3 mma.sync, frag-pipelined)
    mma_gemm_kernel<<<dim3(C_ / 128, BT / 128), 256, GEMM_SMEM>>>(b_out, out, 1);
}

// round 9
// speedup vs baseline: 6.3034x; 1.0200x over previous
#include <cuda_runtime.h>
#include <cuda_bf16.h>
#include <cuda_fp16.h>
#include <stdint.h>
#include <math.h>

// Problem constants
#define B_  2
#define T_  2048
#define C_  1024
#define H_  16
#define D_  64
#define BT  (B_*T_)          // 4096
#define N3C (3*C_)           // 3072

// Scratch (device globals; no allocation allowed)
__device__ float g_q[B_*H_*T_*D_];     // [B,H,T,D] fp32
__device__ float g_k[B_*H_*T_*D_];     // pre-rounded to tf32 grid
__device__ __align__(16) __half g_vb[B_*H_*T_*D_];     // V as fp16
__device__ __align__(16) __nv_bfloat16 g_xh[BT*C_];    // x hi/lo
__device__ __align__(16) __nv_bfloat16 g_xl[BT*C_];
__device__ __align__(16) __nv_bfloat16 g_wqh[N3C*C_];  // W_qkv^T hi/lo
__device__ __align__(16) __nv_bfloat16 g_wql[N3C*C_];
__device__ __align__(16) __nv_bfloat16 g_woh[C_*C_];   // W_out^T hi/lo
__device__ __align__(16) __nv_bfloat16 g_wol[C_*C_];
__device__ __align__(16) __nv_bfloat16 g_ah[BT*C_];    // attn out hi/lo [B,T,C]
__device__ __align__(16) __nv_bfloat16 g_al[BT*C_];

// ---------------------------------------------------------------------------
// mma.sync / ldmatrix helpers (arch-portable; compiles for compute_103)
// ---------------------------------------------------------------------------
__device__ __forceinline__ void mma_bf16(float* c, const uint32_t* a, uint32_t b0, uint32_t b1) {
    asm volatile("mma.sync.aligned.m16n8k16.row.col.f32.bf16.bf16.f32 "
        "{%0,%1,%2,%3}, {%4,%5,%6,%7}, {%8,%9}, {%0,%1,%2,%3};"
        : "+f"(c[0]), "+f"(c[1]), "+f"(c[2]), "+f"(c[3])
        : "r"(a[0]), "r"(a[1]), "r"(a[2]), "r"(a[3]), "r"(b0), "r"(b1));
}
__device__ __forceinline__ void mma_f16(float* c, const uint32_t* a, uint32_t b0, uint32_t b1) {
    asm volatile("mma.sync.aligned.m16n8k16.row.col.f32.f16.f16.f32 "
        "{%0,%1,%2,%3}, {%4,%5,%6,%7}, {%8,%9}, {%0,%1,%2,%3};"
        : "+f"(c[0]), "+f"(c[1]), "+f"(c[2]), "+f"(c[3])
        : "r"(a[0]), "r"(a[1]), "r"(a[2]), "r"(a[3]), "r"(b0), "r"(b1));
}
__device__ __forceinline__ void mma_tf32(float* c, const uint32_t* a, uint32_t b0, uint32_t b1) {
    asm volatile("mma.sync.aligned.m16n8k8.row.col.f32.tf32.tf32.f32 "
        "{%0,%1,%2,%3}, {%4,%5,%6,%7}, {%8,%9}, {%0,%1,%2,%3};"
        : "+f"(c[0]), "+f"(c[1]), "+f"(c[2]), "+f"(c[3])
        : "r"(a[0]), "r"(a[1]), "r"(a[2]), "r"(a[3]), "r"(b0), "r"(b1));
}
__device__ __forceinline__ uint32_t f2tf32(float f) {
    uint32_t r; asm("cvt.rna.tf32.f32 %0, %1;" : "=r"(r) : "f"(f)); return r;
}
__device__ __forceinline__ uint32_t smem_u32(const void* p) {
    uint32_t a;
    asm("{ .reg .u64 t; cvta.to.shared.u64 t, %1; cvt.u32.u64 %0, t; }" : "=r"(a) : "l"(p));
    return a;
}
__device__ __forceinline__ void ldsm_x4(uint32_t* r, uint32_t addr) {
    asm volatile("ldmatrix.sync.aligned.m8n8.x4.shared.b16 {%0,%1,%2,%3}, [%4];"
        : "=r"(r[0]), "=r"(r[1]), "=r"(r[2]), "=r"(r[3]) : "r"(addr));
}
__device__ __forceinline__ void ldsm_x4_t(uint32_t* r, uint32_t addr) {
    asm volatile("ldmatrix.sync.aligned.m8n8.x4.trans.shared.b16 {%0,%1,%2,%3}, [%4];"
        : "=r"(r[0]), "=r"(r[1]), "=r"(r[2]), "=r"(r[3]) : "r"(addr));
}
__device__ __forceinline__ void cp16(uint32_t dst, const void* src) {
    asm volatile("cp.async.cg.shared.global [%0], [%1], 16;" :: "r"(dst), "l"(src));
}
#define CP_COMMIT() asm volatile("cp.async.commit_group;" ::: "memory")
#define CP_WAIT(n)  asm volatile("cp.async.wait_group %0;" :: "n"(n) : "memory")
__device__ __forceinline__ uint32_t pack_f16x2(float lo, float hi) {
    __half2 t = __floats2half2_rn(lo, hi);
    return *(uint32_t*)&t;
}

// ---------------------------------------------------------------------------
// Kernel 0a: convert x fp32 -> hi/lo bf16
// ---------------------------------------------------------------------------
__global__ __launch_bounds__(256)
void conv_x_kernel(const float4* __restrict__ X)
{
    int i = blockIdx.x * 256 + threadIdx.x;
    float4 v = X[i];
    __nv_bfloat16 hx = __float2bfloat16(v.x);
    __nv_bfloat16 hy = __float2bfloat16(v.y);
    __nv_bfloat16 hz = __float2bfloat16(v.z);
    __nv_bfloat16 hw = __float2bfloat16(v.w);
    __nv_bfloat16 lx = __float2bfloat16(v.x - __bfloat162float(hx));
    __nv_bfloat16 ly = __float2bfloat16(v.y - __bfloat162float(hy));
    __nv_bfloat16 lz = __float2bfloat16(v.z - __bfloat162float(hz));
    __nv_bfloat16 lw = __float2bfloat16(v.w - __bfloat162float(hw));
    __nv_bfloat162* ph = (__nv_bfloat162*)g_xh + (size_t)i * 2;
    __nv_bfloat162* pl = (__nv_bfloat162*)g_xl + (size_t)i * 2;
    ph[0] = __halves2bfloat162(hx, hy);
    ph[1] = __halves2bfloat162(hz, hw);
    pl[0] = __halves2bfloat162(lx, ly);
    pl[1] = __halves2bfloat162(lz, lw);
}

// ---------------------------------------------------------------------------
// Kernel 0b: transpose + convert both weights fp32 -> WT hi/lo bf16 (merged)
// blocks x < 96: W_qkv (N=3072); else W_out (N=1024)
// ---------------------------------------------------------------------------
__global__ __launch_bounds__(256)
void conv_wt_kernel(const float* __restrict__ Wq, const float* __restrict__ Wo)
{
    __shared__ float tile[32][33];
    int which, n0;
    const float* W;
    int N;
    if (blockIdx.x < 96) { which = 0; W = Wq; N = N3C; n0 = blockIdx.x * 32; }
    else                 { which = 1; W = Wo; N = C_;  n0 = (blockIdx.x - 96) * 32; }
    int k0 = blockIdx.y * 32;
    int tx = threadIdx.x;
    int ty = threadIdx.y;

    #pragma unroll
    for (int i = 0; i < 32; i += 8)
        tile[ty + i][tx] = W[(size_t)(k0 + ty + i) * N + n0 + tx];
    __syncthreads();

    __nv_bfloat16* Th = which ? g_woh : g_wqh;
    __nv_bfloat16* Tl = which ? g_wol : g_wql;
    #pragma unroll
    for (int i = 0; i < 32; i += 8) {
        float v = tile[tx][ty + i];
        __nv_bfloat16 h = __float2bfloat16(v);
        __nv_bfloat16 l = __float2bfloat16(v - __bfloat162float(h));
        size_t idx = (size_t)(n0 + ty + i) * C_ + k0 + tx;
        Th[idx] = h;
        Tl[idx] = l;
    }
}

// ---------------------------------------------------------------------------
// Kernel 1/3: bf16x3 GEMM, fragment-software-pipelined (unchanged from R7).
// ---------------------------------------------------------------------------
#define AST16 24
#define TILE2 (128*AST16*2)
#define STG_B (4*TILE2)
#define NSTG  4
#define KT16  (C_/16)

__global__ __launch_bounds__(256, 2)
void mma_gemm_kernel(const float* __restrict__ bias, float* __restrict__ outp, int mode)
{
    extern __shared__ char smem[];
    const uint32_t sb = smem_u32(smem);

    const int tid  = threadIdx.x;
    const int m0   = blockIdx.y * 128;
    const int n0   = blockIdx.x * 128;
    const int warp = tid >> 5, lane = tid & 31;
    const int mw = warp & 1, nw = warp >> 1;
    const int g = lane >> 2, tig = lane & 3;

    const __nv_bfloat16* Ah = mode ? g_ah : g_xh;
    const __nv_bfloat16* Al = mode ? g_al : g_xl;
    const __nv_bfloat16* Bh = mode ? g_woh : g_wqh;
    const __nv_bfloat16* Bl = mode ? g_wol : g_wql;

    const int lrow = tid >> 1;
    const int lofs = (tid & 1) * 8;
    const __nv_bfloat16* pAh = Ah + (size_t)(m0 + lrow) * C_ + lofs;
    const __nv_bfloat16* pAl = Al + (size_t)(m0 + lrow) * C_ + lofs;
    const __nv_bfloat16* pBh = Bh + (size_t)(n0 + lrow) * C_ + lofs;
    const __nv_bfloat16* pBl = Bl + (size_t)(n0 + lrow) * C_ + lofs;
    const uint32_t soff = (uint32_t)(lrow * AST16 * 2 + (tid & 1) * 16);

    const uint32_t aoff = (uint32_t)((lane & 15) * (AST16 * 2) + (lane >> 4) * 16);
    const uint32_t boff = (uint32_t)((lane & 7) * (AST16 * 2) + ((lane >> 3) & 1) * 16)
                        + (uint32_t)(lane >> 4) * TILE2;

    float acc[16][4];
    #pragma unroll
    for (int i = 0; i < 16; i++)
        #pragma unroll
        for (int j = 0; j < 4; j++) acc[i][j] = 0.f;

    uint32_t ah[4][4], al[4][4], bf[4][4];

    #define ISSUE(ktile, stg) do {                                   \
        uint32_t s0 = sb + (uint32_t)(stg) * STG_B + soff;           \
        const int ko = (ktile) * 16;                                 \
        cp16(s0,             pAh + ko);                              \
        cp16(s0 +   TILE2,   pAl + ko);                              \
        cp16(s0 + 2*TILE2,   pBh + ko);                              \
        cp16(s0 + 3*TILE2,   pBl + ko);                              \
    } while (0)

    #define LOADFRAGS(kt_) do {                                      \
        uint32_t stgb = sb + (uint32_t)((kt_) & 3) * STG_B;          \
        _Pragma("unroll")                                            \
        for (int mf = 0; mf < 4; mf++) {                             \
            uint32_t ab = stgb + (uint32_t)((mw*64 + mf*16) * (AST16*2)) + aoff; \
            ldsm_x4(ah[mf], ab);                                     \
            ldsm_x4(al[mf], ab + TILE2);                             \
        }                                                            \
        _Pragma("unroll")                                            \
        for (int nf = 0; nf < 4; nf++) {                             \
            uint32_t bb = stgb + 2*TILE2                             \
                        + (uint32_t)((nw*32 + nf*8) * (AST16*2)) + boff; \
            ldsm_x4(bf[nf], bb);                                     \
        }                                                            \
    } while (0)

    ISSUE(0, 0); CP_COMMIT();
    ISSUE(1, 1); CP_COMMIT();
    ISSUE(2, 2); CP_COMMIT();
    CP_WAIT(2);
    __syncthreads();
    LOADFRAGS(0);

    for (int kt = 0; kt < KT16; kt++) {
        if (kt + 3 < KT16) ISSUE(kt + 3, (kt + 3) & 3);
        CP_COMMIT();

        #pragma unroll
        for (int nf = 0; nf < 4; nf++) {
            #pragma unroll
            for (int mf = 0; mf < 4; mf++) {
                mma_bf16(acc[mf * 4 + nf], ah[mf], bf[nf][0], bf[nf][1]);
                mma_bf16(acc[mf * 4 + nf], ah[mf], bf[nf][2], bf[nf][3]);
                mma_bf16(acc[mf * 4 + nf], al[mf], bf[nf][0], bf[nf][1]);
            }
        }

        CP_WAIT(2);
        __syncthreads();
        if (kt + 1 < KT16) LOADFRAGS(kt + 1);
    }
    #undef ISSUE
    #undef LOADFRAGS

    // Epilogue
    #pragma unroll
    for (int nf = 0; nf < 4; nf++) {
        const int c = n0 + nw * 32 + nf * 8 + 2 * tig;
        float2 bv = *(const float2*)&bias[c];
        #pragma unroll
        for (int mf = 0; mf < 4; mf++) {
            const float* a = acc[mf * 4 + nf];
            const int r0 = m0 + mw * 64 + mf * 16 + g;
            if (mode == 0) {
                int h  = c / 192;
                int rr = c - h * 192;
                int seg = rr >> 6;
                int d0  = rr & 63;
                int b = r0 >> 11;
                int t = r0 & (T_ - 1);
                size_t idx0 = ((size_t)(b * H_ + h) * T_ + t) * D_ + d0;
                float2 v0 = {a[0] + bv.x, a[1] + bv.y};
                float2 v1 = {a[2] + bv.x, a[3] + bv.y};
                if (seg == 2) {          // V: store fp16
                    *(__half2*)&g_vb[idx0]          = __floats2half2_rn(v0.x, v0.y);
                    *(__half2*)&g_vb[idx0 + 8 * D_] = __floats2half2_rn(v1.x, v1.y);
                } else {
                    float* base = (seg == 0) ? g_q : g_k;
                    if (seg == 1) {      // K consumed as tf32: pre-round
                        v0.x = __uint_as_float(f2tf32(v0.x));
                        v0.y = __uint_as_float(f2tf32(v0.y));
                        v1.x = __uint_as_float(f2tf32(v1.x));
                        v1.y = __uint_as_float(f2tf32(v1.y));
                    }
                    *(float2*)&base[idx0]          = v0;
                    *(float2*)&base[idx0 + 8 * D_] = v1;
                }
            } else {
                float2 v0 = {a[0] + bv.x, a[1] + bv.y};
                float2 v1 = {a[2] + bv.x, a[3] + bv.y};
                *(float2*)&outp[(size_t)r0 * C_ + c]       = v0;
                *(float2*)&outp[(size_t)(r0 + 8) * C_ + c] = v1;
            }
        }
    }
}

// ---------------------------------------------------------------------------
// Kernel 2: flash attention. S = QK^T in tf32 mma (K B-frags via ldmatrix on
// the fp32 tile viewed as b16 pairs); PV in fp16 m16n8k16 with P packed from
// S accumulators; V via ldmatrix.trans. K/V double-buffered with cp.async.
// ---------------------------------------------------------------------------
#define KST 84                         // K row stride (floats), 336B
#define VSTB 72                        // V row stride (halfs), 144B
#define KTILE_AB (64*KST*4)            // 21504
#define VTILE_AB (64*VSTB*2)           // 9216
#define ASTG_AB  (KTILE_AB + VTILE_AB) // 30720

__global__ __launch_bounds__(128, 3)
void attn_kernel()
{
    extern __shared__ char smc[];
    const uint32_t sb = smem_u32(smc);
    const int tid  = threadIdx.x;
    const int warp = tid >> 5, lane = tid & 31;
    const int g = lane >> 2, tig = lane & 3;

    const int q0 = blockIdx.x * 64;
    const int h  = blockIdx.y;
    const int b  = blockIdx.z;
    const size_t bh = (size_t)(b * H_ + h);
    const float* Qb = g_q + bh * (T_ * D_);
    const float* Kb = g_k + bh * (T_ * D_);
    const __half* Vb = g_vb + bh * (T_ * D_);

    // Q fragments, resident (tf32), rows q0+warp*16+{g,g+8}
    uint32_t qf[8][4];
    {
        const float* qr0 = Qb + (size_t)(q0 + warp * 16 + g) * D_;
        const float* qr1 = qr0 + 8 * D_;
        #pragma unroll
        for (int kf = 0; kf < 8; kf++) {
            qf[kf][0] = f2tf32(qr0[kf * 8 + tig]     * 0.125f);
            qf[kf][1] = f2tf32(qr1[kf * 8 + tig]     * 0.125f);
            qf[kf][2] = f2tf32(qr0[kf * 8 + tig + 4] * 0.125f);
            qf[kf][3] = f2tf32(qr1[kf * 8 + tig + 4] * 0.125f);
        }
    }

    float oacc[8][4];
    #pragma unroll
    for (int i = 0; i < 8; i++)
        #pragma unroll
        for (int j = 0; j < 4; j++) oacc[i][j] = 0.f;
    float m0 = -1e30f, m1 = -1e30f, l0 = 0.f, l1 = 0.f;

    // cp.async issue of K (16KB) + V (8KB) tile kb_ into stage stg_
    #define KV_ISSUE(kb_, stg_) do {                                          \
        uint32_t base = sb + (uint32_t)(stg_) * ASTG_AB;                      \
        const char* kg = (const char*)(Kb + (size_t)(kb_) * 64 * D_);         \
        const char* vg = (const char*)(Vb + (size_t)(kb_) * 64 * D_);         \
        _Pragma("unroll")                                                     \
        for (int u = 0; u < 8; u++) {                                         \
            int un = u * 128 + tid;                                           \
            cp16(base + (un >> 4) * (KST * 4) + (un & 15) * 16, kg + un * 16);\
        }                                                                     \
        _Pragma("unroll")                                                     \
        for (int u = 0; u < 4; u++) {                                         \
            int un = u * 128 + tid;                                           \
            cp16(base + KTILE_AB + (un >> 3) * (VSTB * 2) + (un & 7) * 16,    \
                 vg + un * 16);                                               \
        }                                                                     \
    } while (0)

    KV_ISSUE(0, 0); CP_COMMIT();

    // per-lane ldmatrix offsets
    // K (tf32 B-frags via b16 x4): row = n (lane&7), 16B chunk = lane>>3
    const uint32_t klo = (uint32_t)((lane & 7) * (KST * 4) + (lane >> 3) * 16);
    // V (trans): rows = key (lane&15), dim chunk +8 for lanes>=16
    const uint32_t vlo = (uint32_t)((lane & 15) * (VSTB * 2) + (lane >> 4) * 16);

    for (int kb = 0; kb < T_ / 64; kb++) {
        if (kb + 1 < T_ / 64) KV_ISSUE(kb + 1, (kb + 1) & 1);
        CP_COMMIT();
        CP_WAIT(1);
        __syncthreads();

        const uint32_t stgb = sb + (uint32_t)(kb & 1) * ASTG_AB;
        const uint32_t vbase = stgb + KTILE_AB;

        // S = Q K^T (tf32); K B-frags via ldmatrix:
        // x4 at +64*q covers kf=2q (b0,b1) and kf=2q+1 (b0,b1)
        float sacc[8][4];
        #pragma unroll
        for (int i = 0; i < 8; i++)
            #pragma unroll
            for (int j = 0; j < 4; j++) sacc[i][j] = 0.f;
        #pragma unroll
        for (int nf = 0; nf < 8; nf++) {
            uint32_t kaddr = stgb + (uint32_t)(nf * 8 * (KST * 4)) + klo;
            uint32_t bq[4][4];
            #pragma unroll
            for (int q = 0; q < 4; q++) ldsm_x4(bq[q], kaddr + q * 64);
            #pragma unroll
            for (int kf = 0; kf < 8; kf++) {
                mma_tf32(sacc[nf], qf[kf],
                         bq[kf >> 1][(kf & 1) * 2],
                         bq[kf >> 1][(kf & 1) * 2 + 1]);
            }
        }

        // online softmax (rows g / g+8; quad lanes share rows)
        float r0 = -1e30f, r1 = -1e30f;
        #pragma unroll
        for (int nf = 0; nf < 8; nf++) {
            r0 = fmaxf(r0, fmaxf(sacc[nf][0], sacc[nf][1]));
            r1 = fmaxf(r1, fmaxf(sacc[nf][2], sacc[nf][3]));
        }
        r0 = fmaxf(r0, __shfl_xor_sync(0xffffffffu, r0, 1));
        r0 = fmaxf(r0, __shfl_xor_sync(0xffffffffu, r0, 2));
        r1 = fmaxf(r1, __shfl_xor_sync(0xffffffffu, r1, 1));
        r1 = fmaxf(r1, __shfl_xor_sync(0xffffffffu, r1, 2));
        float m0n = fmaxf(m0, r0);
        float m1n = fmaxf(m1, r1);
        float f0 = __expf(m0 - m0n);
        float f1 = __expf(m1 - m1n);
        l0 *= f0; l1 *= f1;
        #pragma unroll
        for (int nf = 0; nf < 8; nf++) {
            oacc[nf][0] *= f0; oacc[nf][1] *= f0;
            oacc[nf][2] *= f1; oacc[nf][3] *= f1;
        }
        m0 = m0n; m1 = m1n;

        // p = exp(s - m); overwrite sacc with p (fp32), accumulate l
        float ps0 = 0.f, ps1 = 0.f;
        #pragma unroll
        for (int nf = 0; nf < 8; nf++) {
            float p0 = __expf(sacc[nf][0] - m0n);
            float p1 = __expf(sacc[nf][1] - m0n);
            float p2 = __expf(sacc[nf][2] - m1n);
            float p3 = __expf(sacc[nf][3] - m1n);
            ps0 += p0 + p1;
            ps1 += p2 + p3;
            sacc[nf][0] = p0; sacc[nf][1] = p1;
            sacc[nf][2] = p2; sacc[nf][3] = p3;
        }
        ps0 += __shfl_xor_sync(0xffffffffu, ps0, 1);
        ps0 += __shfl_xor_sync(0xffffffffu, ps0, 2);
        ps1 += __shfl_xor_sync(0xffffffffu, ps1, 1);
        ps1 += __shfl_xor_sync(0xffffffffu, ps1, 2);
        l0 += ps0; l1 += ps1;

        // O += P V  (fp16 m16n8k16; P A-frags packed from S accumulators)
        #pragma unroll
        for (int kf = 0; kf < 4; kf++) {
            uint32_t pa[4];
            pa[0] = pack_f16x2(sacc[2*kf][0],     sacc[2*kf][1]);
            pa[1] = pack_f16x2(sacc[2*kf][2],     sacc[2*kf][3]);
            pa[2] = pack_f16x2(sacc[2*kf+1][0],   sacc[2*kf+1][1]);
            pa[3] = pack_f16x2(sacc[2*kf+1][2],   sacc[2*kf+1][3]);
            #pragma unroll
            for (int nb = 0; nb < 4; nb++) {
                uint32_t bv[4];
                uint32_t va = vbase + (uint32_t)(kf * 16 * (VSTB * 2) + nb * 32) + vlo;
                ldsm_x4_t(bv, va);
                mma_f16(oacc[2*nb],     pa, bv[0], bv[1]);
                mma_f16(oacc[2*nb + 1], pa, bv[2], bv[3]);
            }
        }
        __syncthreads();
    }
    #undef KV_ISSUE

    // epilogue: normalize, split to bf16 hi/lo, write [B,T,C]
    float inv0 = 1.f / l0;
    float inv1 = 1.f / l1;
    const int t0 = q0 + warp * 16 + g;
    __nv_bfloat16* oh0 = g_ah + ((size_t)b * T_ + t0) * C_ + h * D_;
    __nv_bfloat16* ol0 = g_al + ((size_t)b * T_ + t0) * C_ + h * D_;
    __nv_bfloat16* oh1 = oh0 + 8 * (size_t)C_;
    __nv_bfloat16* ol1 = ol0 + 8 * (size_t)C_;
    #pragma unroll
    for (int nf = 0; nf < 8; nf++) {
        const int c = nf * 8 + 2 * tig;
        float v0 = oacc[nf][0] * inv0, v1 = oacc[nf][1] * inv0;
        float v2 = oacc[nf][2] * inv1, v3 = oacc[nf][3] * inv1;
        __nv_bfloat16 h0 = __float2bfloat16(v0), h1 = __float2bfloat16(v1);
        __nv_bfloat16 h2 = __float2bfloat16(v2), h3 = __float2bfloat16(v3);
        *(__nv_bfloat162*)&oh0[c] = __halves2bfloat162(h0, h1);
        *(__nv_bfloat162*)&oh1[c] = __halves2bfloat162(h2, h3);
        *(__nv_bfloat162*)&ol0[c] = __halves2bfloat162(
            __float2bfloat16(v0 - __bfloat162float(h0)),
            __float2bfloat16(v1 - __bfloat162float(h1)));
        *(__nv_bfloat162*)&ol1[c] = __halves2bfloat162(
            __float2bfloat16(v2 - __bfloat162float(h2)),
            __float2bfloat16(v3 - __bfloat162float(h3)));
    }
}

// ---------------------------------------------------------------------------
extern "C" void kernel_launch(void* const* d_in, const int* in_sizes, int n_in,
                              void* d_out, int out_size)
{
    const float* x     = (const float*)d_in[0];   // [2,2048,1024]
    const float* W_qkv = (const float*)d_in[1];   // [1024,3072]
    const float* b_qkv = (const float*)d_in[2];   // [3072]
    const float* W_out = (const float*)d_in[3];   // [1024,1024]
    const float* b_out = (const float*)d_in[4];   // [1024]
    float* out = (float*)d_out;                   // [2,2048,1024]

    (void)in_sizes; (void)n_in; (void)out_size;

    const int GEMM_SMEM = NSTG * STG_B;            // 98304
    cudaFuncSetAttribute(mma_gemm_kernel,
                         cudaFuncAttributeMaxDynamicSharedMemorySize, GEMM_SMEM);
    const int ATTN_SMEM = 2 * ASTG_AB;             // 61440
    cudaFuncSetAttribute(attn_kernel,
                         cudaFuncAttributeMaxDynamicSharedMemorySize, ATTN_SMEM);

    // 0) conversions
    conv_x_kernel<<<(BT * C_ / 4) / 256, 256>>>((const float4*)x);
    conv_wt_kernel<<<dim3(96 + 32, C_ / 32), dim3(32, 8)>>>(W_qkv, W_out);
    // 1) QKV projection (bf16x3 mma.sync, frag-pipelined)
    mma_gemm_kernel<<<dim3(N3C / 128, BT / 128), 256, GEMM_SMEM>>>(b_qkv, nullptr, 0);
    // 2) Flash attention (tf32 QK via ldmatrix + fp16 PV)
    attn_kernel<<<dim3(T_ / 64, H_, B_), 128, ATTN_SMEM>>>();
    // 3) Output projection (bf16x3 mma.sync, frag-pipelined)
    mma_gemm_kernel<<<dim3(C_ / 128, BT / 128), 256, GEMM_SMEM>>>(b_out, out, 1);
}

// round 10
// speedup vs baseline: 7.9986x; 1.2689x over previous
#include <cuda_runtime.h>
#include <cuda_bf16.h>
#include <cuda_fp16.h>
#include <stdint.h>
#include <math.h>

// Problem constants
#define B_  2
#define T_  2048
#define C_  1024
#define H_  16
#define D_  64
#define BT  (B_*T_)          // 4096
#define N3C (3*C_)           // 3072

// Scratch (device globals; no allocation allowed)
__device__ float g_q[B_*H_*T_*D_];     // [B,H,T,D] fp32
__device__ float g_k[B_*H_*T_*D_];     // pre-rounded to tf32 grid
__device__ __align__(16) __half g_vb[B_*H_*T_*D_];   // V as fp16
__device__ __align__(16) __half g_xh[BT*C_];         // x hi/lo fp16 (exact pair)
__device__ __align__(16) __half g_xl[BT*C_];
__device__ __align__(16) __half g_wq[N3C*C_];        // W_qkv^T fp16
__device__ __align__(16) __half g_wo[C_*C_];         // W_out^T fp16
__device__ __align__(16) __half g_ah[BT*C_];         // attn out hi/lo fp16 [B,T,C]
__device__ __align__(16) __half g_al[BT*C_];

// ---------------------------------------------------------------------------
// mma.sync / ldmatrix helpers (arch-portable; compiles for compute_103)
// ---------------------------------------------------------------------------
__device__ __forceinline__ void mma_f16(float* c, const uint32_t* a, uint32_t b0, uint32_t b1) {
    asm volatile("mma.sync.aligned.m16n8k16.row.col.f32.f16.f16.f32 "
        "{%0,%1,%2,%3}, {%4,%5,%6,%7}, {%8,%9}, {%0,%1,%2,%3};"
        : "+f"(c[0]), "+f"(c[1]), "+f"(c[2]), "+f"(c[3])
        : "r"(a[0]), "r"(a[1]), "r"(a[2]), "r"(a[3]), "r"(b0), "r"(b1));
}
__device__ __forceinline__ void mma_tf32(float* c, const uint32_t* a, uint32_t b0, uint32_t b1) {
    asm volatile("mma.sync.aligned.m16n8k8.row.col.f32.tf32.tf32.f32 "
        "{%0,%1,%2,%3}, {%4,%5,%6,%7}, {%8,%9}, {%0,%1,%2,%3};"
        : "+f"(c[0]), "+f"(c[1]), "+f"(c[2]), "+f"(c[3])
        : "r"(a[0]), "r"(a[1]), "r"(a[2]), "r"(a[3]), "r"(b0), "r"(b1));
}
__device__ __forceinline__ uint32_t f2tf32(float f) {
    uint32_t r; asm("cvt.rna.tf32.f32 %0, %1;" : "=r"(r) : "f"(f)); return r;
}
__device__ __forceinline__ uint32_t smem_u32(const void* p) {
    uint32_t a;
    asm("{ .reg .u64 t; cvta.to.shared.u64 t, %1; cvt.u32.u64 %0, t; }" : "=r"(a) : "l"(p));
    return a;
}
__device__ __forceinline__ void ldsm_x4(uint32_t* r, uint32_t addr) {
    asm volatile("ldmatrix.sync.aligned.m8n8.x4.shared.b16 {%0,%1,%2,%3}, [%4];"
        : "=r"(r[0]), "=r"(r[1]), "=r"(r[2]), "=r"(r[3]) : "r"(addr));
}
__device__ __forceinline__ void ldsm_x4_t(uint32_t* r, uint32_t addr) {
    asm volatile("ldmatrix.sync.aligned.m8n8.x4.trans.shared.b16 {%0,%1,%2,%3}, [%4];"
        : "=r"(r[0]), "=r"(r[1]), "=r"(r[2]), "=r"(r[3]) : "r"(addr));
}
__device__ __forceinline__ void cp16(uint32_t dst, const void* src) {
    asm volatile("cp.async.cg.shared.global [%0], [%1], 16;" :: "r"(dst), "l"(src));
}
#define CP_COMMIT() asm volatile("cp.async.commit_group;" ::: "memory")
#define CP_WAIT(n)  asm volatile("cp.async.wait_group %0;" :: "n"(n) : "memory")
__device__ __forceinline__ uint32_t pack_f16x2(float lo, float hi) {
    __half2 t = __floats2half2_rn(lo, hi);
    return *(uint32_t*)&t;
}

// ---------------------------------------------------------------------------
// Kernel 0a: convert x fp32 -> hi/lo fp16 (exact 22-bit pair)
// ---------------------------------------------------------------------------
__global__ __launch_bounds__(256)
void conv_x_kernel(const float4* __restrict__ X)
{
    int i = blockIdx.x * 256 + threadIdx.x;
    float4 v = X[i];
    __half hx = __float2half_rn(v.x);
    __half hy = __float2half_rn(v.y);
    __half hz = __float2half_rn(v.z);
    __half hw = __float2half_rn(v.w);
    __half lx = __float2half_rn(v.x - __half2float(hx));
    __half ly = __float2half_rn(v.y - __half2float(hy));
    __half lz = __float2half_rn(v.z - __half2float(hz));
    __half lw = __float2half_rn(v.w - __half2float(hw));
    __half2* ph = (__half2*)g_xh + (size_t)i * 2;
    __half2* pl = (__half2*)g_xl + (size_t)i * 2;
    ph[0] = __halves2half2(hx, hy);
    ph[1] = __halves2half2(hz, hw);
    pl[0] = __halves2half2(lx, ly);
    pl[1] = __halves2half2(lz, lw);
}

// ---------------------------------------------------------------------------
// Kernel 0b: transpose + convert both weights fp32 -> WT fp16 (merged)
// blocks x < 96: W_qkv (N=3072); else W_out (N=1024)
// ---------------------------------------------------------------------------
__global__ __launch_bounds__(256)
void conv_wt_kernel(const float* __restrict__ Wq, const float* __restrict__ Wo)
{
    __shared__ float tile[32][33];
    int which, n0;
    const float* W;
    int N;
    if (blockIdx.x < 96) { which = 0; W = Wq; N = N3C; n0 = blockIdx.x * 32; }
    else                 { which = 1; W = Wo; N = C_;  n0 = (blockIdx.x - 96) * 32; }
    int k0 = blockIdx.y * 32;
    int tx = threadIdx.x;
    int ty = threadIdx.y;

    #pragma unroll
    for (int i = 0; i < 32; i += 8)
        tile[ty + i][tx] = W[(size_t)(k0 + ty + i) * N + n0 + tx];
    __syncthreads();

    __half* Tw = which ? g_wo : g_wq;
    #pragma unroll
    for (int i = 0; i < 32; i += 8) {
        float v = tile[tx][ty + i];
        Tw[(size_t)(n0 + ty + i) * C_ + k0 + tx] = __float2half_rn(v);
    }
}

// ---------------------------------------------------------------------------
// Kernel 1/3: fp16 split-activation x2 GEMM, fragment-software-pipelined.
// Block tile 128x128, kc=16, 4-stage cp.async, 8 warps = 2(M) x 4(N).
// D = xh*w + xl*w : 2 MMAs per (mf,nf) per k16-step.
// ---------------------------------------------------------------------------
#define AST16 24
#define TILE2 (128*AST16*2)           // 6144 bytes per matrix tile
#define STG_B (3*TILE2)               // 18432: AH, AL, W
#define NSTG  4
#define KT16  (C_/16)

__global__ __launch_bounds__(256, 2)
void mma_gemm_kernel(const float* __restrict__ bias, float* __restrict__ outp, int mode)
{
    extern __shared__ char smem[];
    const uint32_t sb = smem_u32(smem);

    const int tid  = threadIdx.x;
    const int m0   = blockIdx.y * 128;
    const int n0   = blockIdx.x * 128;
    const int warp = tid >> 5, lane = tid & 31;
    const int mw = warp & 1, nw = warp >> 1;
    const int g = lane >> 2, tig = lane & 3;

    const __half* Ah = mode ? g_ah : g_xh;
    const __half* Al = mode ? g_al : g_xl;
    const __half* Bw = mode ? g_wo : g_wq;

    const int lrow = tid >> 1;
    const __half* pAh = Ah + (size_t)(m0 + lrow) * C_ + (tid & 1) * 8;
    const __half* pAl = Al + (size_t)(m0 + lrow) * C_ + (tid & 1) * 8;
    const __half* pBw = Bw + (size_t)(n0 + lrow) * C_ + (tid & 1) * 8;
    const uint32_t soff = (uint32_t)(lrow * AST16 * 2 + (tid & 1) * 16);

    // ldmatrix per-lane byte offsets (row stride 48B; phases conflict-free)
    const uint32_t aoff = (uint32_t)((lane & 15) * (AST16 * 2) + (lane >> 4) * 16);
    // B x4 covers 16 n-rows x 16 k: lanes 0-7 rows n0-7 chunk0, 8-15 rows n0-7
    // chunk1, 16-23 rows n8-15 chunk0, 24-31 rows n8-15 chunk1
    const uint32_t boff = (uint32_t)((lane & 7) * (AST16 * 2) + ((lane >> 3) & 1) * 16
                        + (lane >> 4) * 8 * (AST16 * 2));

    float acc[16][4];
    #pragma unroll
    for (int i = 0; i < 16; i++)
        #pragma unroll
        for (int j = 0; j < 4; j++) acc[i][j] = 0.f;

    uint32_t ah[4][4], al[4][4], bf[2][4];

    #define ISSUE(ktile, stg) do {                                   \
        uint32_t s0 = sb + (uint32_t)(stg) * STG_B + soff;           \
        const int ko = (ktile) * 16;                                 \
        cp16(s0,             pAh + ko);                              \
        cp16(s0 +   TILE2,   pAl + ko);                              \
        cp16(s0 + 2*TILE2,   pBw + ko);                              \
    } while (0)

    #define LOADFRAGS(kt_) do {                                      \
        uint32_t stgb = sb + (uint32_t)((kt_) & 3) * STG_B;          \
        _Pragma("unroll")                                            \
        for (int mf = 0; mf < 4; mf++) {                             \
            uint32_t ab = stgb + (uint32_t)((mw*64 + mf*16) * (AST16*2)) + aoff; \
            ldsm_x4(ah[mf], ab);                                     \
            ldsm_x4(al[mf], ab + TILE2);                             \
        }                                                            \
        _Pragma("unroll")                                            \
        for (int j = 0; j < 2; j++) {                                \
            uint32_t bb = stgb + 2*TILE2                             \
                        + (uint32_t)((nw*32 + j*16) * (AST16*2)) + boff; \
            ldsm_x4(bf[j], bb);                                      \
        }                                                            \
    } while (0)

    ISSUE(0, 0); CP_COMMIT();
    ISSUE(1, 1); CP_COMMIT();
    ISSUE(2, 2); CP_COMMIT();
    CP_WAIT(2);
    __syncthreads();
    LOADFRAGS(0);

    for (int kt = 0; kt < KT16; kt++) {
        if (kt + 3 < KT16) ISSUE(kt + 3, (kt + 3) & 3);
        CP_COMMIT();

        // MMAs for tile kt from registers: D += xh*w + xl*w
        #pragma unroll
        for (int nf = 0; nf < 4; nf++) {
            const uint32_t b0 = bf[nf >> 1][(nf & 1) * 2];
            const uint32_t b1 = bf[nf >> 1][(nf & 1) * 2 + 1];
            #pragma unroll
            for (int mf = 0; mf < 4; mf++) {
                mma_f16(acc[mf * 4 + nf], ah[mf], b0, b1);
                mma_f16(acc[mf * 4 + nf], al[mf], b0, b1);
            }
        }

        CP_WAIT(2);
        __syncthreads();
        if (kt + 1 < KT16) LOADFRAGS(kt + 1);
    }
    #undef ISSUE
    #undef LOADFRAGS

    // Epilogue
    #pragma unroll
    for (int nf = 0; nf < 4; nf++) {
        const int c = n0 + nw * 32 + nf * 8 + 2 * tig;
        float2 bv = *(const float2*)&bias[c];
        #pragma unroll
        for (int mf = 0; mf < 4; mf++) {
            const float* a = acc[mf * 4 + nf];
            const int r0 = m0 + mw * 64 + mf * 16 + g;
            if (mode == 0) {
                int h  = c / 192;
                int rr = c - h * 192;
                int seg = rr >> 6;
                int d0  = rr & 63;
                int b = r0 >> 11;
                int t = r0 & (T_ - 1);
                size_t idx0 = ((size_t)(b * H_ + h) * T_ + t) * D_ + d0;
                float2 v0 = {a[0] + bv.x, a[1] + bv.y};
                float2 v1 = {a[2] + bv.x, a[3] + bv.y};
                if (seg == 2) {          // V: store fp16
                    *(__half2*)&g_vb[idx0]          = __floats2half2_rn(v0.x, v0.y);
                    *(__half2*)&g_vb[idx0 + 8 * D_] = __floats2half2_rn(v1.x, v1.y);
                } else {
                    float* base = (seg == 0) ? g_q : g_k;
                    if (seg == 1) {      // K consumed as tf32: pre-round
                        v0.x = __uint_as_float(f2tf32(v0.x));
                        v0.y = __uint_as_float(f2tf32(v0.y));
                        v1.x = __uint_as_float(f2tf32(v1.x));
                        v1.y = __uint_as_float(f2tf32(v1.y));
                    }
                    *(float2*)&base[idx0]          = v0;
                    *(float2*)&base[idx0 + 8 * D_] = v1;
                }
            } else {
                float2 v0 = {a[0] + bv.x, a[1] + bv.y};
                float2 v1 = {a[2] + bv.x, a[3] + bv.y};
                *(float2*)&outp[(size_t)r0 * C_ + c]       = v0;
                *(float2*)&outp[(size_t)(r0 + 8) * C_ + c] = v1;
            }
        }
    }
}

// ---------------------------------------------------------------------------
// Kernel 2: flash attention. S = QK^T in tf32 mma (K B-frags via ldmatrix on
// the fp32 tile viewed as b16 pairs); PV in fp16 m16n8k16 with P packed from
// S accumulators; V via ldmatrix.trans. K/V double-buffered with cp.async.
// Epilogue emits fp16 hi/lo for the out-projection.
// ---------------------------------------------------------------------------
#define KST 84                         // K row stride (floats), 336B
#define VSTB 72                        // V row stride (halfs), 144B
#define KTILE_AB (64*KST*4)            // 21504
#define VTILE_AB (64*VSTB*2)           // 9216
#define ASTG_AB  (KTILE_AB + VTILE_AB) // 30720

__global__ __launch_bounds__(128, 3)
void attn_kernel()
{
    extern __shared__ char smc[];
    const uint32_t sb = smem_u32(smc);
    const int tid  = threadIdx.x;
    const int warp = tid >> 5, lane = tid & 31;
    const int g = lane >> 2, tig = lane & 3;

    const int q0 = blockIdx.x * 64;
    const int h  = blockIdx.y;
    const int b  = blockIdx.z;
    const size_t bh = (size_t)(b * H_ + h);
    const float* Qb = g_q + bh * (T_ * D_);
    const float* Kb = g_k + bh * (T_ * D_);
    const __half* Vb = g_vb + bh * (T_ * D_);

    // Q fragments, resident (tf32), rows q0+warp*16+{g,g+8}
    uint32_t qf[8][4];
    {
        const float* qr0 = Qb + (size_t)(q0 + warp * 16 + g) * D_;
        const float* qr1 = qr0 + 8 * D_;
        #pragma unroll
        for (int kf = 0; kf < 8; kf++) {
            qf[kf][0] = f2tf32(qr0[kf * 8 + tig]     * 0.125f);
            qf[kf][1] = f2tf32(qr1[kf * 8 + tig]     * 0.125f);
            qf[kf][2] = f2tf32(qr0[kf * 8 + tig + 4] * 0.125f);
            qf[kf][3] = f2tf32(qr1[kf * 8 + tig + 4] * 0.125f);
        }
    }

    float oacc[8][4];
    #pragma unroll
    for (int i = 0; i < 8; i++)
        #pragma unroll
        for (int j = 0; j < 4; j++) oacc[i][j] = 0.f;
    float m0 = -1e30f, m1 = -1e30f, l0 = 0.f, l1 = 0.f;

    // cp.async issue of K (16KB) + V (8KB) tile kb_ into stage stg_
    #define KV_ISSUE(kb_, stg_) do {                                          \
        uint32_t base = sb + (uint32_t)(stg_) * ASTG_AB;                      \
        const char* kg = (const char*)(Kb + (size_t)(kb_) * 64 * D_);         \
        const char* vg = (const char*)(Vb + (size_t)(kb_) * 64 * D_);         \
        _Pragma("unroll")                                                     \
        for (int u = 0; u < 8; u++) {                                         \
            int un = u * 128 + tid;                                           \
            cp16(base + (un >> 4) * (KST * 4) + (un & 15) * 16, kg + un * 16);\
        }                                                                     \
        _Pragma("unroll")                                                     \
        for (int u = 0; u < 4; u++) {                                         \
            int un = u * 128 + tid;                                           \
            cp16(base + KTILE_AB + (un >> 3) * (VSTB * 2) + (un & 7) * 16,    \
                 vg + un * 16);                                               \
        }                                                                     \
    } while (0)

    KV_ISSUE(0, 0); CP_COMMIT();

    // per-lane ldmatrix offsets
    const uint32_t klo = (uint32_t)((lane & 7) * (KST * 4) + (lane >> 3) * 16);
    const uint32_t vlo = (uint32_t)((lane & 15) * (VSTB * 2) + (lane >> 4) * 16);

    for (int kb = 0; kb < T_ / 64; kb++) {
        if (kb + 1 < T_ / 64) KV_ISSUE(kb + 1, (kb + 1) & 1);
        CP_COMMIT();
        CP_WAIT(1);
        __syncthreads();

        const uint32_t stgb = sb + (uint32_t)(kb & 1) * ASTG_AB;
        const uint32_t vbase = stgb + KTILE_AB;

        // S = Q K^T (tf32); K B-frags via ldmatrix
        float sacc[8][4];
        #pragma unroll
        for (int i = 0; i < 8; i++)
            #pragma unroll
            for (int j = 0; j < 4; j++) sacc[i][j] = 0.f;
        #pragma unroll
        for (int nf = 0; nf < 8; nf++) {
            uint32_t kaddr = stgb + (uint32_t)(nf * 8 * (KST * 4)) + klo;
            uint32_t bq[4][4];
            #pragma unroll
            for (int q = 0; q < 4; q++) ldsm_x4(bq[q], kaddr + q * 64);
            #pragma unroll
            for (int kf = 0; kf < 8; kf++) {
                mma_tf32(sacc[nf], qf[kf],
                         bq[kf >> 1][(kf & 1) * 2],
                         bq[kf >> 1][(kf & 1) * 2 + 1]);
            }
        }

        // online softmax
        float r0 = -1e30f, r1 = -1e30f;
        #pragma unroll
        for (int nf = 0; nf < 8; nf++) {
            r0 = fmaxf(r0, fmaxf(sacc[nf][0], sacc[nf][1]));
            r1 = fmaxf(r1, fmaxf(sacc[nf][2], sacc[nf][3]));
        }
        r0 = fmaxf(r0, __shfl_xor_sync(0xffffffffu, r0, 1));
        r0 = fmaxf(r0, __shfl_xor_sync(0xffffffffu, r0, 2));
        r1 = fmaxf(r1, __shfl_xor_sync(0xffffffffu, r1, 1));
        r1 = fmaxf(r1, __shfl_xor_sync(0xffffffffu, r1, 2));
        float m0n = fmaxf(m0, r0);
        float m1n = fmaxf(m1, r1);
        float f0 = __expf(m0 - m0n);
        float f1 = __expf(m1 - m1n);
        l0 *= f0; l1 *= f1;
        #pragma unroll
        for (int nf = 0; nf < 8; nf++) {
            oacc[nf][0] *= f0; oacc[nf][1] *= f0;
            oacc[nf][2] *= f1; oacc[nf][3] *= f1;
        }
        m0 = m0n; m1 = m1n;

        float ps0 = 0.f, ps1 = 0.f;
        #pragma unroll
        for (int nf = 0; nf < 8; nf++) {
            float p0 = __expf(sacc[nf][0] - m0n);
            float p1 = __expf(sacc[nf][1] - m0n);
            float p2 = __expf(sacc[nf][2] - m1n);
            float p3 = __expf(sacc[nf][3] - m1n);
            ps0 += p0 + p1;
            ps1 += p2 + p3;
            sacc[nf][0] = p0; sacc[nf][1] = p1;
            sacc[nf][2] = p2; sacc[nf][3] = p3;
        }
        ps0 += __shfl_xor_sync(0xffffffffu, ps0, 1);
        ps0 += __shfl_xor_sync(0xffffffffu, ps0, 2);
        ps1 += __shfl_xor_sync(0xffffffffu, ps1, 1);
        ps1 += __shfl_xor_sync(0xffffffffu, ps1, 2);
        l0 += ps0; l1 += ps1;

        // O += P V (fp16)
        #pragma unroll
        for (int kf = 0; kf < 4; kf++) {
            uint32_t pa[4];
            pa[0] = pack_f16x2(sacc[2*kf][0],     sacc[2*kf][1]);
            pa[1] = pack_f16x2(sacc[2*kf][2],     sacc[2*kf][3]);
            pa[2] = pack_f16x2(sacc[2*kf+1][0],   sacc[2*kf+1][1]);
            pa[3] = pack_f16x2(sacc[2*kf+1][2],   sacc[2*kf+1][3]);
            #pragma unroll
            for (int nb = 0; nb < 4; nb++) {
                uint32_t bv[4];
                uint32_t va = vbase + (uint32_t)(kf * 16 * (VSTB * 2) + nb * 32) + vlo;
                ldsm_x4_t(bv, va);
                mma_f16(oacc[2*nb],     pa, bv[0], bv[1]);
                mma_f16(oacc[2*nb + 1], pa, bv[2], bv[3]);
            }
        }
        __syncthreads();
    }
    #undef KV_ISSUE

    // epilogue: normalize, split to fp16 hi/lo, write [B,T,C]
    float inv0 = 1.f / l0;
    float inv1 = 1.f / l1;
    const int t0 = q0 + warp * 16 + g;
    __half* oh0 = g_ah + ((size_t)b * T_ + t0) * C_ + h * D_;
    __half* ol0 = g_al + ((size_t)b * T_ + t0) * C_ + h * D_;
    __half* oh1 = oh0 + 8 * (size_t)C_;
    __half* ol1 = ol0 + 8 * (size_t)C_;
    #pragma unroll
    for (int nf = 0; nf < 8; nf++) {
        const int c = nf * 8 + 2 * tig;
        float v0 = oacc[nf][0] * inv0, v1 = oacc[nf][1] * inv0;
        float v2 = oacc[nf][2] * inv1, v3 = oacc[nf][3] * inv1;
        __half h0 = __float2half_rn(v0), h1 = __float2half_rn(v1);
        __half h2 = __float2half_rn(v2), h3 = __float2half_rn(v3);
        *(__half2*)&oh0[c] = __halves2half2(h0, h1);
        *(__half2*)&oh1[c] = __halves2half2(h2, h3);
        *(__half2*)&ol0[c] = __halves2half2(
            __float2half_rn(v0 - __half2float(h0)),
            __float2half_rn(v1 - __half2float(h1)));
        *(__half2*)&ol1[c] = __halves2half2(
            __float2half_rn(v2 - __half2float(h2)),
            __float2half_rn(v3 - __half2float(h3)));
    }
}

// ---------------------------------------------------------------------------
extern "C" void kernel_launch(void* const* d_in, const int* in_sizes, int n_in,
                              void* d_out, int out_size)
{
    const float* x     = (const float*)d_in[0];   // [2,2048,1024]
    const float* W_qkv = (const float*)d_in[1];   // [1024,3072]
    const float* b_qkv = (const float*)d_in[2];   // [3072]
    const float* W_out = (const float*)d_in[3];   // [1024,1024]
    const float* b_out = (const float*)d_in[4];   // [1024]
    float* out = (float*)d_out;                   // [2,2048,1024]

    (void)in_sizes; (void)n_in; (void)out_size;

    const int GEMM_SMEM = NSTG * STG_B;            // 4 * 18432 = 73728
    cudaFuncSetAttribute(mma_gemm_kernel,
                         cudaFuncAttributeMaxDynamicSharedMemorySize, GEMM_SMEM);
    const int ATTN_SMEM = 2 * ASTG_AB;             // 61440
    cudaFuncSetAttribute(attn_kernel,
                         cudaFuncAttributeMaxDynamicSharedMemorySize, ATTN_SMEM);

    // 0) conversions
    conv_x_kernel<<<(BT * C_ / 4) / 256, 256>>>((const float4*)x);
    conv_wt_kernel<<<dim3(96 + 32, C_ / 32), dim3(32, 8)>>>(W_qkv, W_out);
    // 1) QKV projection (fp16 split-A x2 mma.sync)
    mma_gemm_kernel<<<dim3(N3C / 128, BT / 128), 256, GEMM_SMEM>>>(b_qkv, nullptr, 0);
    // 2) Flash attention (tf32 QK via ldmatrix + fp16 PV)
    attn_kernel<<<dim3(T_ / 64, H_, B_), 128, ATTN_SMEM>>>();
    // 3) Output projection (fp16 split-A x2 mma.sync)
    mma_gemm_kernel<<<dim3(C_ / 128, BT / 128), 256, GEMM_SMEM>>>(b_out, out, 1);
}